// round 9
// baseline (speedup 1.0000x reference)
#include <cuda_runtime.h>
#include <cuda_bf16.h>
#include <math.h>
#include <stdint.h>

#define NB    4
#define NS    1024
#define NHID  1024
#define NHEADS 16
#define NKVH  4
#define DH    64
#define NE    8
#define NF    2048
#define NTOK  4096
#define QKVN  1536
#define GUN   4096

// ---------------- scratch (device globals, allocation-free) ----------------
__device__ float g_xn[NTOK * NHID];
__device__ __nv_bfloat16 g_xnh[NTOK * NHID];
__device__ __nv_bfloat16 g_xnl[NTOK * NHID];
__device__ float g_qkv[NTOK * QKVN];
__device__ __nv_bfloat16 g_atth[NTOK * NHID];
__device__ __nv_bfloat16 g_attl[NTOK * NHID];
__device__ float g_h[NTOK * NHID];
__device__ __nv_bfloat16 g_wqkvh[NHID * QKVN];
__device__ __nv_bfloat16 g_wqkvl[NHID * QKVN];
__device__ __nv_bfloat16 g_woh[NHID * NHID];
__device__ __nv_bfloat16 g_wol[NHID * NHID];
__device__ __nv_bfloat16 g_wguh[NE * NHID * GUN];
__device__ __nv_bfloat16 g_wgul[NE * NHID * GUN];
__device__ __nv_bfloat16 g_wdh[NE * NF * NHID];
__device__ __nv_bfloat16 g_wdl[NE * NF * NHID];
__device__ float g_GU[(size_t)NE * NTOK * GUN];
__device__ __nv_bfloat16 g_Gh[NE * NTOK * NF];
__device__ __nv_bfloat16 g_Gl[NE * NTOK * NF];
__device__ int   g_cnt[NE];
__device__ int   g_tok[NE * NTOK];
__device__ float g_wgt[NE * NTOK];

// ---------------- helpers ----------------
__device__ __forceinline__ uint32_t pack_hi2(float a, float b, uint32_t* lo) {
    __nv_bfloat16 ha = __float2bfloat16(a);
    __nv_bfloat16 hb = __float2bfloat16(b);
    __nv_bfloat16 la = __float2bfloat16(a - __bfloat162float(ha));
    __nv_bfloat16 lb = __float2bfloat16(b - __bfloat162float(hb));
    *lo = ((uint32_t)__bfloat16_as_ushort(lb) << 16) | (uint32_t)__bfloat16_as_ushort(la);
    return ((uint32_t)__bfloat16_as_ushort(hb) << 16) | (uint32_t)__bfloat16_as_ushort(ha);
}

__device__ __forceinline__ void ldsm4(uint32_t* r, uint32_t a) {
    asm volatile("ldmatrix.sync.aligned.m8n8.x4.shared.b16 {%0,%1,%2,%3}, [%4];\n"
        : "=r"(r[0]), "=r"(r[1]), "=r"(r[2]), "=r"(r[3]) : "r"(a));
}
__device__ __forceinline__ void ldsm4t(uint32_t* r, uint32_t a) {
    asm volatile("ldmatrix.sync.aligned.m8n8.x4.trans.shared.b16 {%0,%1,%2,%3}, [%4];\n"
        : "=r"(r[0]), "=r"(r[1]), "=r"(r[2]), "=r"(r[3]) : "r"(a));
}
__device__ __forceinline__ void mma16816(float* d, const uint32_t* a, uint32_t b0, uint32_t b1) {
    asm volatile("mma.sync.aligned.m16n8k16.row.col.f32.bf16.bf16.f32 "
        "{%0,%1,%2,%3},{%4,%5,%6,%7},{%8,%9},{%0,%1,%2,%3};\n"
        : "+f"(d[0]), "+f"(d[1]), "+f"(d[2]), "+f"(d[3])
        : "r"(a[0]), "r"(a[1]), "r"(a[2]), "r"(a[3]), "r"(b0), "r"(b1));
}
__device__ __forceinline__ void cpa16(uint32_t dst, const void* src, int sz) {
    asm volatile("cp.async.cg.shared.global [%0], [%1], 16, %2;\n"
        :: "r"(dst), "l"(src), "r"(sz));
}

// ---- packed f32x2 (sm_100+ family, not 'a'-gated) ----
struct __align__(16) ull2_t { unsigned long long x, y; };
__device__ __forceinline__ unsigned long long pk2(float a, float b) {
    unsigned long long r;
    asm("mov.b64 %0, {%1, %2};" : "=l"(r) : "f"(a), "f"(b));
    return r;
}
__device__ __forceinline__ void upk2(unsigned long long v, float* a, float* b) {
    asm("mov.b64 {%0, %1}, %2;" : "=f"(*a), "=f"(*b) : "l"(v));
}
__device__ __forceinline__ unsigned long long fma2(unsigned long long a, unsigned long long b,
                                                   unsigned long long c) {
    unsigned long long d;
    asm("fma.rn.f32x2 %0, %1, %2, %3;" : "=l"(d) : "l"(a), "l"(b), "l"(c));
    return d;
}
__device__ __forceinline__ unsigned long long mul2(unsigned long long a, unsigned long long b) {
    unsigned long long d;
    asm("mul.rn.f32x2 %0, %1, %2;" : "=l"(d) : "l"(a), "l"(b));
    return d;
}

// ---------------- fused RMSNorm + bf16 hi/lo split ----------------
__global__ void rmsnorm_split_k(const float* __restrict__ xext, const float* __restrict__ w,
                                int use_h, int write_xn) {
    int t = blockIdx.x;
    const float* src = use_h ? (const float*)g_h : xext;
    const float4* xr = (const float4*)(src + (size_t)t * NHID);
    float4 v = xr[threadIdx.x];
    float ss = v.x*v.x + v.y*v.y + v.z*v.z + v.w*v.w;
    #pragma unroll
    for (int o = 16; o; o >>= 1) ss += __shfl_down_sync(0xffffffffu, ss, o);
    __shared__ float red[8];
    if ((threadIdx.x & 31) == 0) red[threadIdx.x >> 5] = ss;
    __syncthreads();
    if (threadIdx.x < 8) {
        float s = red[threadIdx.x];
        #pragma unroll
        for (int o = 4; o; o >>= 1) s += __shfl_down_sync(0xffu, s, o);
        if (threadIdx.x == 0) red[0] = s;
    }
    __syncthreads();
    float rs = rsqrtf(red[0] * (1.0f / NHID) + 1e-6f);
    float4 wv = ((const float4*)w)[threadIdx.x];
    float4 ov;
    ov.x = v.x * rs * wv.x;
    ov.y = v.y * rs * wv.y;
    ov.z = v.z * rs * wv.z;
    ov.w = v.w * rs * wv.w;
    if (write_xn) {
        ((float4*)(g_xn + (size_t)t * NHID))[threadIdx.x] = ov;
    }
    uint32_t l0, l1;
    uint32_t h0 = pack_hi2(ov.x, ov.y, &l0);
    uint32_t h1 = pack_hi2(ov.z, ov.w, &l1);
    uint32_t* ph = (uint32_t*)(g_xnh + (size_t)t * NHID) + threadIdx.x * 2;
    uint32_t* pl = (uint32_t*)(g_xnl + (size_t)t * NHID) + threadIdx.x * 2;
    ph[0] = h0;
    ph[1] = h1;
    pl[0] = l0;
    pl[1] = l1;
}

// ---------------- combined QKV weight split-pack ----------------
__global__ void split_pack_qkv_k(const float4* __restrict__ Wq, const float4* __restrict__ Wk,
                                 const float4* __restrict__ Wv) {
    int i = blockIdx.x * 256 + threadIdx.x;
    int el = i * 4;
    int r = el / QKVN;
    int c = el % QKVN;
    float4 v;
    if (c < 1024)      v = Wq[(r * 1024 + c) / 4];
    else if (c < 1280) v = Wk[(r * 256 + (c - 1024)) / 4];
    else               v = Wv[(r * 256 + (c - 1280)) / 4];
    uint32_t l0, l1;
    uint32_t h0 = pack_hi2(v.x, v.y, &l0);
    uint32_t h1 = pack_hi2(v.z, v.w, &l1);
    uint32_t* ph = (uint32_t*)(g_wqkvh + (size_t)r * QKVN + c);
    uint32_t* pl = (uint32_t*)(g_wqkvl + (size_t)r * QKVN + c);
    ph[0] = h0;
    ph[1] = h1;
    pl[0] = l0;
    pl[1] = l1;
}

// ---------------- plain split: fp32 -> bf16 hi/lo -------------
__global__ void split_k(const float4* __restrict__ ext, int n4, int sel) {
    int i = blockIdx.x * 256 + threadIdx.x;
    if (i >= n4) return;
    uint32_t* dh;
    uint32_t* dl;
    if (sel == 1) { dh = (uint32_t*)g_woh;  dl = (uint32_t*)g_wol; }
    else          { dh = (uint32_t*)g_wdh;  dl = (uint32_t*)g_wdl; }
    float4 v = ext[i];
    uint32_t l0, l1;
    uint32_t h0 = pack_hi2(v.x, v.y, &l0);
    uint32_t h1 = pack_hi2(v.z, v.w, &l1);
    dh[i*2]   = h0;
    dh[i*2+1] = h1;
    dl[i*2]   = l0;
    dl[i*2+1] = l1;
}

// pack columns: src [rows][cs] -> g_wguh/g_wgul [rows][cd] at column offset off
__global__ void split_pack_k(const float4* __restrict__ s, int n4, int cs, int cd, int off) {
    int i = blockIdx.x * 256 + threadIdx.x;
    if (i >= n4) return;
    float4 v = s[i];
    int el = i * 4;
    int r = el / cs;
    int c = el % cs;
    size_t d = (size_t)r * cd + off + c;
    uint32_t l0, l1;
    uint32_t h0 = pack_hi2(v.x, v.y, &l0);
    uint32_t h1 = pack_hi2(v.z, v.w, &l1);
    uint32_t* ph = (uint32_t*)(g_wguh + d);
    uint32_t* pl = (uint32_t*)(g_wgul + d);
    ph[0] = h0;
    ph[1] = h1;
    pl[0] = l0;
    pl[1] = l1;
}

// ---------------- tensor-core GEMM (bf16x3), 128x128x32 tiles, 2-stage ------
#define TG_SMEM 75776

__device__ __forceinline__ void tg_load(
        uint32_t sA, uint32_t sB, int stg, int k0,
        int ar, int ac8, int br, int bc8,
        const __nv_bfloat16* aph0, const __nv_bfloat16* apl0, int asz0,
        const __nv_bfloat16* aph1, const __nv_bfloat16* apl1, int asz1,
        const __nv_bfloat16* Bh, const __nv_bfloat16* Bl, int N, int bx) {
    uint32_t a0 = sA + stg * 20480 + ar * 80 + ac8 * 16;
    cpa16(a0,                 aph0 + k0, asz0);
    cpa16(a0 + 10240,         apl0 + k0, asz0);
    cpa16(a0 + 64*80,         aph1 + k0, asz1);
    cpa16(a0 + 10240 + 64*80, apl1 + k0, asz1);
    const __nv_bfloat16* sh0 = Bh + (size_t)(k0 + br) * N + bx + bc8*8;
    const __nv_bfloat16* sl0 = Bl + (size_t)(k0 + br) * N + bx + bc8*8;
    uint32_t b0 = sB + stg * 17408 + br * 272 + bc8 * 16;
    cpa16(b0,                 sh0, 16);
    cpa16(b0 + 8704,          sl0, 16);
    cpa16(b0 + 16*272,        sh0 + (size_t)16*N, 16);
    cpa16(b0 + 8704 + 16*272, sl0 + (size_t)16*N, 16);
    asm volatile("cp.async.commit_group;\n");
}

__global__ __launch_bounds__(256, 2) void tgemm_k(int op, const float* __restrict__ cadd_ext,
                                                  float* __restrict__ cout_ext) {
    extern __shared__ char smraw[];
    uint32_t sA = (uint32_t)__cvta_generic_to_shared(smraw);
    uint32_t sB = sA + 40960;

    const __nv_bfloat16* Ah;
    const __nv_bfloat16* Al;
    const __nv_bfloat16* Bh;
    const __nv_bfloat16* Bl;
    float* C;
    const float* Cadd = 0;
    int N, K, mode;
    if (op == 0) {
        Ah = g_xnh;  Al = g_xnl;  Bh = g_wqkvh; Bl = g_wqkvl;
        C = g_qkv;  N = QKVN; K = NHID; mode = 0;
    } else if (op == 1) {
        Ah = g_atth; Al = g_attl; Bh = g_woh;   Bl = g_wol;
        C = g_h;    Cadd = cadd_ext; N = NHID; K = NHID; mode = 0;
    } else if (op == 2) {
        Ah = g_xnh;  Al = g_xnl;  Bh = g_wguh;  Bl = g_wgul;
        C = g_GU;   N = GUN;  K = NHID; mode = 1;
    } else {
        Ah = g_Gh;   Al = g_Gl;   Bh = g_wdh;   Bl = g_wdl;
        C = cout_ext; N = NHID; K = NF; mode = 2;
    }

    int tid = threadIdx.x;
    int bx = blockIdx.x * 128;
    int by = blockIdx.y * 128;
    int e = blockIdx.z;
    int m = NTOK;
    if (mode != 0) {
        m = g_cnt[e];
        if (by >= m) return;
        Bh += (size_t)e * K * N;
        Bl += (size_t)e * K * N;
    }

    int ar = tid >> 2;
    int ac8 = tid & 3;
    const __nv_bfloat16* aph0;
    const __nv_bfloat16* apl0;
    const __nv_bfloat16* aph1;
    const __nv_bfloat16* apl1;
    int asz0, asz1;
    {
        int lr0 = by + ar;
        int lr1 = by + ar + 64;
        size_t g0, g1;
        bool v0 = true, v1 = true;
        if (mode == 0) {
            g0 = (size_t)lr0;
            g1 = (size_t)lr1;
        } else if (mode == 1) {
            v0 = lr0 < m;
            v1 = lr1 < m;
            g0 = v0 ? (size_t)g_tok[e * NTOK + lr0] : 0;
            g1 = v1 ? (size_t)g_tok[e * NTOK + lr1] : 0;
        } else {
            v0 = lr0 < m;
            v1 = lr1 < m;
            g0 = (size_t)e * NTOK + (v0 ? (size_t)lr0 : 0);
            g1 = (size_t)e * NTOK + (v1 ? (size_t)lr1 : 0);
        }
        aph0 = Ah + g0 * K + ac8 * 8;
        apl0 = Al + g0 * K + ac8 * 8;
        aph1 = Ah + g1 * K + ac8 * 8;
        apl1 = Al + g1 * K + ac8 * 8;
        asz0 = v0 ? 16 : 0;
        asz1 = v1 ? 16 : 0;
    }
    int br = tid >> 4;
    int bc8 = tid & 15;

    int wid = tid >> 5;
    int lane = tid & 31;
    int wm = (wid >> 2) * 64;
    int wn = (wid & 3) * 32;

    float acc[4][4][4];
    #pragma unroll
    for (int i = 0; i < 4; i++) {
        #pragma unroll
        for (int j = 0; j < 4; j++) {
            #pragma unroll
            for (int r = 0; r < 4; r++) acc[i][j][r] = 0.f;
        }
    }

    int NC = K / 32;
    tg_load(sA, sB, 0, 0, ar, ac8, br, bc8, aph0, apl0, asz0, aph1, apl1, asz1, Bh, Bl, N, bx);

    for (int c = 0; c < NC; c++) {
        int buf = c & 1;
        if (c + 1 < NC) {
            tg_load(sA, sB, buf ^ 1, (c + 1) * 32, ar, ac8, br, bc8,
                    aph0, apl0, asz0, aph1, apl1, asz1, Bh, Bl, N, bx);
            asm volatile("cp.async.wait_group 1;\n");
        } else {
            asm volatile("cp.async.wait_group 0;\n");
        }
        __syncthreads();

        uint32_t abase = sA + buf * 20480;
        uint32_t bbase = sB + buf * 17408;

        #pragma unroll
        for (int kk = 0; kk < 32; kk += 16) {
            uint32_t ah[4][4], al[4][4], bh[2][4], bl[2][4];
            int arow = wm + (lane & 15);
            int acolb = (kk + (lane >> 4) * 8) * 2;
            #pragma unroll
            for (int i = 0; i < 4; i++) {
                uint32_t off = abase + (arow + i*16)*80 + acolb;
                ldsm4(ah[i], off);
                ldsm4(al[i], off + 10240);
            }
            int brow = kk + (lane & 15);
            #pragma unroll
            for (int j = 0; j < 2; j++) {
                uint32_t off = bbase + brow*272 + (wn + j*16 + (lane >> 4)*8)*2;
                ldsm4t(bh[j], off);
                ldsm4t(bl[j], off + 8704);
            }
            #pragma unroll
            for (int i = 0; i < 4; i++) {
                #pragma unroll
                for (int n8 = 0; n8 < 4; n8++) {
                    uint32_t b0h = bh[n8>>1][(n8&1)*2];
                    uint32_t b1h = bh[n8>>1][(n8&1)*2+1];
                    uint32_t b0l = bl[n8>>1][(n8&1)*2];
                    uint32_t b1l = bl[n8>>1][(n8&1)*2+1];
                    mma16816(acc[i][n8], ah[i], b0h, b1h);
                    mma16816(acc[i][n8], al[i], b0h, b1h);
                    mma16816(acc[i][n8], ah[i], b0l, b1l);
                }
            }
        }
        __syncthreads();
    }

    int ln4 = lane >> 2;
    int lc = (lane & 3) * 2;
    #pragma unroll
    for (int i = 0; i < 4; i++) {
        int r0 = wm + i * 16 + ln4;
        #pragma unroll
        for (int n8 = 0; n8 < 4; n8++) {
            int gc = bx + wn + n8 * 8 + lc;
            float* a = acc[i][n8];
            if (mode == 0) {
                size_t o0 = (size_t)(by + r0) * N + gc;
                size_t o1 = o0 + (size_t)8 * N;
                if (Cadd) {
                    C[o0]   = a[0] + Cadd[o0];
                    C[o0+1] = a[1] + Cadd[o0+1];
                    C[o1]   = a[2] + Cadd[o1];
                    C[o1+1] = a[3] + Cadd[o1+1];
                } else {
                    float2 w0; w0.x = a[0]; w0.y = a[1];
                    float2 w1; w1.x = a[2]; w1.y = a[3];
                    *(float2*)(C + o0) = w0;
                    *(float2*)(C + o1) = w1;
                }
            } else if (mode == 1) {
                int s0 = by + r0;
                int s1 = s0 + 8;
                if (s0 < m) {
                    float2 w0; w0.x = a[0]; w0.y = a[1];
                    *(float2*)(C + ((size_t)e*NTOK + s0)*N + gc) = w0;
                }
                if (s1 < m) {
                    float2 w1; w1.x = a[2]; w1.y = a[3];
                    *(float2*)(C + ((size_t)e*NTOK + s1)*N + gc) = w1;
                }
            } else {
                int s0 = by + r0;
                int s1 = s0 + 8;
                if (s0 < m) {
                    int tk = g_tok[e*NTOK + s0];
                    float w = g_wgt[e*NTOK + s0];
                    atomicAdd(&C[(size_t)tk*N + gc],   w * a[0]);
                    atomicAdd(&C[(size_t)tk*N + gc+1], w * a[1]);
                }
                if (s1 < m) {
                    int tk = g_tok[e*NTOK + s1];
                    float w = g_wgt[e*NTOK + s1];
                    atomicAdd(&C[(size_t)tk*N + gc],   w * a[2]);
                    atomicAdd(&C[(size_t)tk*N + gc+1], w * a[3]);
                }
            }
        }
    }
}

// -------- flash attention, 128-row q tiles, packed f32x2 FMA ---------------
__global__ __launch_bounds__(128) void flash_k() {
    int qt = blockIdx.x;
    int h = blockIdx.y;
    int b = blockIdx.z;
    int g = h >> 2;
    int tid = threadIdx.x;
    int qrow = qt * 128 + tid;
    size_t t = (size_t)b * NS + qrow;

    unsigned long long q2[32], o2[32];
    const float4* qp = (const float4*)(g_qkv + t * QKVN + h * DH);
    #pragma unroll
    for (int i = 0; i < 16; i++) {
        float4 v = qp[i];
        q2[2*i]   = pk2(v.x * 0.125f, v.y * 0.125f);
        q2[2*i+1] = pk2(v.z * 0.125f, v.w * 0.125f);
        o2[2*i] = 0ULL;
        o2[2*i+1] = 0ULL;
    }
    float m = -INFINITY, l = 0.f;

    __shared__ float4 Ks[32][16];
    __shared__ float4 Vs[32][16];

    int ktmax = (qt * 128 + 127) >> 5;
    for (int kt = 0; kt <= ktmax; kt++) {
        __syncthreads();
        #pragma unroll
        for (int i = 0; i < 4; i++) {
            int f = tid + i * 128;
            int r = f >> 4;
            int c = f & 15;
            size_t krow = (size_t)b * NS + kt * 32 + r;
            Ks[r][c] = ((const float4*)(g_qkv + krow * QKVN + 1024 + g * DH))[c];
            Vs[r][c] = ((const float4*)(g_qkv + krow * QKVN + 1280 + g * DH))[c];
        }
        __syncthreads();

        float s[32];
        int kbase = kt * 32;
        #pragma unroll
        for (int j = 0; j < 32; j++) {
            const ull2_t* kr = (const ull2_t*)Ks[j];
            unsigned long long acc2 = 0ULL;
            #pragma unroll
            for (int c = 0; c < 16; c++) {
                ull2_t kv = kr[c];
                acc2 = fma2(q2[2*c], kv.x, acc2);
                acc2 = fma2(q2[2*c+1], kv.y, acc2);
            }
            float a0, a1;
            upk2(acc2, &a0, &a1);
            s[j] = (kbase + j <= qrow) ? (a0 + a1) : -1e9f;
        }
        float mt = m;
        #pragma unroll
        for (int j = 0; j < 32; j++) mt = fmaxf(mt, s[j]);
        float scalef = __expf(m - mt);
        l *= scalef;
        unsigned long long sc2 = pk2(scalef, scalef);
        #pragma unroll
        for (int i = 0; i < 32; i++) o2[i] = mul2(o2[i], sc2);
        #pragma unroll
        for (int j = 0; j < 32; j++) {
            float p = __expf(s[j] - mt);
            l += p;
            unsigned long long p2 = pk2(p, p);
            const ull2_t* vr = (const ull2_t*)Vs[j];
            #pragma unroll
            for (int c = 0; c < 16; c++) {
                ull2_t vv = vr[c];
                o2[2*c]   = fma2(p2, vv.x, o2[2*c]);
                o2[2*c+1] = fma2(p2, vv.y, o2[2*c+1]);
            }
        }
        m = mt;
    }
    float inv = 1.0f / l;
    uint32_t* oh = (uint32_t*)(g_atth + t * NHID + h * DH);
    uint32_t* ol = (uint32_t*)(g_attl + t * NHID + h * DH);
    #pragma unroll
    for (int i = 0; i < 16; i++) {
        float a0, a1, a2, a3;
        upk2(o2[2*i], &a0, &a1);
        upk2(o2[2*i+1], &a2, &a3);
        a0 *= inv; a1 *= inv; a2 *= inv; a3 *= inv;
        uint32_t l0, l1;
        uint32_t h0 = pack_hi2(a0, a1, &l0);
        uint32_t h1 = pack_hi2(a2, a3, &l1);
        oh[i*2]   = h0;
        oh[i*2+1] = h1;
        ol[i*2]   = l0;
        ol[i*2+1] = l1;
    }
}

// ---------------- router (reads g_xn) ----------------
__global__ void router_k(const float* __restrict__ Wgate) {
    int t = blockIdx.x;
    float acc[NE];
    #pragma unroll
    for (int e = 0; e < NE; e++) acc[e] = 0.f;
    for (int h = threadIdx.x; h < NHID; h += 128) {
        float xv = g_xn[(size_t)t * NHID + h];
        const float4* wr = (const float4*)(Wgate + (size_t)h * NE);
        float4 w0 = wr[0];
        float4 w1 = wr[1];
        acc[0] += xv*w0.x; acc[1] += xv*w0.y; acc[2] += xv*w0.z; acc[3] += xv*w0.w;
        acc[4] += xv*w1.x; acc[5] += xv*w1.y; acc[6] += xv*w1.z; acc[7] += xv*w1.w;
    }
    #pragma unroll
    for (int e = 0; e < NE; e++) {
        #pragma unroll
        for (int o = 16; o; o >>= 1) acc[e] += __shfl_down_sync(0xffffffffu, acc[e], o);
    }
    __shared__ float sm[4][NE];
    int warp = threadIdx.x >> 5;
    int lane = threadIdx.x & 31;
    if (lane == 0) {
        for (int e = 0; e < NE; e++) sm[warp][e] = acc[e];
    }
    __syncthreads();
    if (threadIdx.x == 0) {
        float lg[NE];
        float mx = -INFINITY;
        for (int e = 0; e < NE; e++) {
            lg[e] = sm[0][e] + sm[1][e] + sm[2][e] + sm[3][e];
            mx = fmaxf(mx, lg[e]);
        }
        float p[NE];
        float sum = 0.f;
        for (int e = 0; e < NE; e++) { p[e] = expf(lg[e] - mx); sum += p[e]; }
        float inv = 1.0f / sum;
        for (int e = 0; e < NE; e++) p[e] *= inv;
        int i1 = 0;
        float b1 = p[0];
        for (int e = 1; e < NE; e++) {
            if (p[e] > b1) { b1 = p[e]; i1 = e; }
        }
        int i2 = -1;
        float b2 = -INFINITY;
        for (int e = 0; e < NE; e++) {
            if (e != i1 && p[e] > b2) { b2 = p[e]; i2 = e; }
        }
        int s1 = atomicAdd(&g_cnt[i1], 1);
        g_tok[i1 * NTOK + s1] = t;
        g_wgt[i1 * NTOK + s1] = b1;
        int s2 = atomicAdd(&g_cnt[i2], 1);
        g_tok[i2 * NTOK + s2] = t;
        g_wgt[i2 * NTOK + s2] = b2;
    }
}

__global__ void zero_cnt_k() {
    if (threadIdx.x < NE) g_cnt[threadIdx.x] = 0;
}

// silu(gate)*up from packed g_GU[slot][4096] -> split bf16 g_Gh/g_Gl [slot][2048]
__global__ void silu_k() {
    int slot = blockIdx.x;
    int e = blockIdx.y;
    if (slot >= g_cnt[e]) return;
    size_t b  = ((size_t)e * NTOK + slot) * GUN;
    size_t ob = ((size_t)e * NTOK + slot) * NF;
    for (int f = threadIdx.x * 4; f < NF; f += 1024) {
        float4 g4 = *(const float4*)(g_GU + b + f);
        float4 u4 = *(const float4*)(g_GU + b + NF + f);
        float a0 = g4.x / (1.f + __expf(-g4.x)) * u4.x;
        float a1 = g4.y / (1.f + __expf(-g4.y)) * u4.y;
        float a2 = g4.z / (1.f + __expf(-g4.z)) * u4.z;
        float a3 = g4.w / (1.f + __expf(-g4.w)) * u4.w;
        uint32_t l0, l1;
        uint32_t h0 = pack_hi2(a0, a1, &l0);
        uint32_t h1 = pack_hi2(a2, a3, &l1);
        uint32_t* ph = (uint32_t*)(g_Gh + ob + f);
        uint32_t* pl = (uint32_t*)(g_Gl + ob + f);
        ph[0] = h0;
        ph[1] = h1;
        pl[0] = l0;
        pl[1] = l1;
    }
}

// out = g_h (residual base for down-proj scatter)
__global__ void copy_k(float* __restrict__ dst) {
    size_t i = (size_t)blockIdx.x * 256 + threadIdx.x;
    ((float4*)dst)[i] = ((const float4*)g_h)[i];
}

// ---------------- launch ----------------
extern "C" void kernel_launch(void* const* d_in, const int* in_sizes, int n_in,
                              void* d_out, int out_size) {
    (void)in_sizes; (void)n_in; (void)out_size;
    const float* x     = (const float*)d_in[0];
    const float* w_ln1 = (const float*)d_in[2];
    const float* w_ln2 = (const float*)d_in[3];
    const float* Wq    = (const float*)d_in[4];
    const float* Wk    = (const float*)d_in[5];
    const float* Wv    = (const float*)d_in[6];
    const float* Wo    = (const float*)d_in[7];
    const float* Wgate = (const float*)d_in[8];
    const float* Wg    = (const float*)d_in[9];
    const float* Wu    = (const float*)d_in[10];
    const float* Wd    = (const float*)d_in[11];
    float* out = (float*)d_out;

    cudaFuncSetAttribute(tgemm_k, cudaFuncAttributeMaxDynamicSharedMemorySize, TG_SMEM);

    // 0) ln1 (fused split)
    rmsnorm_split_k<<<NTOK, 256>>>(x, w_ln1, 0, 0);
    // 1) fused QKV weight split-pack
    split_pack_qkv_k<<<NHID*QKVN/4/256, 256>>>((const float4*)Wq, (const float4*)Wk, (const float4*)Wv);
    // 2) fused QKV projection
    tgemm_k<<<dim3(QKVN/128, NTOK/128), 256, TG_SMEM>>>(0, 0, 0);
    // 3) attention  <-- profiled slot
    flash_k<<<dim3(NS/128, NHEADS, NB), 128>>>();
    // 4) Wo split
    split_k<<<NHID*NHID/4/256, 256>>>((const float4*)Wo, NHID*NHID/4, 1);
    // 5) output proj + residual
    tgemm_k<<<dim3(NHID/128, NTOK/128), 256, TG_SMEM>>>(1, x, 0);
    // 6) ln2 (fused split + fp32 for router)
    rmsnorm_split_k<<<NTOK, 256>>>(0, w_ln2, 1, 1);
    // 7) routing
    zero_cnt_k<<<1, 32>>>();
    router_k<<<NTOK, 128>>>(Wgate);
    // 8) MoE weight splits
    split_pack_k<<<NE*NHID*NF/4/256, 256>>>((const float4*)Wg, NE*NHID*NF/4, NF, GUN, 0);
    split_pack_k<<<NE*NHID*NF/4/256, 256>>>((const float4*)Wu, NE*NHID*NF/4, NF, GUN, NF);
    // 9) fused gate|up grouped GEMM
    tgemm_k<<<dim3(GUN/128, NTOK/128, NE), 256, TG_SMEM>>>(2, 0, 0);
    // 10) silu * up -> split
    silu_k<<<dim3(NTOK, NE), 256>>>();
    // 11) Wd split
    split_k<<<NE*NF*NHID/4/256, 256>>>((const float4*)Wd, NE*NF*NHID/4, 3);
    // 12) residual copy + down-proj scatter
    copy_k<<<NTOK, 256>>>(out);
    tgemm_k<<<dim3(NHID/128, NTOK/128, NE), 256, TG_SMEM>>>(3, 0, out);
}

// round 10
// speedup vs baseline: 1.2297x; 1.2297x over previous
#include <cuda_runtime.h>
#include <cuda_bf16.h>
#include <math.h>
#include <stdint.h>

#define NB    4
#define NS    1024
#define NHID  1024
#define NHEADS 16
#define NKVH  4
#define DH    64
#define NE    8
#define NF    2048
#define NTOK  4096
#define QKVN  1536
#define GUN   4096

// ---------------- scratch (device globals, allocation-free) ----------------
__device__ float g_xn[NTOK * NHID];
__device__ __nv_bfloat16 g_xnh[NTOK * NHID];
__device__ __nv_bfloat16 g_xnl[NTOK * NHID];
__device__ float g_qkv[NTOK * QKVN];
__device__ __nv_bfloat16 g_atth[NTOK * NHID];
__device__ __nv_bfloat16 g_attl[NTOK * NHID];
__device__ float g_h[NTOK * NHID];
__device__ __nv_bfloat16 g_wqkvh[NHID * QKVN];
__device__ __nv_bfloat16 g_wqkvl[NHID * QKVN];
__device__ __nv_bfloat16 g_woh[NHID * NHID];
__device__ __nv_bfloat16 g_wol[NHID * NHID];
__device__ __nv_bfloat16 g_wguh[NE * NHID * GUN];
__device__ __nv_bfloat16 g_wgul[NE * NHID * GUN];
__device__ __nv_bfloat16 g_wdh[NE * NF * NHID];
__device__ __nv_bfloat16 g_wdl[NE * NF * NHID];
__device__ float g_GU[(size_t)NE * NTOK * GUN];
__device__ __nv_bfloat16 g_Gh[NE * NTOK * NF];
__device__ __nv_bfloat16 g_Gl[NE * NTOK * NF];
__device__ int   g_cnt[NE];
__device__ int   g_tok[NE * NTOK];
__device__ float g_wgt[NE * NTOK];
// attention operand splits: Q [b][h][s][d] (scaled), Kt [b][g][d][s], V [b][g][s][d]
__device__ __nv_bfloat16 g_qh[NB * NHEADS * NS * DH];
__device__ __nv_bfloat16 g_ql[NB * NHEADS * NS * DH];
__device__ __nv_bfloat16 g_kth[NB * NKVH * DH * NS];
__device__ __nv_bfloat16 g_ktl[NB * NKVH * DH * NS];
__device__ __nv_bfloat16 g_vh[NB * NKVH * NS * DH];
__device__ __nv_bfloat16 g_vl[NB * NKVH * NS * DH];

// ---------------- helpers ----------------
__device__ __forceinline__ uint32_t pack_hi2(float a, float b, uint32_t* lo) {
    __nv_bfloat16 ha = __float2bfloat16(a);
    __nv_bfloat16 hb = __float2bfloat16(b);
    __nv_bfloat16 la = __float2bfloat16(a - __bfloat162float(ha));
    __nv_bfloat16 lb = __float2bfloat16(b - __bfloat162float(hb));
    *lo = ((uint32_t)__bfloat16_as_ushort(lb) << 16) | (uint32_t)__bfloat16_as_ushort(la);
    return ((uint32_t)__bfloat16_as_ushort(hb) << 16) | (uint32_t)__bfloat16_as_ushort(ha);
}
__device__ __forceinline__ void splt1(float v, __nv_bfloat16* ph, __nv_bfloat16* pl) {
    __nv_bfloat16 h = __float2bfloat16(v);
    *ph = h;
    *pl = __float2bfloat16(v - __bfloat162float(h));
}
__device__ __forceinline__ void ldsm4(uint32_t* r, uint32_t a) {
    asm volatile("ldmatrix.sync.aligned.m8n8.x4.shared.b16 {%0,%1,%2,%3}, [%4];\n"
        : "=r"(r[0]), "=r"(r[1]), "=r"(r[2]), "=r"(r[3]) : "r"(a));
}
__device__ __forceinline__ void ldsm4t(uint32_t* r, uint32_t a) {
    asm volatile("ldmatrix.sync.aligned.m8n8.x4.trans.shared.b16 {%0,%1,%2,%3}, [%4];\n"
        : "=r"(r[0]), "=r"(r[1]), "=r"(r[2]), "=r"(r[3]) : "r"(a));
}
__device__ __forceinline__ void mma16816(float* d, const uint32_t* a, uint32_t b0, uint32_t b1) {
    asm volatile("mma.sync.aligned.m16n8k16.row.col.f32.bf16.bf16.f32 "
        "{%0,%1,%2,%3},{%4,%5,%6,%7},{%8,%9},{%0,%1,%2,%3};\n"
        : "+f"(d[0]), "+f"(d[1]), "+f"(d[2]), "+f"(d[3])
        : "r"(a[0]), "r"(a[1]), "r"(a[2]), "r"(a[3]), "r"(b0), "r"(b1));
}
__device__ __forceinline__ void cpa16(uint32_t dst, const void* src, int sz) {
    asm volatile("cp.async.cg.shared.global [%0], [%1], 16, %2;\n"
        :: "r"(dst), "l"(src), "r"(sz));
}

// ---------------- fused RMSNorm + bf16 hi/lo split ----------------
__global__ void rmsnorm_split_k(const float* __restrict__ xext, const float* __restrict__ w,
                                int use_h, int write_xn) {
    int t = blockIdx.x;
    const float* src = use_h ? (const float*)g_h : xext;
    const float4* xr = (const float4*)(src + (size_t)t * NHID);
    float4 v = xr[threadIdx.x];
    float ss = v.x*v.x + v.y*v.y + v.z*v.z + v.w*v.w;
    #pragma unroll
    for (int o = 16; o; o >>= 1) ss += __shfl_down_sync(0xffffffffu, ss, o);
    __shared__ float red[8];
    if ((threadIdx.x & 31) == 0) red[threadIdx.x >> 5] = ss;
    __syncthreads();
    if (threadIdx.x < 8) {
        float s = red[threadIdx.x];
        #pragma unroll
        for (int o = 4; o; o >>= 1) s += __shfl_down_sync(0xffu, s, o);
        if (threadIdx.x == 0) red[0] = s;
    }
    __syncthreads();
    float rs = rsqrtf(red[0] * (1.0f / NHID) + 1e-6f);
    float4 wv = ((const float4*)w)[threadIdx.x];
    float4 ov;
    ov.x = v.x * rs * wv.x;
    ov.y = v.y * rs * wv.y;
    ov.z = v.z * rs * wv.z;
    ov.w = v.w * rs * wv.w;
    if (write_xn) {
        ((float4*)(g_xn + (size_t)t * NHID))[threadIdx.x] = ov;
    }
    uint32_t l0, l1;
    uint32_t h0 = pack_hi2(ov.x, ov.y, &l0);
    uint32_t h1 = pack_hi2(ov.z, ov.w, &l1);
    uint32_t* ph = (uint32_t*)(g_xnh + (size_t)t * NHID) + threadIdx.x * 2;
    uint32_t* pl = (uint32_t*)(g_xnl + (size_t)t * NHID) + threadIdx.x * 2;
    ph[0] = h0;
    ph[1] = h1;
    pl[0] = l0;
    pl[1] = l1;
}

// ---------------- combined QKV weight split-pack ----------------
__global__ void split_pack_qkv_k(const float4* __restrict__ Wq, const float4* __restrict__ Wk,
                                 const float4* __restrict__ Wv) {
    int i = blockIdx.x * 256 + threadIdx.x;
    int el = i * 4;
    int r = el / QKVN;
    int c = el % QKVN;
    float4 v;
    if (c < 1024)      v = Wq[(r * 1024 + c) / 4];
    else if (c < 1280) v = Wk[(r * 256 + (c - 1024)) / 4];
    else               v = Wv[(r * 256 + (c - 1280)) / 4];
    uint32_t l0, l1;
    uint32_t h0 = pack_hi2(v.x, v.y, &l0);
    uint32_t h1 = pack_hi2(v.z, v.w, &l1);
    uint32_t* ph = (uint32_t*)(g_wqkvh + (size_t)r * QKVN + c);
    uint32_t* pl = (uint32_t*)(g_wqkvl + (size_t)r * QKVN + c);
    ph[0] = h0;
    ph[1] = h1;
    pl[0] = l0;
    pl[1] = l1;
}

// ---------------- plain split: fp32 -> bf16 hi/lo -------------
__global__ void split_k(const float4* __restrict__ ext, int n4, int sel) {
    int i = blockIdx.x * 256 + threadIdx.x;
    if (i >= n4) return;
    uint32_t* dh;
    uint32_t* dl;
    if (sel == 1) { dh = (uint32_t*)g_woh;  dl = (uint32_t*)g_wol; }
    else          { dh = (uint32_t*)g_wdh;  dl = (uint32_t*)g_wdl; }
    float4 v = ext[i];
    uint32_t l0, l1;
    uint32_t h0 = pack_hi2(v.x, v.y, &l0);
    uint32_t h1 = pack_hi2(v.z, v.w, &l1);
    dh[i*2]   = h0;
    dh[i*2+1] = h1;
    dl[i*2]   = l0;
    dl[i*2+1] = l1;
}

// pack columns: src [rows][cs] -> g_wguh/g_wgul [rows][cd] at column offset off
__global__ void split_pack_k(const float4* __restrict__ s, int n4, int cs, int cd, int off) {
    int i = blockIdx.x * 256 + threadIdx.x;
    if (i >= n4) return;
    float4 v = s[i];
    int el = i * 4;
    int r = el / cs;
    int c = el % cs;
    size_t d = (size_t)r * cd + off + c;
    uint32_t l0, l1;
    uint32_t h0 = pack_hi2(v.x, v.y, &l0);
    uint32_t h1 = pack_hi2(v.z, v.w, &l1);
    uint32_t* ph = (uint32_t*)(g_wguh + d);
    uint32_t* pl = (uint32_t*)(g_wgul + d);
    ph[0] = h0;
    ph[1] = h1;
    pl[0] = l0;
    pl[1] = l1;
}

// ---------------- qkv fp32 -> attention bf16 operands ----------------
// Q scaled by 0.125 -> g_qh/g_ql [b][h][s][64]; K -> g_kth/g_ktl [b][g][d][s]; V -> g_vh/g_vl [b][g][s][d]
__global__ void qkvsplit_k() {
    int t = blockIdx.x;
    int b = t >> 10;
    int s = t & 1023;
    const float4* row = (const float4*)(g_qkv + (size_t)t * QKVN);
    #pragma unroll
    for (int k = 0; k < 3; k++) {
        int i = threadIdx.x + k * 128;
        float4 v = row[i];
        int c = i * 4;
        if (c < 1024) {
            int h = c >> 6, d = c & 63;
            size_t q = (((size_t)b * 16 + h) * 1024 + s) * 64 + d;
            uint32_t l0, l1;
            uint32_t h0 = pack_hi2(v.x * 0.125f, v.y * 0.125f, &l0);
            uint32_t h1 = pack_hi2(v.z * 0.125f, v.w * 0.125f, &l1);
            uint32_t* ph = (uint32_t*)(g_qh + q);
            uint32_t* pl = (uint32_t*)(g_ql + q);
            ph[0] = h0; ph[1] = h1;
            pl[0] = l0; pl[1] = l1;
        } else if (c < 1280) {
            int cc = c - 1024;
            int g = cc >> 6, d = cc & 63;
            size_t base = (((size_t)b * 4 + g) * 64 + d) * 1024 + s;
            float arr[4];
            arr[0] = v.x; arr[1] = v.y; arr[2] = v.z; arr[3] = v.w;
            #pragma unroll
            for (int jj = 0; jj < 4; jj++) {
                splt1(arr[jj], &g_kth[base + (size_t)jj * 1024], &g_ktl[base + (size_t)jj * 1024]);
            }
        } else {
            int cc = c - 1280;
            int g = cc >> 6, d = cc & 63;
            size_t base = (((size_t)b * 4 + g) * 1024 + s) * 64 + d;
            uint32_t l0, l1;
            uint32_t h0 = pack_hi2(v.x, v.y, &l0);
            uint32_t h1 = pack_hi2(v.z, v.w, &l1);
            uint32_t* ph = (uint32_t*)(g_vh + base);
            uint32_t* pl = (uint32_t*)(g_vl + base);
            ph[0] = h0; ph[1] = h1;
            pl[0] = l0; pl[1] = l1;
        }
    }
}

// ---------------- tensor-core GEMM (bf16x3), 128x128x32 tiles, 2-stage ------
#define TG_SMEM 75776

__device__ __forceinline__ void tg_load(
        uint32_t sA, uint32_t sB, int stg, int k0,
        int ar, int ac8, int br, int bc8,
        const __nv_bfloat16* aph0, const __nv_bfloat16* apl0, int asz0,
        const __nv_bfloat16* aph1, const __nv_bfloat16* apl1, int asz1,
        const __nv_bfloat16* Bh, const __nv_bfloat16* Bl, int N, int bx) {
    uint32_t a0 = sA + stg * 20480 + ar * 80 + ac8 * 16;
    cpa16(a0,                 aph0 + k0, asz0);
    cpa16(a0 + 10240,         apl0 + k0, asz0);
    cpa16(a0 + 64*80,         aph1 + k0, asz1);
    cpa16(a0 + 10240 + 64*80, apl1 + k0, asz1);
    const __nv_bfloat16* sh0 = Bh + (size_t)(k0 + br) * N + bx + bc8*8;
    const __nv_bfloat16* sl0 = Bl + (size_t)(k0 + br) * N + bx + bc8*8;
    uint32_t b0 = sB + stg * 17408 + br * 272 + bc8 * 16;
    cpa16(b0,                 sh0, 16);
    cpa16(b0 + 8704,          sl0, 16);
    cpa16(b0 + 16*272,        sh0 + (size_t)16*N, 16);
    cpa16(b0 + 8704 + 16*272, sl0 + (size_t)16*N, 16);
    asm volatile("cp.async.commit_group;\n");
}

__global__ __launch_bounds__(256, 2) void tgemm_k(int op, const float* __restrict__ cadd_ext,
                                                  float* __restrict__ cout_ext) {
    extern __shared__ char smraw[];
    uint32_t sA = (uint32_t)__cvta_generic_to_shared(smraw);
    uint32_t sB = sA + 40960;

    const __nv_bfloat16* Ah;
    const __nv_bfloat16* Al;
    const __nv_bfloat16* Bh;
    const __nv_bfloat16* Bl;
    float* C;
    const float* Cadd = 0;
    int N, K, mode;
    if (op == 0) {
        Ah = g_xnh;  Al = g_xnl;  Bh = g_wqkvh; Bl = g_wqkvl;
        C = g_qkv;  N = QKVN; K = NHID; mode = 0;
    } else if (op == 1) {
        Ah = g_atth; Al = g_attl; Bh = g_woh;   Bl = g_wol;
        C = g_h;    Cadd = cadd_ext; N = NHID; K = NHID; mode = 0;
    } else if (op == 2) {
        Ah = g_xnh;  Al = g_xnl;  Bh = g_wguh;  Bl = g_wgul;
        C = g_GU;   N = GUN;  K = NHID; mode = 1;
    } else {
        Ah = g_Gh;   Al = g_Gl;   Bh = g_wdh;   Bl = g_wdl;
        C = cout_ext; N = NHID; K = NF; mode = 2;
    }

    int tid = threadIdx.x;
    int bx = blockIdx.x * 128;
    int by = blockIdx.y * 128;
    int e = blockIdx.z;
    int m = NTOK;
    if (mode != 0) {
        m = g_cnt[e];
        if (by >= m) return;
        Bh += (size_t)e * K * N;
        Bl += (size_t)e * K * N;
    }

    int ar = tid >> 2;
    int ac8 = tid & 3;
    const __nv_bfloat16* aph0;
    const __nv_bfloat16* apl0;
    const __nv_bfloat16* aph1;
    const __nv_bfloat16* apl1;
    int asz0, asz1;
    {
        int lr0 = by + ar;
        int lr1 = by + ar + 64;
        size_t g0, g1;
        bool v0 = true, v1 = true;
        if (mode == 0) {
            g0 = (size_t)lr0;
            g1 = (size_t)lr1;
        } else if (mode == 1) {
            v0 = lr0 < m;
            v1 = lr1 < m;
            g0 = v0 ? (size_t)g_tok[e * NTOK + lr0] : 0;
            g1 = v1 ? (size_t)g_tok[e * NTOK + lr1] : 0;
        } else {
            v0 = lr0 < m;
            v1 = lr1 < m;
            g0 = (size_t)e * NTOK + (v0 ? (size_t)lr0 : 0);
            g1 = (size_t)e * NTOK + (v1 ? (size_t)lr1 : 0);
        }
        aph0 = Ah + g0 * K + ac8 * 8;
        apl0 = Al + g0 * K + ac8 * 8;
        aph1 = Ah + g1 * K + ac8 * 8;
        apl1 = Al + g1 * K + ac8 * 8;
        asz0 = v0 ? 16 : 0;
        asz1 = v1 ? 16 : 0;
    }
    int br = tid >> 4;
    int bc8 = tid & 15;

    int wid = tid >> 5;
    int lane = tid & 31;
    int wm = (wid >> 2) * 64;
    int wn = (wid & 3) * 32;

    float acc[4][4][4];
    #pragma unroll
    for (int i = 0; i < 4; i++) {
        #pragma unroll
        for (int j = 0; j < 4; j++) {
            #pragma unroll
            for (int r = 0; r < 4; r++) acc[i][j][r] = 0.f;
        }
    }

    int NC = K / 32;
    tg_load(sA, sB, 0, 0, ar, ac8, br, bc8, aph0, apl0, asz0, aph1, apl1, asz1, Bh, Bl, N, bx);

    for (int c = 0; c < NC; c++) {
        int buf = c & 1;
        if (c + 1 < NC) {
            tg_load(sA, sB, buf ^ 1, (c + 1) * 32, ar, ac8, br, bc8,
                    aph0, apl0, asz0, aph1, apl1, asz1, Bh, Bl, N, bx);
            asm volatile("cp.async.wait_group 1;\n");
        } else {
            asm volatile("cp.async.wait_group 0;\n");
        }
        __syncthreads();

        uint32_t abase = sA + buf * 20480;
        uint32_t bbase = sB + buf * 17408;

        #pragma unroll
        for (int kk = 0; kk < 32; kk += 16) {
            uint32_t ah[4][4], al[4][4], bh[2][4], bl[2][4];
            int arow = wm + (lane & 15);
            int acolb = (kk + (lane >> 4) * 8) * 2;
            #pragma unroll
            for (int i = 0; i < 4; i++) {
                uint32_t off = abase + (arow + i*16)*80 + acolb;
                ldsm4(ah[i], off);
                ldsm4(al[i], off + 10240);
            }
            int brow = kk + (lane & 15);
            #pragma unroll
            for (int j = 0; j < 2; j++) {
                uint32_t off = bbase + brow*272 + (wn + j*16 + (lane >> 4)*8)*2;
                ldsm4t(bh[j], off);
                ldsm4t(bl[j], off + 8704);
            }
            #pragma unroll
            for (int i = 0; i < 4; i++) {
                #pragma unroll
                for (int n8 = 0; n8 < 4; n8++) {
                    uint32_t b0h = bh[n8>>1][(n8&1)*2];
                    uint32_t b1h = bh[n8>>1][(n8&1)*2+1];
                    uint32_t b0l = bl[n8>>1][(n8&1)*2];
                    uint32_t b1l = bl[n8>>1][(n8&1)*2+1];
                    mma16816(acc[i][n8], ah[i], b0h, b1h);
                    mma16816(acc[i][n8], al[i], b0h, b1h);
                    mma16816(acc[i][n8], ah[i], b0l, b1l);
                }
            }
        }
        __syncthreads();
    }

    int ln4 = lane >> 2;
    int lc = (lane & 3) * 2;
    #pragma unroll
    for (int i = 0; i < 4; i++) {
        int r0 = wm + i * 16 + ln4;
        #pragma unroll
        for (int n8 = 0; n8 < 4; n8++) {
            int gc = bx + wn + n8 * 8 + lc;
            float* a = acc[i][n8];
            if (mode == 0) {
                size_t o0 = (size_t)(by + r0) * N + gc;
                size_t o1 = o0 + (size_t)8 * N;
                if (Cadd) {
                    C[o0]   = a[0] + Cadd[o0];
                    C[o0+1] = a[1] + Cadd[o0+1];
                    C[o1]   = a[2] + Cadd[o1];
                    C[o1+1] = a[3] + Cadd[o1+1];
                } else {
                    float2 w0; w0.x = a[0]; w0.y = a[1];
                    float2 w1; w1.x = a[2]; w1.y = a[3];
                    *(float2*)(C + o0) = w0;
                    *(float2*)(C + o1) = w1;
                }
            } else if (mode == 1) {
                int s0 = by + r0;
                int s1 = s0 + 8;
                if (s0 < m) {
                    float2 w0; w0.x = a[0]; w0.y = a[1];
                    *(float2*)(C + ((size_t)e*NTOK + s0)*N + gc) = w0;
                }
                if (s1 < m) {
                    float2 w1; w1.x = a[2]; w1.y = a[3];
                    *(float2*)(C + ((size_t)e*NTOK + s1)*N + gc) = w1;
                }
            } else {
                int s0 = by + r0;
                int s1 = s0 + 8;
                if (s0 < m) {
                    int tk = g_tok[e*NTOK + s0];
                    float w = g_wgt[e*NTOK + s0];
                    atomicAdd(&C[(size_t)tk*N + gc],   w * a[0]);
                    atomicAdd(&C[(size_t)tk*N + gc+1], w * a[1]);
                }
                if (s1 < m) {
                    int tk = g_tok[e*NTOK + s1];
                    float w = g_wgt[e*NTOK + s1];
                    atomicAdd(&C[(size_t)tk*N + gc],   w * a[2]);
                    atomicAdd(&C[(size_t)tk*N + gc+1], w * a[3]);
                }
            }
        }
    }
}

// ---------------- mma flash attention ----------------
// block = 128 thr (4 warps), handles (b, h, 64 q rows). bf16x3 for S and PV.
// smem: Qh/Ql 64x144 each; 2 stages of (Kh,Kl,Vh,Vl) 64x144 each.
#define FPITCH 144
#define FL_SMEM 92160

__device__ __forceinline__ void fl_load_kv(uint32_t base, int b, int g, int kv0, int tid) {
    #pragma unroll
    for (int j = 0; j < 8; j++) {
        int cc = tid + j * 128;
        int which = cc >> 9;
        int c2 = cc & 511;
        int row = c2 >> 3;
        int c8 = c2 & 7;
        size_t koff = (((size_t)b * 4 + g) * 64 + row) * 1024 + kv0 + c8 * 8;
        const __nv_bfloat16* src = which ? (g_ktl + koff) : (g_kth + koff);
        cpa16(base + which * 9216 + row * FPITCH + c8 * 16, src, 16);
    }
    #pragma unroll
    for (int j = 0; j < 8; j++) {
        int cc = tid + j * 128;
        int which = cc >> 9;
        int c2 = cc & 511;
        int row = c2 >> 3;
        int c8 = c2 & 7;
        size_t voff = (((size_t)b * 4 + g) * 1024 + kv0 + row) * 64 + c8 * 8;
        const __nv_bfloat16* src = which ? (g_vl + voff) : (g_vh + voff);
        cpa16(base + 18432 + which * 9216 + row * FPITCH + c8 * 16, src, 16);
    }
    asm volatile("cp.async.commit_group;\n");
}

__global__ __launch_bounds__(128) void flashmma_k() {
    extern __shared__ char fsm[];
    uint32_t sb = (uint32_t)__cvta_generic_to_shared(fsm);
    int qt = blockIdx.x;
    int h = blockIdx.y;
    int b = blockIdx.z;
    int g = h >> 2;
    int tid = threadIdx.x;
    int wid = tid >> 5;
    int lane = tid & 31;

    // load Q tile (hi+lo): 1024 x 16B chunks
    #pragma unroll
    for (int j = 0; j < 8; j++) {
        int cc = tid + j * 128;
        int which = cc >> 9;
        int c2 = cc & 511;
        int row = c2 >> 3;
        int c8 = c2 & 7;
        size_t qoff = (((size_t)b * 16 + h) * 1024 + qt * 64 + row) * 64 + c8 * 8;
        const __nv_bfloat16* src = which ? (g_ql + qoff) : (g_qh + qoff);
        cpa16(sb + which * 9216 + row * FPITCH + c8 * 16, src, 16);
    }
    asm volatile("cp.async.commit_group;\n");
    fl_load_kv(sb + 18432, b, g, 0, tid);
    asm volatile("cp.async.wait_group 1;\n");
    __syncthreads();

    // A fragments from Q (per warp: rows wid*16..+16)
    uint32_t ah[4][4], al[4][4];
    {
        int arow = wid * 16 + (lane & 15);
        #pragma unroll
        for (int j2 = 0; j2 < 4; j2++) {
            uint32_t acol = (uint32_t)(j2 * 16 + (lane >> 4) * 8) * 2;
            ldsm4(ah[j2], sb + arow * FPITCH + acol);
            ldsm4(al[j2], sb + 9216 + arow * FPITCH + acol);
        }
    }

    float m0 = -INFINITY, m1 = -INFINITY, l0 = 0.f, l1 = 0.f;
    float oacc[8][4];
    #pragma unroll
    for (int i = 0; i < 8; i++) {
        #pragma unroll
        for (int r = 0; r < 4; r++) oacc[i][r] = 0.f;
    }

    int r0g = qt * 64 + wid * 16 + (lane >> 2);   // global row of this thread's row0

    for (int kt = 0; kt <= qt; kt++) {
        int st = kt & 1;
        if (kt < qt) {
            fl_load_kv(sb + 18432 + (st ^ 1) * 36864, b, g, (kt + 1) * 64, tid);
            asm volatile("cp.async.wait_group 1;\n");
        } else {
            asm volatile("cp.async.wait_group 0;\n");
        }
        __syncthreads();

        uint32_t kb = sb + 18432 + st * 36864;

        // S = Q K^T
        float sacc[8][4];
        #pragma unroll
        for (int i = 0; i < 8; i++) {
            #pragma unroll
            for (int r = 0; r < 4; r++) sacc[i][r] = 0.f;
        }
        #pragma unroll
        for (int j2 = 0; j2 < 4; j2++) {
            uint32_t bh[4][4], bl[4][4];
            int brow = j2 * 16 + (lane & 15);
            #pragma unroll
            for (int ng = 0; ng < 4; ng++) {
                uint32_t off = kb + brow * FPITCH + (uint32_t)(ng * 16 + (lane >> 4) * 8) * 2;
                ldsm4t(bh[ng], off);
                ldsm4t(bl[ng], off + 9216);
            }
            #pragma unroll
            for (int n8 = 0; n8 < 8; n8++) {
                int ng = n8 >> 1;
                int jj = (n8 & 1) * 2;
                uint32_t b0h = bh[ng][jj], b1h = bh[ng][jj+1];
                uint32_t b0l = bl[ng][jj], b1l = bl[ng][jj+1];
                mma16816(sacc[n8], ah[j2], b0h, b1h);
                mma16816(sacc[n8], al[j2], b0h, b1h);
                mma16816(sacc[n8], ah[j2], b0l, b1l);
            }
        }

        // causal mask on diagonal tile
        if (kt == qt) {
            #pragma unroll
            for (int n8 = 0; n8 < 8; n8++) {
                int col = kt * 64 + n8 * 8 + (lane & 3) * 2;
                if (col > r0g)         sacc[n8][0] = -1e9f;
                if (col + 1 > r0g)     sacc[n8][1] = -1e9f;
                if (col > r0g + 8)     sacc[n8][2] = -1e9f;
                if (col + 1 > r0g + 8) sacc[n8][3] = -1e9f;
            }
        }

        // online softmax
        float mx0 = -INFINITY, mx1 = -INFINITY;
        #pragma unroll
        for (int n8 = 0; n8 < 8; n8++) {
            mx0 = fmaxf(mx0, fmaxf(sacc[n8][0], sacc[n8][1]));
            mx1 = fmaxf(mx1, fmaxf(sacc[n8][2], sacc[n8][3]));
        }
        mx0 = fmaxf(mx0, __shfl_xor_sync(0xffffffffu, mx0, 1));
        mx0 = fmaxf(mx0, __shfl_xor_sync(0xffffffffu, mx0, 2));
        mx1 = fmaxf(mx1, __shfl_xor_sync(0xffffffffu, mx1, 1));
        mx1 = fmaxf(mx1, __shfl_xor_sync(0xffffffffu, mx1, 2));
        float nm0 = fmaxf(m0, mx0);
        float nm1 = fmaxf(m1, mx1);
        float f0 = __expf(m0 - nm0);
        float f1 = __expf(m1 - nm1);
        l0 *= f0;
        l1 *= f1;
        #pragma unroll
        for (int n8 = 0; n8 < 8; n8++) {
            oacc[n8][0] *= f0;
            oacc[n8][1] *= f0;
            oacc[n8][2] *= f1;
            oacc[n8][3] *= f1;
        }
        m0 = nm0;
        m1 = nm1;
        #pragma unroll
        for (int n8 = 0; n8 < 8; n8++) {
            float p0 = __expf(sacc[n8][0] - nm0);
            float p1 = __expf(sacc[n8][1] - nm0);
            float p2 = __expf(sacc[n8][2] - nm1);
            float p3 = __expf(sacc[n8][3] - nm1);
            l0 += p0 + p1;
            l1 += p2 + p3;
            sacc[n8][0] = p0;
            sacc[n8][1] = p1;
            sacc[n8][2] = p2;
            sacc[n8][3] = p3;
        }

        // O += P V
        uint32_t vb = kb + 18432;
        #pragma unroll
        for (int j2 = 0; j2 < 4; j2++) {
            uint32_t pa[4], pl[4];
            pa[0] = pack_hi2(sacc[2*j2][0],   sacc[2*j2][1],   &pl[0]);
            pa[1] = pack_hi2(sacc[2*j2][2],   sacc[2*j2][3],   &pl[1]);
            pa[2] = pack_hi2(sacc[2*j2+1][0], sacc[2*j2+1][1], &pl[2]);
            pa[3] = pack_hi2(sacc[2*j2+1][2], sacc[2*j2+1][3], &pl[3]);
            uint32_t vh[4][4], vl[4][4];
            int vrow = j2 * 16 + (lane & 15);
            #pragma unroll
            for (int ng = 0; ng < 4; ng++) {
                uint32_t off = vb + vrow * FPITCH + (uint32_t)(ng * 16 + (lane >> 4) * 8) * 2;
                ldsm4t(vh[ng], off);
                ldsm4t(vl[ng], off + 9216);
            }
            #pragma unroll
            for (int n8 = 0; n8 < 8; n8++) {
                int ng = n8 >> 1;
                int jj = (n8 & 1) * 2;
                uint32_t b0h = vh[ng][jj], b1h = vh[ng][jj+1];
                uint32_t b0l = vl[ng][jj], b1l = vl[ng][jj+1];
                mma16816(oacc[n8], pa, b0h, b1h);
                mma16816(oacc[n8], pl, b0h, b1h);
                mma16816(oacc[n8], pa, b0l, b1l);
            }
        }
        __syncthreads();
    }

    // epilogue
    l0 += __shfl_xor_sync(0xffffffffu, l0, 1);
    l0 += __shfl_xor_sync(0xffffffffu, l0, 2);
    l1 += __shfl_xor_sync(0xffffffffu, l1, 1);
    l1 += __shfl_xor_sync(0xffffffffu, l1, 2);
    float i0 = 1.0f / l0;
    float i1 = 1.0f / l1;
    size_t t0 = (size_t)b * 1024 + r0g;
    size_t t1 = t0 + 8;
    #pragma unroll
    for (int n8 = 0; n8 < 8; n8++) {
        int col = h * 64 + n8 * 8 + (lane & 3) * 2;
        uint32_t lo;
        uint32_t hi = pack_hi2(oacc[n8][0] * i0, oacc[n8][1] * i0, &lo);
        *(uint32_t*)(g_atth + t0 * NHID + col) = hi;
        *(uint32_t*)(g_attl + t0 * NHID + col) = lo;
        hi = pack_hi2(oacc[n8][2] * i1, oacc[n8][3] * i1, &lo);
        *(uint32_t*)(g_atth + t1 * NHID + col) = hi;
        *(uint32_t*)(g_attl + t1 * NHID + col) = lo;
    }
}

// ---------------- router (reads g_xn) ----------------
__global__ void router_k(const float* __restrict__ Wgate) {
    int t = blockIdx.x;
    float acc[NE];
    #pragma unroll
    for (int e = 0; e < NE; e++) acc[e] = 0.f;
    for (int h = threadIdx.x; h < NHID; h += 128) {
        float xv = g_xn[(size_t)t * NHID + h];
        const float4* wr = (const float4*)(Wgate + (size_t)h * NE);
        float4 w0 = wr[0];
        float4 w1 = wr[1];
        acc[0] += xv*w0.x; acc[1] += xv*w0.y; acc[2] += xv*w0.z; acc[3] += xv*w0.w;
        acc[4] += xv*w1.x; acc[5] += xv*w1.y; acc[6] += xv*w1.z; acc[7] += xv*w1.w;
    }
    #pragma unroll
    for (int e = 0; e < NE; e++) {
        #pragma unroll
        for (int o = 16; o; o >>= 1) acc[e] += __shfl_down_sync(0xffffffffu, acc[e], o);
    }
    __shared__ float sm[4][NE];
    int warp = threadIdx.x >> 5;
    int lane = threadIdx.x & 31;
    if (lane == 0) {
        for (int e = 0; e < NE; e++) sm[warp][e] = acc[e];
    }
    __syncthreads();
    if (threadIdx.x == 0) {
        float lg[NE];
        float mx = -INFINITY;
        for (int e = 0; e < NE; e++) {
            lg[e] = sm[0][e] + sm[1][e] + sm[2][e] + sm[3][e];
            mx = fmaxf(mx, lg[e]);
        }
        float p[NE];
        float sum = 0.f;
        for (int e = 0; e < NE; e++) { p[e] = expf(lg[e] - mx); sum += p[e]; }
        float inv = 1.0f / sum;
        for (int e = 0; e < NE; e++) p[e] *= inv;
        int i1 = 0;
        float b1 = p[0];
        for (int e = 1; e < NE; e++) {
            if (p[e] > b1) { b1 = p[e]; i1 = e; }
        }
        int i2 = -1;
        float b2 = -INFINITY;
        for (int e = 0; e < NE; e++) {
            if (e != i1 && p[e] > b2) { b2 = p[e]; i2 = e; }
        }
        int s1 = atomicAdd(&g_cnt[i1], 1);
        g_tok[i1 * NTOK + s1] = t;
        g_wgt[i1 * NTOK + s1] = b1;
        int s2 = atomicAdd(&g_cnt[i2], 1);
        g_tok[i2 * NTOK + s2] = t;
        g_wgt[i2 * NTOK + s2] = b2;
    }
}

__global__ void zero_cnt_k() {
    if (threadIdx.x < NE) g_cnt[threadIdx.x] = 0;
}

// silu(gate)*up from packed g_GU[slot][4096] -> split bf16 g_Gh/g_Gl [slot][2048]
__global__ void silu_k() {
    int slot = blockIdx.x;
    int e = blockIdx.y;
    if (slot >= g_cnt[e]) return;
    size_t b  = ((size_t)e * NTOK + slot) * GUN;
    size_t ob = ((size_t)e * NTOK + slot) * NF;
    for (int f = threadIdx.x * 4; f < NF; f += 1024) {
        float4 g4 = *(const float4*)(g_GU + b + f);
        float4 u4 = *(const float4*)(g_GU + b + NF + f);
        float a0 = g4.x / (1.f + __expf(-g4.x)) * u4.x;
        float a1 = g4.y / (1.f + __expf(-g4.y)) * u4.y;
        float a2 = g4.z / (1.f + __expf(-g4.z)) * u4.z;
        float a3 = g4.w / (1.f + __expf(-g4.w)) * u4.w;
        uint32_t l0, l1;
        uint32_t h0 = pack_hi2(a0, a1, &l0);
        uint32_t h1 = pack_hi2(a2, a3, &l1);
        uint32_t* ph = (uint32_t*)(g_Gh + ob + f);
        uint32_t* pl = (uint32_t*)(g_Gl + ob + f);
        ph[0] = h0;
        ph[1] = h1;
        pl[0] = l0;
        pl[1] = l1;
    }
}

// out = g_h (residual base for down-proj scatter)
__global__ void copy_k(float* __restrict__ dst) {
    size_t i = (size_t)blockIdx.x * 256 + threadIdx.x;
    ((float4*)dst)[i] = ((const float4*)g_h)[i];
}

// ---------------- launch ----------------
extern "C" void kernel_launch(void* const* d_in, const int* in_sizes, int n_in,
                              void* d_out, int out_size) {
    (void)in_sizes; (void)n_in; (void)out_size;
    const float* x     = (const float*)d_in[0];
    const float* w_ln1 = (const float*)d_in[2];
    const float* w_ln2 = (const float*)d_in[3];
    const float* Wq    = (const float*)d_in[4];
    const float* Wk    = (const float*)d_in[5];
    const float* Wv    = (const float*)d_in[6];
    const float* Wo    = (const float*)d_in[7];
    const float* Wgate = (const float*)d_in[8];
    const float* Wg    = (const float*)d_in[9];
    const float* Wu    = (const float*)d_in[10];
    const float* Wd    = (const float*)d_in[11];
    float* out = (float*)d_out;

    cudaFuncSetAttribute(tgemm_k, cudaFuncAttributeMaxDynamicSharedMemorySize, TG_SMEM);
    cudaFuncSetAttribute(flashmma_k, cudaFuncAttributeMaxDynamicSharedMemorySize, FL_SMEM);

    // 0) ln1 (fused split)
    rmsnorm_split_k<<<NTOK, 256>>>(x, w_ln1, 0, 0);
    // 1) fused QKV weight split-pack
    split_pack_qkv_k<<<NHID*QKVN/4/256, 256>>>((const float4*)Wq, (const float4*)Wk, (const float4*)Wv);
    // 2) fused QKV projection
    tgemm_k<<<dim3(QKVN/128, NTOK/128), 256, TG_SMEM>>>(0, 0, 0);
    // 3) qkv -> attention operands (bf16 hi/lo, Kt transposed)
    qkvsplit_k<<<NTOK, 128>>>();
    // 4) mma flash attention
    flashmma_k<<<dim3(NS/64, NHEADS, NB), 128, FL_SMEM>>>();
    // 5) Wo split
    split_k<<<NHID*NHID/4/256, 256>>>((const float4*)Wo, NHID*NHID/4, 1);
    // 6) output proj + residual
    tgemm_k<<<dim3(NHID/128, NTOK/128), 256, TG_SMEM>>>(1, x, 0);
    // 7) ln2 (fused split + fp32 for router)
    rmsnorm_split_k<<<NTOK, 256>>>(0, w_ln2, 1, 1);
    // 8) routing
    zero_cnt_k<<<1, 32>>>();
    router_k<<<NTOK, 128>>>(Wgate);
    // 9) MoE weight splits
    split_pack_k<<<NE*NHID*NF/4/256, 256>>>((const float4*)Wg, NE*NHID*NF/4, NF, GUN, 0);
    split_pack_k<<<NE*NHID*NF/4/256, 256>>>((const float4*)Wu, NE*NHID*NF/4, NF, GUN, NF);
    // 10) fused gate|up grouped GEMM
    tgemm_k<<<dim3(GUN/128, NTOK/128, NE), 256, TG_SMEM>>>(2, 0, 0);
    // 11) silu * up -> split
    silu_k<<<dim3(NTOK, NE), 256>>>();
    // 12) Wd split
    split_k<<<NE*NF*NHID/4/256, 256>>>((const float4*)Wd, NE*NF*NHID/4, 3);
    // 13) residual copy + down-proj scatter
    copy_k<<<NTOK, 256>>>(out);
    tgemm_k<<<dim3(NHID/128, NTOK/128, NE), 256, TG_SMEM>>>(3, 0, out);
}

// round 11
// speedup vs baseline: 2.0724x; 1.6854x over previous
#include <cuda_runtime.h>
#include <cuda_fp16.h>
#include <math.h>
#include <stdint.h>

#define NB    4
#define NS    1024
#define NHID  1024
#define NHEADS 16
#define NKVH  4
#define DH    64
#define NE    8
#define NF    2048
#define NTOK  4096
#define QKVN  1536
#define GUN   4096

// ---------------- scratch (device globals, allocation-free) ----------------
__device__ float g_xn[NTOK * NHID];
__device__ __half g_xnh[NTOK * NHID];
__device__ float g_qkv[NTOK * QKVN];
__device__ __half g_atth[NTOK * NHID];
__device__ float g_h[NTOK * NHID];
__device__ __half g_wqkvh[NHID * QKVN];
__device__ __half g_woh[NHID * NHID];
__device__ __half g_wguh[NE * NHID * GUN];
__device__ __half g_wdh[NE * NF * NHID];
__device__ float g_GU[(size_t)NE * NTOK * GUN];
__device__ __half g_Gh[NE * NTOK * NF];
__device__ int   g_cnt[NE];
__device__ int   g_tok[NE * NTOK];
__device__ float g_wgt[NE * NTOK];
// attention operands: Q [b][h][s][d] (scaled), Kt [b][g][d][s], V [b][g][s][d]
__device__ __half g_qh[NB * NHEADS * NS * DH];
__device__ __half g_kth[NB * NKVH * DH * NS];
__device__ __half g_vh[NB * NKVH * NS * DH];

// ---------------- helpers ----------------
__device__ __forceinline__ uint32_t pack2h(float a, float b) {
    __half2 h = __floats2half2_rn(a, b);
    return *(uint32_t*)&h;
}
__device__ __forceinline__ void ldsm4(uint32_t* r, uint32_t a) {
    asm volatile("ldmatrix.sync.aligned.m8n8.x4.shared.b16 {%0,%1,%2,%3}, [%4];\n"
        : "=r"(r[0]), "=r"(r[1]), "=r"(r[2]), "=r"(r[3]) : "r"(a));
}
__device__ __forceinline__ void ldsm4t(uint32_t* r, uint32_t a) {
    asm volatile("ldmatrix.sync.aligned.m8n8.x4.trans.shared.b16 {%0,%1,%2,%3}, [%4];\n"
        : "=r"(r[0]), "=r"(r[1]), "=r"(r[2]), "=r"(r[3]) : "r"(a));
}
__device__ __forceinline__ void mma16816(float* d, const uint32_t* a, uint32_t b0, uint32_t b1) {
    asm volatile("mma.sync.aligned.m16n8k16.row.col.f32.f16.f16.f32 "
        "{%0,%1,%2,%3},{%4,%5,%6,%7},{%8,%9},{%0,%1,%2,%3};\n"
        : "+f"(d[0]), "+f"(d[1]), "+f"(d[2]), "+f"(d[3])
        : "r"(a[0]), "r"(a[1]), "r"(a[2]), "r"(a[3]), "r"(b0), "r"(b1));
}
__device__ __forceinline__ void cpa16(uint32_t dst, const void* src, int sz) {
    asm volatile("cp.async.cg.shared.global [%0], [%1], 16, %2;\n"
        :: "r"(dst), "l"(src), "r"(sz));
}

// ---------------- fused RMSNorm + fp16 convert ----------------
__global__ void rmsnorm_half_k(const float* __restrict__ xext, const float* __restrict__ w,
                               int use_h, int write_xn) {
    int t = blockIdx.x;
    const float* src = use_h ? (const float*)g_h : xext;
    const float4* xr = (const float4*)(src + (size_t)t * NHID);
    float4 v = xr[threadIdx.x];
    float ss = v.x*v.x + v.y*v.y + v.z*v.z + v.w*v.w;
    #pragma unroll
    for (int o = 16; o; o >>= 1) ss += __shfl_down_sync(0xffffffffu, ss, o);
    __shared__ float red[8];
    if ((threadIdx.x & 31) == 0) red[threadIdx.x >> 5] = ss;
    __syncthreads();
    if (threadIdx.x < 8) {
        float s = red[threadIdx.x];
        #pragma unroll
        for (int o = 4; o; o >>= 1) s += __shfl_down_sync(0xffu, s, o);
        if (threadIdx.x == 0) red[0] = s;
    }
    __syncthreads();
    float rs = rsqrtf(red[0] * (1.0f / NHID) + 1e-6f);
    float4 wv = ((const float4*)w)[threadIdx.x];
    float4 ov;
    ov.x = v.x * rs * wv.x;
    ov.y = v.y * rs * wv.y;
    ov.z = v.z * rs * wv.z;
    ov.w = v.w * rs * wv.w;
    if (write_xn) {
        ((float4*)(g_xn + (size_t)t * NHID))[threadIdx.x] = ov;
    }
    uint32_t* p = (uint32_t*)(g_xnh + (size_t)t * NHID) + threadIdx.x * 2;
    p[0] = pack2h(ov.x, ov.y);
    p[1] = pack2h(ov.z, ov.w);
}

// ---------------- combined QKV weight pack (fp32 -> fp16, packed cols) -----
__global__ void split_pack_qkv_k(const float4* __restrict__ Wq, const float4* __restrict__ Wk,
                                 const float4* __restrict__ Wv) {
    int i = blockIdx.x * 256 + threadIdx.x;
    int el = i * 4;
    int r = el / QKVN;
    int c = el % QKVN;
    float4 v;
    if (c < 1024)      v = Wq[(r * 1024 + c) / 4];
    else if (c < 1280) v = Wk[(r * 256 + (c - 1024)) / 4];
    else               v = Wv[(r * 256 + (c - 1280)) / 4];
    uint32_t* p = (uint32_t*)(g_wqkvh + (size_t)r * QKVN + c);
    p[0] = pack2h(v.x, v.y);
    p[1] = pack2h(v.z, v.w);
}

// ---------------- plain convert: fp32 -> fp16 (sel 1: Wo, else Wd) ----------
__global__ void split_k(const float4* __restrict__ ext, int n4, int sel) {
    int i = blockIdx.x * 256 + threadIdx.x;
    if (i >= n4) return;
    uint32_t* d = (sel == 1) ? (uint32_t*)g_woh : (uint32_t*)g_wdh;
    float4 v = ext[i];
    d[i*2]   = pack2h(v.x, v.y);
    d[i*2+1] = pack2h(v.z, v.w);
}

// pack columns: src [rows][cs] -> g_wguh [rows][cd] at column offset off
__global__ void split_pack_k(const float4* __restrict__ s, int n4, int cs, int cd, int off) {
    int i = blockIdx.x * 256 + threadIdx.x;
    if (i >= n4) return;
    float4 v = s[i];
    int el = i * 4;
    int r = el / cs;
    int c = el % cs;
    size_t d = (size_t)r * cd + off + c;
    uint32_t* p = (uint32_t*)(g_wguh + d);
    p[0] = pack2h(v.x, v.y);
    p[1] = pack2h(v.z, v.w);
}

// ---------------- qkv fp32 -> attention fp16 operands ----------------
__global__ void qkvsplit_k() {
    int t = blockIdx.x;
    int b = t >> 10;
    int s = t & 1023;
    const float4* row = (const float4*)(g_qkv + (size_t)t * QKVN);
    #pragma unroll
    for (int k = 0; k < 3; k++) {
        int i = threadIdx.x + k * 128;
        float4 v = row[i];
        int c = i * 4;
        if (c < 1024) {
            int h = c >> 6, d = c & 63;
            size_t q = (((size_t)b * 16 + h) * 1024 + s) * 64 + d;
            uint32_t* p = (uint32_t*)(g_qh + q);
            p[0] = pack2h(v.x * 0.125f, v.y * 0.125f);
            p[1] = pack2h(v.z * 0.125f, v.w * 0.125f);
        } else if (c < 1280) {
            int cc = c - 1024;
            int g = cc >> 6, d = cc & 63;
            size_t base = (((size_t)b * 4 + g) * 64 + d) * 1024 + s;
            g_kth[base]          = __float2half(v.x);
            g_kth[base + 1024]   = __float2half(v.y);
            g_kth[base + 2048]   = __float2half(v.z);
            g_kth[base + 3072]   = __float2half(v.w);
        } else {
            int cc = c - 1280;
            int g = cc >> 6, d = cc & 63;
            size_t base = (((size_t)b * 4 + g) * 1024 + s) * 64 + d;
            uint32_t* p = (uint32_t*)(g_vh + base);
            p[0] = pack2h(v.x, v.y);
            p[1] = pack2h(v.z, v.w);
        }
    }
}

// ---------------- tensor-core GEMM (fp16), 128x128x64 tiles, 2-stage --------
// op 0: QKV   A=g_xnh  B=g_wqkvh C=g_qkv          dense   N=QKVN K=NHID
// op 1: Oproj A=g_atth B=g_woh   C=g_h  Cadd=ext  dense   N=NHID K=NHID
// op 2: GU    A=gather xnh, B=g_wguh C=g_GU       mode1   N=GUN  K=NHID
// op 3: Down  A=g_Gh   B=g_wdh   C=ext atomic     mode2   N=NHID K=NF
// smem: A 2 stages x 128x144 = 36864 ; B 2 x 64x272 = 34816 -> 71680
#define TG_SMEM 71680

__device__ __forceinline__ void tg_load64(
        uint32_t sA, uint32_t sB, int stg, int k0,
        int ar, int ac4, int br, int bc4,
        const __half* apr, int asz,
        const __half* Bp, int N, int bx) {
    uint32_t abase = sA + stg * 18432 + ar * 144;
    #pragma unroll
    for (int i = 0; i < 4; i++) {
        int c8 = ac4 + i;
        cpa16(abase + c8 * 16, apr + k0 + c8 * 8, asz);
    }
    const __half* brow = Bp + (size_t)(k0 + br) * N + bx;
    uint32_t bbase = sB + stg * 17408 + br * 272;
    #pragma unroll
    for (int i = 0; i < 4; i++) {
        int c8 = bc4 + i;
        cpa16(bbase + c8 * 16, brow + c8 * 8, 16);
    }
    asm volatile("cp.async.commit_group;\n");
}

__global__ __launch_bounds__(256, 2) void tgemm_k(int op, const float* __restrict__ cadd_ext,
                                                  float* __restrict__ cout_ext) {
    extern __shared__ char smraw[];
    uint32_t sA = (uint32_t)__cvta_generic_to_shared(smraw);
    uint32_t sB = sA + 36864;

    const __half* Ah;
    const __half* Bh;
    float* C;
    const float* Cadd = 0;
    int N, K, mode;
    if (op == 0) {
        Ah = g_xnh;  Bh = g_wqkvh;
        C = g_qkv;  N = QKVN; K = NHID; mode = 0;
    } else if (op == 1) {
        Ah = g_atth; Bh = g_woh;
        C = g_h;    Cadd = cadd_ext; N = NHID; K = NHID; mode = 0;
    } else if (op == 2) {
        Ah = g_xnh;  Bh = g_wguh;
        C = g_GU;   N = GUN;  K = NHID; mode = 1;
    } else {
        Ah = g_Gh;   Bh = g_wdh;
        C = cout_ext; N = NHID; K = NF; mode = 2;
    }

    int tid = threadIdx.x;
    int bx = blockIdx.x * 128;
    int by = blockIdx.y * 128;
    int e = blockIdx.z;
    int m = NTOK;
    if (mode != 0) {
        m = g_cnt[e];
        if (by >= m) return;
        Bh += (size_t)e * K * N;
    }

    // A loader: one row per thread-pair; row = tid>>1, chunks (tid&1)*4..+3
    int ar = tid >> 1;
    int ac4 = (tid & 1) * 4;
    const __half* apr;
    int asz;
    {
        int lr = by + ar;
        size_t g0;
        bool v0 = true;
        if (mode == 0) {
            g0 = (size_t)lr;
        } else if (mode == 1) {
            v0 = lr < m;
            g0 = v0 ? (size_t)g_tok[e * NTOK + lr] : 0;
        } else {
            v0 = lr < m;
            g0 = (size_t)e * NTOK + (v0 ? (size_t)lr : 0);
        }
        apr = Ah + g0 * K;
        asz = v0 ? 16 : 0;
    }
    int br = tid >> 2;
    int bc4 = (tid & 3) * 4;

    int wid = tid >> 5;
    int lane = tid & 31;
    int wm = (wid >> 2) * 64;
    int wn = (wid & 3) * 32;

    float acc[4][4][4];
    #pragma unroll
    for (int i = 0; i < 4; i++) {
        #pragma unroll
        for (int j = 0; j < 4; j++) {
            #pragma unroll
            for (int r = 0; r < 4; r++) acc[i][j][r] = 0.f;
        }
    }

    int NC = K / 64;
    tg_load64(sA, sB, 0, 0, ar, ac4, br, bc4, apr, asz, Bh, N, bx);

    for (int c = 0; c < NC; c++) {
        int buf = c & 1;
        if (c + 1 < NC) {
            tg_load64(sA, sB, buf ^ 1, (c + 1) * 64, ar, ac4, br, bc4, apr, asz, Bh, N, bx);
            asm volatile("cp.async.wait_group 1;\n");
        } else {
            asm volatile("cp.async.wait_group 0;\n");
        }
        __syncthreads();

        uint32_t abase = sA + buf * 18432;
        uint32_t bbase = sB + buf * 17408;

        #pragma unroll
        for (int kk = 0; kk < 64; kk += 16) {
            uint32_t ah[4][4], bh2[2][4];
            int arow = wm + (lane & 15);
            int acolb = (kk + (lane >> 4) * 8) * 2;
            #pragma unroll
            for (int i = 0; i < 4; i++) {
                ldsm4(ah[i], abase + (arow + i*16)*144 + acolb);
            }
            int brow = kk + (lane & 15);
            #pragma unroll
            for (int j = 0; j < 2; j++) {
                ldsm4t(bh2[j], bbase + brow*272 + (wn + j*16 + (lane >> 4)*8)*2);
            }
            #pragma unroll
            for (int i = 0; i < 4; i++) {
                #pragma unroll
                for (int n8 = 0; n8 < 4; n8++) {
                    mma16816(acc[i][n8], ah[i], bh2[n8>>1][(n8&1)*2], bh2[n8>>1][(n8&1)*2+1]);
                }
            }
        }
        __syncthreads();
    }

    int ln4 = lane >> 2;
    int lc = (lane & 3) * 2;
    #pragma unroll
    for (int i = 0; i < 4; i++) {
        int r0 = wm + i * 16 + ln4;
        #pragma unroll
        for (int n8 = 0; n8 < 4; n8++) {
            int gc = bx + wn + n8 * 8 + lc;
            float* a = acc[i][n8];
            if (mode == 0) {
                size_t o0 = (size_t)(by + r0) * N + gc;
                size_t o1 = o0 + (size_t)8 * N;
                if (Cadd) {
                    C[o0]   = a[0] + Cadd[o0];
                    C[o0+1] = a[1] + Cadd[o0+1];
                    C[o1]   = a[2] + Cadd[o1];
                    C[o1+1] = a[3] + Cadd[o1+1];
                } else {
                    float2 w0; w0.x = a[0]; w0.y = a[1];
                    float2 w1; w1.x = a[2]; w1.y = a[3];
                    *(float2*)(C + o0) = w0;
                    *(float2*)(C + o1) = w1;
                }
            } else if (mode == 1) {
                int s0 = by + r0;
                int s1 = s0 + 8;
                if (s0 < m) {
                    float2 w0; w0.x = a[0]; w0.y = a[1];
                    *(float2*)(C + ((size_t)e*NTOK + s0)*N + gc) = w0;
                }
                if (s1 < m) {
                    float2 w1; w1.x = a[2]; w1.y = a[3];
                    *(float2*)(C + ((size_t)e*NTOK + s1)*N + gc) = w1;
                }
            } else {
                int s0 = by + r0;
                int s1 = s0 + 8;
                if (s0 < m) {
                    int tk = g_tok[e*NTOK + s0];
                    float w = g_wgt[e*NTOK + s0];
                    atomicAdd(&C[(size_t)tk*N + gc],   w * a[0]);
                    atomicAdd(&C[(size_t)tk*N + gc+1], w * a[1]);
                }
                if (s1 < m) {
                    int tk = g_tok[e*NTOK + s1];
                    float w = g_wgt[e*NTOK + s1];
                    atomicAdd(&C[(size_t)tk*N + gc],   w * a[2]);
                    atomicAdd(&C[(size_t)tk*N + gc+1], w * a[3]);
                }
            }
        }
    }
}

// ---------------- mma flash attention (fp16 single) ----------------
// block = 128 thr (4 warps), (b, h, 64 q rows). smem: Q 64x144 = 9216;
// 2 stages x (K 9216 + V 9216) = 36864 ; total 46080
#define FPITCH 144
#define FL_SMEM 46080

__device__ __forceinline__ void fl_load_kv(uint32_t base, int b, int g, int kv0, int tid) {
    #pragma unroll
    for (int j = 0; j < 4; j++) {
        int cc = tid + j * 128;
        int row = cc >> 3;
        int c8 = cc & 7;
        size_t koff = (((size_t)b * 4 + g) * 64 + row) * 1024 + kv0 + c8 * 8;
        cpa16(base + row * FPITCH + c8 * 16, g_kth + koff, 16);
    }
    #pragma unroll
    for (int j = 0; j < 4; j++) {
        int cc = tid + j * 128;
        int row = cc >> 3;
        int c8 = cc & 7;
        size_t voff = (((size_t)b * 4 + g) * 1024 + kv0 + row) * 64 + c8 * 8;
        cpa16(base + 9216 + row * FPITCH + c8 * 16, g_vh + voff, 16);
    }
    asm volatile("cp.async.commit_group;\n");
}

__global__ __launch_bounds__(128) void flashmma_k() {
    extern __shared__ char fsm[];
    uint32_t sb = (uint32_t)__cvta_generic_to_shared(fsm);
    int qt = blockIdx.x;
    int h = blockIdx.y;
    int b = blockIdx.z;
    int g = h >> 2;
    int tid = threadIdx.x;
    int wid = tid >> 5;
    int lane = tid & 31;

    // load Q tile
    #pragma unroll
    for (int j = 0; j < 4; j++) {
        int cc = tid + j * 128;
        int row = cc >> 3;
        int c8 = cc & 7;
        size_t qoff = (((size_t)b * 16 + h) * 1024 + qt * 64 + row) * 64 + c8 * 8;
        cpa16(sb + row * FPITCH + c8 * 16, g_qh + qoff, 16);
    }
    asm volatile("cp.async.commit_group;\n");
    fl_load_kv(sb + 9216, b, g, 0, tid);
    asm volatile("cp.async.wait_group 1;\n");
    __syncthreads();

    uint32_t ah[4][4];
    {
        int arow = wid * 16 + (lane & 15);
        #pragma unroll
        for (int j2 = 0; j2 < 4; j2++) {
            ldsm4(ah[j2], sb + arow * FPITCH + (uint32_t)(j2 * 16 + (lane >> 4) * 8) * 2);
        }
    }

    float m0 = -INFINITY, m1 = -INFINITY, l0 = 0.f, l1 = 0.f;
    float oacc[8][4];
    #pragma unroll
    for (int i = 0; i < 8; i++) {
        #pragma unroll
        for (int r = 0; r < 4; r++) oacc[i][r] = 0.f;
    }

    int r0g = qt * 64 + wid * 16 + (lane >> 2);

    for (int kt = 0; kt <= qt; kt++) {
        int st = kt & 1;
        if (kt < qt) {
            fl_load_kv(sb + 9216 + (st ^ 1) * 18432, b, g, (kt + 1) * 64, tid);
            asm volatile("cp.async.wait_group 1;\n");
        } else {
            asm volatile("cp.async.wait_group 0;\n");
        }
        __syncthreads();

        uint32_t kb = sb + 9216 + st * 18432;

        float sacc[8][4];
        #pragma unroll
        for (int i = 0; i < 8; i++) {
            #pragma unroll
            for (int r = 0; r < 4; r++) sacc[i][r] = 0.f;
        }
        #pragma unroll
        for (int j2 = 0; j2 < 4; j2++) {
            uint32_t bh2[4][4];
            int brow = j2 * 16 + (lane & 15);
            #pragma unroll
            for (int ng = 0; ng < 4; ng++) {
                ldsm4t(bh2[ng], kb + brow * FPITCH + (uint32_t)(ng * 16 + (lane >> 4) * 8) * 2);
            }
            #pragma unroll
            for (int n8 = 0; n8 < 8; n8++) {
                mma16816(sacc[n8], ah[j2], bh2[n8>>1][(n8&1)*2], bh2[n8>>1][(n8&1)*2+1]);
            }
        }

        if (kt == qt) {
            #pragma unroll
            for (int n8 = 0; n8 < 8; n8++) {
                int col = kt * 64 + n8 * 8 + (lane & 3) * 2;
                if (col > r0g)         sacc[n8][0] = -1e9f;
                if (col + 1 > r0g)     sacc[n8][1] = -1e9f;
                if (col > r0g + 8)     sacc[n8][2] = -1e9f;
                if (col + 1 > r0g + 8) sacc[n8][3] = -1e9f;
            }
        }

        float mx0 = -INFINITY, mx1 = -INFINITY;
        #pragma unroll
        for (int n8 = 0; n8 < 8; n8++) {
            mx0 = fmaxf(mx0, fmaxf(sacc[n8][0], sacc[n8][1]));
            mx1 = fmaxf(mx1, fmaxf(sacc[n8][2], sacc[n8][3]));
        }
        mx0 = fmaxf(mx0, __shfl_xor_sync(0xffffffffu, mx0, 1));
        mx0 = fmaxf(mx0, __shfl_xor_sync(0xffffffffu, mx0, 2));
        mx1 = fmaxf(mx1, __shfl_xor_sync(0xffffffffu, mx1, 1));
        mx1 = fmaxf(mx1, __shfl_xor_sync(0xffffffffu, mx1, 2));
        float nm0 = fmaxf(m0, mx0);
        float nm1 = fmaxf(m1, mx1);
        float f0 = __expf(m0 - nm0);
        float f1 = __expf(m1 - nm1);
        l0 *= f0;
        l1 *= f1;
        #pragma unroll
        for (int n8 = 0; n8 < 8; n8++) {
            oacc[n8][0] *= f0;
            oacc[n8][1] *= f0;
            oacc[n8][2] *= f1;
            oacc[n8][3] *= f1;
        }
        m0 = nm0;
        m1 = nm1;
        #pragma unroll
        for (int n8 = 0; n8 < 8; n8++) {
            float p0 = __expf(sacc[n8][0] - nm0);
            float p1 = __expf(sacc[n8][1] - nm0);
            float p2 = __expf(sacc[n8][2] - nm1);
            float p3 = __expf(sacc[n8][3] - nm1);
            l0 += p0 + p1;
            l1 += p2 + p3;
            sacc[n8][0] = p0;
            sacc[n8][1] = p1;
            sacc[n8][2] = p2;
            sacc[n8][3] = p3;
        }

        uint32_t vb = kb + 9216;
        #pragma unroll
        for (int j2 = 0; j2 < 4; j2++) {
            uint32_t pa[4];
            pa[0] = pack2h(sacc[2*j2][0],   sacc[2*j2][1]);
            pa[1] = pack2h(sacc[2*j2][2],   sacc[2*j2][3]);
            pa[2] = pack2h(sacc[2*j2+1][0], sacc[2*j2+1][1]);
            pa[3] = pack2h(sacc[2*j2+1][2], sacc[2*j2+1][3]);
            uint32_t vh2[4][4];
            int vrow = j2 * 16 + (lane & 15);
            #pragma unroll
            for (int ng = 0; ng < 4; ng++) {
                ldsm4t(vh2[ng], vb + vrow * FPITCH + (uint32_t)(ng * 16 + (lane >> 4) * 8) * 2);
            }
            #pragma unroll
            for (int n8 = 0; n8 < 8; n8++) {
                mma16816(oacc[n8], pa, vh2[n8>>1][(n8&1)*2], vh2[n8>>1][(n8&1)*2+1]);
            }
        }
        __syncthreads();
    }

    l0 += __shfl_xor_sync(0xffffffffu, l0, 1);
    l0 += __shfl_xor_sync(0xffffffffu, l0, 2);
    l1 += __shfl_xor_sync(0xffffffffu, l1, 1);
    l1 += __shfl_xor_sync(0xffffffffu, l1, 2);
    float i0 = 1.0f / l0;
    float i1 = 1.0f / l1;
    size_t t0 = (size_t)b * 1024 + r0g;
    size_t t1 = t0 + 8;
    #pragma unroll
    for (int n8 = 0; n8 < 8; n8++) {
        int col = h * 64 + n8 * 8 + (lane & 3) * 2;
        *(uint32_t*)(g_atth + t0 * NHID + col) = pack2h(oacc[n8][0] * i0, oacc[n8][1] * i0);
        *(uint32_t*)(g_atth + t1 * NHID + col) = pack2h(oacc[n8][2] * i1, oacc[n8][3] * i1);
    }
}

// ---------------- router (reads g_xn) ----------------
__global__ void router_k(const float* __restrict__ Wgate) {
    int t = blockIdx.x;
    float acc[NE];
    #pragma unroll
    for (int e = 0; e < NE; e++) acc[e] = 0.f;
    for (int h = threadIdx.x; h < NHID; h += 128) {
        float xv = g_xn[(size_t)t * NHID + h];
        const float4* wr = (const float4*)(Wgate + (size_t)h * NE);
        float4 w0 = wr[0];
        float4 w1 = wr[1];
        acc[0] += xv*w0.x; acc[1] += xv*w0.y; acc[2] += xv*w0.z; acc[3] += xv*w0.w;
        acc[4] += xv*w1.x; acc[5] += xv*w1.y; acc[6] += xv*w1.z; acc[7] += xv*w1.w;
    }
    #pragma unroll
    for (int e = 0; e < NE; e++) {
        #pragma unroll
        for (int o = 16; o; o >>= 1) acc[e] += __shfl_down_sync(0xffffffffu, acc[e], o);
    }
    __shared__ float sm[4][NE];
    int warp = threadIdx.x >> 5;
    int lane = threadIdx.x & 31;
    if (lane == 0) {
        for (int e = 0; e < NE; e++) sm[warp][e] = acc[e];
    }
    __syncthreads();
    if (threadIdx.x == 0) {
        float lg[NE];
        float mx = -INFINITY;
        for (int e = 0; e < NE; e++) {
            lg[e] = sm[0][e] + sm[1][e] + sm[2][e] + sm[3][e];
            mx = fmaxf(mx, lg[e]);
        }
        float p[NE];
        float sum = 0.f;
        for (int e = 0; e < NE; e++) { p[e] = expf(lg[e] - mx); sum += p[e]; }
        float inv = 1.0f / sum;
        for (int e = 0; e < NE; e++) p[e] *= inv;
        int i1 = 0;
        float b1 = p[0];
        for (int e = 1; e < NE; e++) {
            if (p[e] > b1) { b1 = p[e]; i1 = e; }
        }
        int i2 = -1;
        float b2 = -INFINITY;
        for (int e = 0; e < NE; e++) {
            if (e != i1 && p[e] > b2) { b2 = p[e]; i2 = e; }
        }
        int s1 = atomicAdd(&g_cnt[i1], 1);
        g_tok[i1 * NTOK + s1] = t;
        g_wgt[i1 * NTOK + s1] = b1;
        int s2 = atomicAdd(&g_cnt[i2], 1);
        g_tok[i2 * NTOK + s2] = t;
        g_wgt[i2 * NTOK + s2] = b2;
    }
}

__global__ void zero_cnt_k() {
    if (threadIdx.x < NE) g_cnt[threadIdx.x] = 0;
}

// silu(gate)*up from packed g_GU[slot][4096] -> fp16 g_Gh [slot][2048]
__global__ void silu_k() {
    int slot = blockIdx.x;
    int e = blockIdx.y;
    if (slot >= g_cnt[e]) return;
    size_t b  = ((size_t)e * NTOK + slot) * GUN;
    size_t ob = ((size_t)e * NTOK + slot) * NF;
    for (int f = threadIdx.x * 4; f < NF; f += 1024) {
        float4 g4 = *(const float4*)(g_GU + b + f);
        float4 u4 = *(const float4*)(g_GU + b + NF + f);
        float a0 = g4.x / (1.f + __expf(-g4.x)) * u4.x;
        float a1 = g4.y / (1.f + __expf(-g4.y)) * u4.y;
        float a2 = g4.z / (1.f + __expf(-g4.z)) * u4.z;
        float a3 = g4.w / (1.f + __expf(-g4.w)) * u4.w;
        uint32_t* p = (uint32_t*)(g_Gh + ob + f);
        p[0] = pack2h(a0, a1);
        p[1] = pack2h(a2, a3);
    }
}

// out = g_h (residual base for down-proj scatter)
__global__ void copy_k(float* __restrict__ dst) {
    size_t i = (size_t)blockIdx.x * 256 + threadIdx.x;
    ((float4*)dst)[i] = ((const float4*)g_h)[i];
}

// ---------------- launch ----------------
extern "C" void kernel_launch(void* const* d_in, const int* in_sizes, int n_in,
                              void* d_out, int out_size) {
    (void)in_sizes; (void)n_in; (void)out_size;
    const float* x     = (const float*)d_in[0];
    const float* w_ln1 = (const float*)d_in[2];
    const float* w_ln2 = (const float*)d_in[3];
    const float* Wq    = (const float*)d_in[4];
    const float* Wk    = (const float*)d_in[5];
    const float* Wv    = (const float*)d_in[6];
    const float* Wo    = (const float*)d_in[7];
    const float* Wgate = (const float*)d_in[8];
    const float* Wg    = (const float*)d_in[9];
    const float* Wu    = (const float*)d_in[10];
    const float* Wd    = (const float*)d_in[11];
    float* out = (float*)d_out;

    cudaFuncSetAttribute(tgemm_k, cudaFuncAttributeMaxDynamicSharedMemorySize, TG_SMEM);
    cudaFuncSetAttribute(flashmma_k, cudaFuncAttributeMaxDynamicSharedMemorySize, FL_SMEM);

    // 0) ln1 (fused fp16 convert)
    rmsnorm_half_k<<<NTOK, 256>>>(x, w_ln1, 0, 0);
    // 1) fused QKV weight pack
    split_pack_qkv_k<<<NHID*QKVN/4/256, 256>>>((const float4*)Wq, (const float4*)Wk, (const float4*)Wv);
    // 2) fused QKV projection
    tgemm_k<<<dim3(QKVN/128, NTOK/128), 256, TG_SMEM>>>(0, 0, 0);
    // 3) qkv -> attention operands
    qkvsplit_k<<<NTOK, 128>>>();
    // 4) mma flash attention
    flashmma_k<<<dim3(NS/64, NHEADS, NB), 128, FL_SMEM>>>();
    // 5) Wo convert
    split_k<<<NHID*NHID/4/256, 256>>>((const float4*)Wo, NHID*NHID/4, 1);
    // 6) output proj + residual
    tgemm_k<<<dim3(NHID/128, NTOK/128), 256, TG_SMEM>>>(1, x, 0);
    // 7) ln2 (fused convert + fp32 for router)
    rmsnorm_half_k<<<NTOK, 256>>>(0, w_ln2, 1, 1);
    // 8) routing
    zero_cnt_k<<<1, 32>>>();
    router_k<<<NTOK, 128>>>(Wgate);
    // 9) MoE weight packs
    split_pack_k<<<NE*NHID*NF/4/256, 256>>>((const float4*)Wg, NE*NHID*NF/4, NF, GUN, 0);
    split_pack_k<<<NE*NHID*NF/4/256, 256>>>((const float4*)Wu, NE*NHID*NF/4, NF, GUN, NF);
    // 10) fused gate|up grouped GEMM
    tgemm_k<<<dim3(GUN/128, NTOK/128, NE), 256, TG_SMEM>>>(2, 0, 0);
    // 11) silu * up -> fp16
    silu_k<<<dim3(NTOK, NE), 256>>>();
    // 12) Wd convert
    split_k<<<NE*NF*NHID/4/256, 256>>>((const float4*)Wd, NE*NF*NHID/4, 3);
    // 13) residual copy + down-proj scatter
    copy_k<<<NTOK, 256>>>(out);
    tgemm_k<<<dim3(NHID/128, NTOK/128, NE), 256, TG_SMEM>>>(3, 0, out);
}

// round 12
// speedup vs baseline: 2.1475x; 1.0362x over previous
#include <cuda_runtime.h>
#include <cuda_fp16.h>
#include <math.h>
#include <stdint.h>

#define NB    4
#define NS    1024
#define NHID  1024
#define NHEADS 16
#define NKVH  4
#define DH    64
#define NE    8
#define NF    2048
#define NTOK  4096
#define QKVN  1536
#define GUN   4096

// ---------------- scratch (device globals, allocation-free) ----------------
__device__ float g_xn[NTOK * NHID];
__device__ __half g_xnh[NTOK * NHID];
__device__ float g_qkv[NTOK * QKVN];
__device__ __half g_atth[NTOK * NHID];
__device__ float g_h[NTOK * NHID];
__device__ __half g_wqkvh[NHID * QKVN];
__device__ __half g_woh[NHID * NHID];
__device__ __half g_wguh[NE * NHID * GUN];   // interleaved: col 2j=gate, 2j+1=up
__device__ __half g_wdh[NE * NF * NHID];
__device__ __half g_Gh[NE * NTOK * NF];
__device__ int   g_cnt[NE];
__device__ int   g_tok[NE * NTOK];
__device__ float g_wgt[NE * NTOK];
// attention operands: Q [b][h][s][d] (scaled), Kt [b][g][d][s], V [b][g][s][d]
__device__ __half g_qh[NB * NHEADS * NS * DH];
__device__ __half g_kth[NB * NKVH * DH * NS];
__device__ __half g_vh[NB * NKVH * NS * DH];

// ---------------- helpers ----------------
__device__ __forceinline__ uint32_t pack2h(float a, float b) {
    __half2 h = __floats2half2_rn(a, b);
    return *(uint32_t*)&h;
}
__device__ __forceinline__ void ldsm4(uint32_t* r, uint32_t a) {
    asm volatile("ldmatrix.sync.aligned.m8n8.x4.shared.b16 {%0,%1,%2,%3}, [%4];\n"
        : "=r"(r[0]), "=r"(r[1]), "=r"(r[2]), "=r"(r[3]) : "r"(a));
}
__device__ __forceinline__ void ldsm4t(uint32_t* r, uint32_t a) {
    asm volatile("ldmatrix.sync.aligned.m8n8.x4.trans.shared.b16 {%0,%1,%2,%3}, [%4];\n"
        : "=r"(r[0]), "=r"(r[1]), "=r"(r[2]), "=r"(r[3]) : "r"(a));
}
__device__ __forceinline__ void mma16816(float* d, const uint32_t* a, uint32_t b0, uint32_t b1) {
    asm volatile("mma.sync.aligned.m16n8k16.row.col.f32.f16.f16.f32 "
        "{%0,%1,%2,%3},{%4,%5,%6,%7},{%8,%9},{%0,%1,%2,%3};\n"
        : "+f"(d[0]), "+f"(d[1]), "+f"(d[2]), "+f"(d[3])
        : "r"(a[0]), "r"(a[1]), "r"(a[2]), "r"(a[3]), "r"(b0), "r"(b1));
}
__device__ __forceinline__ void cpa16(uint32_t dst, const void* src, int sz) {
    asm volatile("cp.async.cg.shared.global [%0], [%1], 16, %2;\n"
        :: "r"(dst), "l"(src), "r"(sz));
}

// ---------------- fused RMSNorm + fp16 convert ----------------
__global__ void rmsnorm_half_k(const float* __restrict__ xext, const float* __restrict__ w,
                               int use_h, int write_xn) {
    int t = blockIdx.x;
    const float* src = use_h ? (const float*)g_h : xext;
    const float4* xr = (const float4*)(src + (size_t)t * NHID);
    float4 v = xr[threadIdx.x];
    float ss = v.x*v.x + v.y*v.y + v.z*v.z + v.w*v.w;
    #pragma unroll
    for (int o = 16; o; o >>= 1) ss += __shfl_down_sync(0xffffffffu, ss, o);
    __shared__ float red[8];
    if ((threadIdx.x & 31) == 0) red[threadIdx.x >> 5] = ss;
    __syncthreads();
    if (threadIdx.x < 8) {
        float s = red[threadIdx.x];
        #pragma unroll
        for (int o = 4; o; o >>= 1) s += __shfl_down_sync(0xffu, s, o);
        if (threadIdx.x == 0) red[0] = s;
    }
    __syncthreads();
    float rs = rsqrtf(red[0] * (1.0f / NHID) + 1e-6f);
    float4 wv = ((const float4*)w)[threadIdx.x];
    float4 ov;
    ov.x = v.x * rs * wv.x;
    ov.y = v.y * rs * wv.y;
    ov.z = v.z * rs * wv.z;
    ov.w = v.w * rs * wv.w;
    if (write_xn) {
        ((float4*)(g_xn + (size_t)t * NHID))[threadIdx.x] = ov;
    }
    uint32_t* p = (uint32_t*)(g_xnh + (size_t)t * NHID) + threadIdx.x * 2;
    p[0] = pack2h(ov.x, ov.y);
    p[1] = pack2h(ov.z, ov.w);
}

// ---------------- combined QKV weight pack (fp32 -> fp16, packed cols) -----
__global__ void split_pack_qkv_k(const float4* __restrict__ Wq, const float4* __restrict__ Wk,
                                 const float4* __restrict__ Wv) {
    int i = blockIdx.x * 256 + threadIdx.x;
    int el = i * 4;
    int r = el / QKVN;
    int c = el % QKVN;
    float4 v;
    if (c < 1024)      v = Wq[(r * 1024 + c) / 4];
    else if (c < 1280) v = Wk[(r * 256 + (c - 1024)) / 4];
    else               v = Wv[(r * 256 + (c - 1280)) / 4];
    uint32_t* p = (uint32_t*)(g_wqkvh + (size_t)r * QKVN + c);
    p[0] = pack2h(v.x, v.y);
    p[1] = pack2h(v.z, v.w);
}

// ---------------- plain convert: fp32 -> fp16 (sel 1: Wo, else Wd) ----------
__global__ void split_k(const float4* __restrict__ ext, int n4, int sel) {
    int i = blockIdx.x * 256 + threadIdx.x;
    if (i >= n4) return;
    uint32_t* d = (sel == 1) ? (uint32_t*)g_woh : (uint32_t*)g_wdh;
    float4 v = ext[i];
    d[i*2]   = pack2h(v.x, v.y);
    d[i*2+1] = pack2h(v.z, v.w);
}

// ---------------- gate|up interleaved pack ----------------
// Wg/Wu [E][H][F] fp32 -> g_wguh [E*H][2F] fp16, col 2j = gate_j, 2j+1 = up_j
__global__ void split_pack_gu_k(const float4* __restrict__ Wg, const float4* __restrict__ Wu) {
    int i = blockIdx.x * 256 + threadIdx.x;   // group of 4 source cols
    float4 g4 = Wg[i];
    float4 u4 = Wu[i];
    int el = i * 4;
    size_t r = (size_t)(el / NF);
    int c = el % NF;
    uint4 o;
    o.x = pack2h(g4.x, u4.x);
    o.y = pack2h(g4.y, u4.y);
    o.z = pack2h(g4.z, u4.z);
    o.w = pack2h(g4.w, u4.w);
    *(uint4*)(g_wguh + r * GUN + 2 * c) = o;
}

// ---------------- qkv fp32 -> attention fp16 operands ----------------
__global__ void qkvsplit_k() {
    int t = blockIdx.x;
    int b = t >> 10;
    int s = t & 1023;
    const float4* row = (const float4*)(g_qkv + (size_t)t * QKVN);
    #pragma unroll
    for (int k = 0; k < 3; k++) {
        int i = threadIdx.x + k * 128;
        float4 v = row[i];
        int c = i * 4;
        if (c < 1024) {
            int h = c >> 6, d = c & 63;
            size_t q = (((size_t)b * 16 + h) * 1024 + s) * 64 + d;
            uint32_t* p = (uint32_t*)(g_qh + q);
            p[0] = pack2h(v.x * 0.125f, v.y * 0.125f);
            p[1] = pack2h(v.z * 0.125f, v.w * 0.125f);
        } else if (c < 1280) {
            int cc = c - 1024;
            int g = cc >> 6, d = cc & 63;
            size_t base = (((size_t)b * 4 + g) * 64 + d) * 1024 + s;
            g_kth[base]          = __float2half(v.x);
            g_kth[base + 1024]   = __float2half(v.y);
            g_kth[base + 2048]   = __float2half(v.z);
            g_kth[base + 3072]   = __float2half(v.w);
        } else {
            int cc = c - 1280;
            int g = cc >> 6, d = cc & 63;
            size_t base = (((size_t)b * 4 + g) * 1024 + s) * 64 + d;
            uint32_t* p = (uint32_t*)(g_vh + base);
            p[0] = pack2h(v.x, v.y);
            p[1] = pack2h(v.z, v.w);
        }
    }
}

// ---------------- tensor-core GEMM (fp16), 128x128x64 tiles, 2-stage --------
// op 0: QKV   A=g_xnh  B=g_wqkvh C=g_qkv          dense   N=QKVN K=NHID
// op 1: Oproj A=g_atth B=g_woh   C=g_h  Cadd=ext  dense   N=NHID K=NHID
// op 2: GU    A=gather xnh, B=g_wguh (interleaved) -> fused silu -> g_Gh fp16
// op 3: Down  A=g_Gh   B=g_wdh   C=ext atomic     mode2   N=NHID K=NF
#define TG_SMEM 71680

__device__ __forceinline__ void tg_load64(
        uint32_t sA, uint32_t sB, int stg, int k0,
        int ar, int ac4, int br, int bc4,
        const __half* apr, int asz,
        const __half* Bp, int N, int bx) {
    uint32_t abase = sA + stg * 18432 + ar * 144;
    #pragma unroll
    for (int i = 0; i < 4; i++) {
        int c8 = ac4 + i;
        cpa16(abase + c8 * 16, apr + k0 + c8 * 8, asz);
    }
    const __half* brow = Bp + (size_t)(k0 + br) * N + bx;
    uint32_t bbase = sB + stg * 17408 + br * 272;
    #pragma unroll
    for (int i = 0; i < 4; i++) {
        int c8 = bc4 + i;
        cpa16(bbase + c8 * 16, brow + c8 * 8, 16);
    }
    asm volatile("cp.async.commit_group;\n");
}

__global__ __launch_bounds__(256, 2) void tgemm_k(int op, const float* __restrict__ cadd_ext,
                                                  float* __restrict__ cout_ext) {
    extern __shared__ char smraw[];
    uint32_t sA = (uint32_t)__cvta_generic_to_shared(smraw);
    uint32_t sB = sA + 36864;

    const __half* Ah;
    const __half* Bh;
    float* C = 0;
    const float* Cadd = 0;
    int N, K, mode;
    if (op == 0) {
        Ah = g_xnh;  Bh = g_wqkvh;
        C = g_qkv;  N = QKVN; K = NHID; mode = 0;
    } else if (op == 1) {
        Ah = g_atth; Bh = g_woh;
        C = g_h;    Cadd = cadd_ext; N = NHID; K = NHID; mode = 0;
    } else if (op == 2) {
        Ah = g_xnh;  Bh = g_wguh;
        N = GUN;  K = NHID; mode = 1;
    } else {
        Ah = g_Gh;   Bh = g_wdh;
        C = cout_ext; N = NHID; K = NF; mode = 2;
    }

    int tid = threadIdx.x;
    int bx = blockIdx.x * 128;
    int by = blockIdx.y * 128;
    int e = blockIdx.z;
    int m = NTOK;
    if (mode != 0) {
        m = g_cnt[e];
        if (by >= m) return;
        Bh += (size_t)e * K * N;
    }

    int ar = tid >> 1;
    int ac4 = (tid & 1) * 4;
    const __half* apr;
    int asz;
    {
        int lr = by + ar;
        size_t g0;
        bool v0 = true;
        if (mode == 0) {
            g0 = (size_t)lr;
        } else if (mode == 1) {
            v0 = lr < m;
            g0 = v0 ? (size_t)g_tok[e * NTOK + lr] : 0;
        } else {
            v0 = lr < m;
            g0 = (size_t)e * NTOK + (v0 ? (size_t)lr : 0);
        }
        apr = Ah + g0 * K;
        asz = v0 ? 16 : 0;
    }
    int br = tid >> 2;
    int bc4 = (tid & 3) * 4;

    int wid = tid >> 5;
    int lane = tid & 31;
    int wm = (wid >> 2) * 64;
    int wn = (wid & 3) * 32;

    float acc[4][4][4];
    #pragma unroll
    for (int i = 0; i < 4; i++) {
        #pragma unroll
        for (int j = 0; j < 4; j++) {
            #pragma unroll
            for (int r = 0; r < 4; r++) acc[i][j][r] = 0.f;
        }
    }

    int NC = K / 64;
    tg_load64(sA, sB, 0, 0, ar, ac4, br, bc4, apr, asz, Bh, N, bx);

    for (int c = 0; c < NC; c++) {
        int buf = c & 1;
        if (c + 1 < NC) {
            tg_load64(sA, sB, buf ^ 1, (c + 1) * 64, ar, ac4, br, bc4, apr, asz, Bh, N, bx);
            asm volatile("cp.async.wait_group 1;\n");
        } else {
            asm volatile("cp.async.wait_group 0;\n");
        }
        __syncthreads();

        uint32_t abase = sA + buf * 18432;
        uint32_t bbase = sB + buf * 17408;

        #pragma unroll
        for (int kk = 0; kk < 64; kk += 16) {
            uint32_t ah[4][4], bh2[2][4];
            int arow = wm + (lane & 15);
            int acolb = (kk + (lane >> 4) * 8) * 2;
            #pragma unroll
            for (int i = 0; i < 4; i++) {
                ldsm4(ah[i], abase + (arow + i*16)*144 + acolb);
            }
            int brow = kk + (lane & 15);
            #pragma unroll
            for (int j = 0; j < 2; j++) {
                ldsm4t(bh2[j], bbase + brow*272 + (wn + j*16 + (lane >> 4)*8)*2);
            }
            #pragma unroll
            for (int i = 0; i < 4; i++) {
                #pragma unroll
                for (int n8 = 0; n8 < 4; n8++) {
                    mma16816(acc[i][n8], ah[i], bh2[n8>>1][(n8&1)*2], bh2[n8>>1][(n8&1)*2+1]);
                }
            }
        }
        __syncthreads();
    }

    int ln4 = lane >> 2;
    int lc = (lane & 3) * 2;
    #pragma unroll
    for (int i = 0; i < 4; i++) {
        int r0 = wm + i * 16 + ln4;
        #pragma unroll
        for (int n8 = 0; n8 < 4; n8++) {
            int gc = bx + wn + n8 * 8 + lc;
            float* a = acc[i][n8];
            if (mode == 0) {
                size_t o0 = (size_t)(by + r0) * N + gc;
                size_t o1 = o0 + (size_t)8 * N;
                if (Cadd) {
                    C[o0]   = a[0] + Cadd[o0];
                    C[o0+1] = a[1] + Cadd[o0+1];
                    C[o1]   = a[2] + Cadd[o1];
                    C[o1+1] = a[3] + Cadd[o1+1];
                } else {
                    float2 w0; w0.x = a[0]; w0.y = a[1];
                    float2 w1; w1.x = a[2]; w1.y = a[3];
                    *(float2*)(C + o0) = w0;
                    *(float2*)(C + o1) = w1;
                }
            } else if (mode == 1) {
                // fused silu(gate)*up: (a[0],a[1]) = (gate,up) for row s0, (a[2],a[3]) for s1
                int s0 = by + r0;
                int s1 = s0 + 8;
                int n = gc >> 1;
                if (s0 < m) {
                    float r = a[0] / (1.f + __expf(-a[0])) * a[1];
                    g_Gh[((size_t)e * NTOK + s0) * NF + n] = __float2half(r);
                }
                if (s1 < m) {
                    float r = a[2] / (1.f + __expf(-a[2])) * a[3];
                    g_Gh[((size_t)e * NTOK + s1) * NF + n] = __float2half(r);
                }
            } else {
                int s0 = by + r0;
                int s1 = s0 + 8;
                if (s0 < m) {
                    int tk = g_tok[e*NTOK + s0];
                    float w = g_wgt[e*NTOK + s0];
                    atomicAdd(&C[(size_t)tk*N + gc],   w * a[0]);
                    atomicAdd(&C[(size_t)tk*N + gc+1], w * a[1]);
                }
                if (s1 < m) {
                    int tk = g_tok[e*NTOK + s1];
                    float w = g_wgt[e*NTOK + s1];
                    atomicAdd(&C[(size_t)tk*N + gc],   w * a[2]);
                    atomicAdd(&C[(size_t)tk*N + gc+1], w * a[3]);
                }
            }
        }
    }
}

// ---------------- mma flash attention (fp16 single) ----------------
#define FPITCH 144
#define FL_SMEM 46080

__device__ __forceinline__ void fl_load_kv(uint32_t base, int b, int g, int kv0, int tid) {
    #pragma unroll
    for (int j = 0; j < 4; j++) {
        int cc = tid + j * 128;
        int row = cc >> 3;
        int c8 = cc & 7;
        size_t koff = (((size_t)b * 4 + g) * 64 + row) * 1024 + kv0 + c8 * 8;
        cpa16(base + row * FPITCH + c8 * 16, g_kth + koff, 16);
    }
    #pragma unroll
    for (int j = 0; j < 4; j++) {
        int cc = tid + j * 128;
        int row = cc >> 3;
        int c8 = cc & 7;
        size_t voff = (((size_t)b * 4 + g) * 1024 + kv0 + row) * 64 + c8 * 8;
        cpa16(base + 9216 + row * FPITCH + c8 * 16, g_vh + voff, 16);
    }
    asm volatile("cp.async.commit_group;\n");
}

__global__ __launch_bounds__(128) void flashmma_k() {
    extern __shared__ char fsm[];
    uint32_t sb = (uint32_t)__cvta_generic_to_shared(fsm);
    int qt = blockIdx.x;
    int h = blockIdx.y;
    int b = blockIdx.z;
    int g = h >> 2;
    int tid = threadIdx.x;
    int wid = tid >> 5;
    int lane = tid & 31;

    #pragma unroll
    for (int j = 0; j < 4; j++) {
        int cc = tid + j * 128;
        int row = cc >> 3;
        int c8 = cc & 7;
        size_t qoff = (((size_t)b * 16 + h) * 1024 + qt * 64 + row) * 64 + c8 * 8;
        cpa16(sb + row * FPITCH + c8 * 16, g_qh + qoff, 16);
    }
    asm volatile("cp.async.commit_group;\n");
    fl_load_kv(sb + 9216, b, g, 0, tid);
    asm volatile("cp.async.wait_group 1;\n");
    __syncthreads();

    uint32_t ah[4][4];
    {
        int arow = wid * 16 + (lane & 15);
        #pragma unroll
        for (int j2 = 0; j2 < 4; j2++) {
            ldsm4(ah[j2], sb + arow * FPITCH + (uint32_t)(j2 * 16 + (lane >> 4) * 8) * 2);
        }
    }

    float m0 = -INFINITY, m1 = -INFINITY, l0 = 0.f, l1 = 0.f;
    float oacc[8][4];
    #pragma unroll
    for (int i = 0; i < 8; i++) {
        #pragma unroll
        for (int r = 0; r < 4; r++) oacc[i][r] = 0.f;
    }

    int r0g = qt * 64 + wid * 16 + (lane >> 2);

    for (int kt = 0; kt <= qt; kt++) {
        int st = kt & 1;
        if (kt < qt) {
            fl_load_kv(sb + 9216 + (st ^ 1) * 18432, b, g, (kt + 1) * 64, tid);
            asm volatile("cp.async.wait_group 1;\n");
        } else {
            asm volatile("cp.async.wait_group 0;\n");
        }
        __syncthreads();

        uint32_t kb = sb + 9216 + st * 18432;

        float sacc[8][4];
        #pragma unroll
        for (int i = 0; i < 8; i++) {
            #pragma unroll
            for (int r = 0; r < 4; r++) sacc[i][r] = 0.f;
        }
        #pragma unroll
        for (int j2 = 0; j2 < 4; j2++) {
            uint32_t bh2[4][4];
            int brow = j2 * 16 + (lane & 15);
            #pragma unroll
            for (int ng = 0; ng < 4; ng++) {
                ldsm4t(bh2[ng], kb + brow * FPITCH + (uint32_t)(ng * 16 + (lane >> 4) * 8) * 2);
            }
            #pragma unroll
            for (int n8 = 0; n8 < 8; n8++) {
                mma16816(sacc[n8], ah[j2], bh2[n8>>1][(n8&1)*2], bh2[n8>>1][(n8&1)*2+1]);
            }
        }

        if (kt == qt) {
            #pragma unroll
            for (int n8 = 0; n8 < 8; n8++) {
                int col = kt * 64 + n8 * 8 + (lane & 3) * 2;
                if (col > r0g)         sacc[n8][0] = -1e9f;
                if (col + 1 > r0g)     sacc[n8][1] = -1e9f;
                if (col > r0g + 8)     sacc[n8][2] = -1e9f;
                if (col + 1 > r0g + 8) sacc[n8][3] = -1e9f;
            }
        }

        float mx0 = -INFINITY, mx1 = -INFINITY;
        #pragma unroll
        for (int n8 = 0; n8 < 8; n8++) {
            mx0 = fmaxf(mx0, fmaxf(sacc[n8][0], sacc[n8][1]));
            mx1 = fmaxf(mx1, fmaxf(sacc[n8][2], sacc[n8][3]));
        }
        mx0 = fmaxf(mx0, __shfl_xor_sync(0xffffffffu, mx0, 1));
        mx0 = fmaxf(mx0, __shfl_xor_sync(0xffffffffu, mx0, 2));
        mx1 = fmaxf(mx1, __shfl_xor_sync(0xffffffffu, mx1, 1));
        mx1 = fmaxf(mx1, __shfl_xor_sync(0xffffffffu, mx1, 2));
        float nm0 = fmaxf(m0, mx0);
        float nm1 = fmaxf(m1, mx1);
        float f0 = __expf(m0 - nm0);
        float f1 = __expf(m1 - nm1);
        l0 *= f0;
        l1 *= f1;
        #pragma unroll
        for (int n8 = 0; n8 < 8; n8++) {
            oacc[n8][0] *= f0;
            oacc[n8][1] *= f0;
            oacc[n8][2] *= f1;
            oacc[n8][3] *= f1;
        }
        m0 = nm0;
        m1 = nm1;
        #pragma unroll
        for (int n8 = 0; n8 < 8; n8++) {
            float p0 = __expf(sacc[n8][0] - nm0);
            float p1 = __expf(sacc[n8][1] - nm0);
            float p2 = __expf(sacc[n8][2] - nm1);
            float p3 = __expf(sacc[n8][3] - nm1);
            l0 += p0 + p1;
            l1 += p2 + p3;
            sacc[n8][0] = p0;
            sacc[n8][1] = p1;
            sacc[n8][2] = p2;
            sacc[n8][3] = p3;
        }

        uint32_t vb = kb + 9216;
        #pragma unroll
        for (int j2 = 0; j2 < 4; j2++) {
            uint32_t pa[4];
            pa[0] = pack2h(sacc[2*j2][0],   sacc[2*j2][1]);
            pa[1] = pack2h(sacc[2*j2][2],   sacc[2*j2][3]);
            pa[2] = pack2h(sacc[2*j2+1][0], sacc[2*j2+1][1]);
            pa[3] = pack2h(sacc[2*j2+1][2], sacc[2*j2+1][3]);
            uint32_t vh2[4][4];
            int vrow = j2 * 16 + (lane & 15);
            #pragma unroll
            for (int ng = 0; ng < 4; ng++) {
                ldsm4t(vh2[ng], vb + vrow * FPITCH + (uint32_t)(ng * 16 + (lane >> 4) * 8) * 2);
            }
            #pragma unroll
            for (int n8 = 0; n8 < 8; n8++) {
                mma16816(oacc[n8], pa, vh2[n8>>1][(n8&1)*2], vh2[n8>>1][(n8&1)*2+1]);
            }
        }
        __syncthreads();
    }

    l0 += __shfl_xor_sync(0xffffffffu, l0, 1);
    l0 += __shfl_xor_sync(0xffffffffu, l0, 2);
    l1 += __shfl_xor_sync(0xffffffffu, l1, 1);
    l1 += __shfl_xor_sync(0xffffffffu, l1, 2);
    float i0 = 1.0f / l0;
    float i1 = 1.0f / l1;
    size_t t0 = (size_t)b * 1024 + r0g;
    size_t t1 = t0 + 8;
    #pragma unroll
    for (int n8 = 0; n8 < 8; n8++) {
        int col = h * 64 + n8 * 8 + (lane & 3) * 2;
        *(uint32_t*)(g_atth + t0 * NHID + col) = pack2h(oacc[n8][0] * i0, oacc[n8][1] * i0);
        *(uint32_t*)(g_atth + t1 * NHID + col) = pack2h(oacc[n8][2] * i1, oacc[n8][3] * i1);
    }
}

// ---------------- router (reads g_xn) ----------------
__global__ void router_k(const float* __restrict__ Wgate) {
    int t = blockIdx.x;
    float acc[NE];
    #pragma unroll
    for (int e = 0; e < NE; e++) acc[e] = 0.f;
    for (int h = threadIdx.x; h < NHID; h += 128) {
        float xv = g_xn[(size_t)t * NHID + h];
        const float4* wr = (const float4*)(Wgate + (size_t)h * NE);
        float4 w0 = wr[0];
        float4 w1 = wr[1];
        acc[0] += xv*w0.x; acc[1] += xv*w0.y; acc[2] += xv*w0.z; acc[3] += xv*w0.w;
        acc[4] += xv*w1.x; acc[5] += xv*w1.y; acc[6] += xv*w1.z; acc[7] += xv*w1.w;
    }
    #pragma unroll
    for (int e = 0; e < NE; e++) {
        #pragma unroll
        for (int o = 16; o; o >>= 1) acc[e] += __shfl_down_sync(0xffffffffu, acc[e], o);
    }
    __shared__ float sm[4][NE];
    int warp = threadIdx.x >> 5;
    int lane = threadIdx.x & 31;
    if (lane == 0) {
        for (int e = 0; e < NE; e++) sm[warp][e] = acc[e];
    }
    __syncthreads();
    if (threadIdx.x == 0) {
        float lg[NE];
        float mx = -INFINITY;
        for (int e = 0; e < NE; e++) {
            lg[e] = sm[0][e] + sm[1][e] + sm[2][e] + sm[3][e];
            mx = fmaxf(mx, lg[e]);
        }
        float p[NE];
        float sum = 0.f;
        for (int e = 0; e < NE; e++) { p[e] = expf(lg[e] - mx); sum += p[e]; }
        float inv = 1.0f / sum;
        for (int e = 0; e < NE; e++) p[e] *= inv;
        int i1 = 0;
        float b1 = p[0];
        for (int e = 1; e < NE; e++) {
            if (p[e] > b1) { b1 = p[e]; i1 = e; }
        }
        int i2 = -1;
        float b2 = -INFINITY;
        for (int e = 0; e < NE; e++) {
            if (e != i1 && p[e] > b2) { b2 = p[e]; i2 = e; }
        }
        int s1 = atomicAdd(&g_cnt[i1], 1);
        g_tok[i1 * NTOK + s1] = t;
        g_wgt[i1 * NTOK + s1] = b1;
        int s2 = atomicAdd(&g_cnt[i2], 1);
        g_tok[i2 * NTOK + s2] = t;
        g_wgt[i2 * NTOK + s2] = b2;
    }
}

__global__ void zero_cnt_k() {
    if (threadIdx.x < NE) g_cnt[threadIdx.x] = 0;
}

// out = g_h (residual base for down-proj scatter)
__global__ void copy_k(float* __restrict__ dst) {
    size_t i = (size_t)blockIdx.x * 256 + threadIdx.x;
    ((float4*)dst)[i] = ((const float4*)g_h)[i];
}

// ---------------- launch ----------------
extern "C" void kernel_launch(void* const* d_in, const int* in_sizes, int n_in,
                              void* d_out, int out_size) {
    (void)in_sizes; (void)n_in; (void)out_size;
    const float* x     = (const float*)d_in[0];
    const float* w_ln1 = (const float*)d_in[2];
    const float* w_ln2 = (const float*)d_in[3];
    const float* Wq    = (const float*)d_in[4];
    const float* Wk    = (const float*)d_in[5];
    const float* Wv    = (const float*)d_in[6];
    const float* Wo    = (const float*)d_in[7];
    const float* Wgate = (const float*)d_in[8];
    const float* Wg    = (const float*)d_in[9];
    const float* Wu    = (const float*)d_in[10];
    const float* Wd    = (const float*)d_in[11];
    float* out = (float*)d_out;

    cudaFuncSetAttribute(tgemm_k, cudaFuncAttributeMaxDynamicSharedMemorySize, TG_SMEM);
    cudaFuncSetAttribute(flashmma_k, cudaFuncAttributeMaxDynamicSharedMemorySize, FL_SMEM);

    // 0) fused QKV weight pack
    split_pack_qkv_k<<<NHID*QKVN/4/256, 256>>>((const float4*)Wq, (const float4*)Wk, (const float4*)Wv);
    // 1) Wo convert
    split_k<<<NHID*NHID/4/256, 256>>>((const float4*)Wo, NHID*NHID/4, 1);
    // 2) ln1 (fused fp16 convert)
    rmsnorm_half_k<<<NTOK, 256>>>(x, w_ln1, 0, 0);
    // 3) fused QKV projection  <-- profiled slot
    tgemm_k<<<dim3(QKVN/128, NTOK/128), 256, TG_SMEM>>>(0, 0, 0);
    // 4) qkv -> attention operands
    qkvsplit_k<<<NTOK, 128>>>();
    // 5) mma flash attention
    flashmma_k<<<dim3(NS/64, NHEADS, NB), 128, FL_SMEM>>>();
    // 6) output proj + residual
    tgemm_k<<<dim3(NHID/128, NTOK/128), 256, TG_SMEM>>>(1, x, 0);
    // 7) ln2 (fused convert + fp32 for router)
    rmsnorm_half_k<<<NTOK, 256>>>(0, w_ln2, 1, 1);
    // 8) routing
    zero_cnt_k<<<1, 32>>>();
    router_k<<<NTOK, 128>>>(Wgate);
    // 9) gate|up interleaved weight pack
    split_pack_gu_k<<<NE*NHID*NF/4/256, 256>>>((const float4*)Wg, (const float4*)Wu);
    // 10) fused gate|up grouped GEMM + silu epilogue -> g_Gh fp16
    tgemm_k<<<dim3(GUN/128, NTOK/128, NE), 256, TG_SMEM>>>(2, 0, 0);
    // 11) Wd convert
    split_k<<<NE*NF*NHID/4/256, 256>>>((const float4*)Wd, NE*NF*NHID/4, 3);
    // 12) residual copy + down-proj scatter
    copy_k<<<NTOK, 256>>>(out);
    tgemm_k<<<dim3(NHID/128, NTOK/128, NE), 256, TG_SMEM>>>(3, 0, out);
}

// round 13
// speedup vs baseline: 2.1595x; 1.0056x over previous
#include <cuda_runtime.h>
#include <cuda_fp16.h>
#include <math.h>
#include <stdint.h>

#define NB    4
#define NS    1024
#define NHID  1024
#define NHEADS 16
#define NKVH  4
#define DH    64
#define NE    8
#define NF    2048
#define NTOK  4096
#define QKVN  1536
#define GUN   4096

// ---------------- scratch (device globals, allocation-free) ----------------
__device__ float g_xn[NTOK * NHID];
__device__ __half g_xnh[NTOK * NHID];
__device__ __half g_atth[NTOK * NHID];
__device__ float g_h[NTOK * NHID];
__device__ __half g_wqkvh[NHID * QKVN];
__device__ __half g_woh[NHID * NHID];
__device__ __half g_wguh[NE * NHID * GUN];   // interleaved: col 2j=gate, 2j+1=up
__device__ __half g_wdh[NE * NF * NHID];
__device__ __half g_Gh[NE * NTOK * NF];
__device__ int   g_cnt[NE];
__device__ int   g_tok[NE * NTOK];
__device__ float g_wgt[NE * NTOK];
// attention operands: Q [b][h][s][d] (scaled), Kt [b][g][d][s], V [b][g][s][d]
__device__ __half g_qh[NB * NHEADS * NS * DH];
__device__ __half g_kth[NB * NKVH * DH * NS];
__device__ __half g_vh[NB * NKVH * NS * DH];

// ---------------- helpers ----------------
__device__ __forceinline__ uint32_t pack2h(float a, float b) {
    __half2 h = __floats2half2_rn(a, b);
    return *(uint32_t*)&h;
}
__device__ __forceinline__ void ldsm4(uint32_t* r, uint32_t a) {
    asm volatile("ldmatrix.sync.aligned.m8n8.x4.shared.b16 {%0,%1,%2,%3}, [%4];\n"
        : "=r"(r[0]), "=r"(r[1]), "=r"(r[2]), "=r"(r[3]) : "r"(a));
}
__device__ __forceinline__ void ldsm4t(uint32_t* r, uint32_t a) {
    asm volatile("ldmatrix.sync.aligned.m8n8.x4.trans.shared.b16 {%0,%1,%2,%3}, [%4];\n"
        : "=r"(r[0]), "=r"(r[1]), "=r"(r[2]), "=r"(r[3]) : "r"(a));
}
__device__ __forceinline__ void mma16816(float* d, const uint32_t* a, uint32_t b0, uint32_t b1) {
    asm volatile("mma.sync.aligned.m16n8k16.row.col.f32.f16.f16.f32 "
        "{%0,%1,%2,%3},{%4,%5,%6,%7},{%8,%9},{%0,%1,%2,%3};\n"
        : "+f"(d[0]), "+f"(d[1]), "+f"(d[2]), "+f"(d[3])
        : "r"(a[0]), "r"(a[1]), "r"(a[2]), "r"(a[3]), "r"(b0), "r"(b1));
}
__device__ __forceinline__ void cpa16(uint32_t dst, const void* src, int sz) {
    asm volatile("cp.async.cg.shared.global [%0], [%1], 16, %2;\n"
        :: "r"(dst), "l"(src), "r"(sz));
}

// ---------------- fused RMSNorm + fp16 convert ----------------
__global__ void rmsnorm_half_k(const float* __restrict__ xext, const float* __restrict__ w,
                               int use_h, int write_xn) {
    int t = blockIdx.x;
    const float* src = use_h ? (const float*)g_h : xext;
    const float4* xr = (const float4*)(src + (size_t)t * NHID);
    float4 v = xr[threadIdx.x];
    float ss = v.x*v.x + v.y*v.y + v.z*v.z + v.w*v.w;
    #pragma unroll
    for (int o = 16; o; o >>= 1) ss += __shfl_down_sync(0xffffffffu, ss, o);
    __shared__ float red[8];
    if ((threadIdx.x & 31) == 0) red[threadIdx.x >> 5] = ss;
    __syncthreads();
    if (threadIdx.x < 8) {
        float s = red[threadIdx.x];
        #pragma unroll
        for (int o = 4; o; o >>= 1) s += __shfl_down_sync(0xffu, s, o);
        if (threadIdx.x == 0) red[0] = s;
    }
    __syncthreads();
    float rs = rsqrtf(red[0] * (1.0f / NHID) + 1e-6f);
    float4 wv = ((const float4*)w)[threadIdx.x];
    float4 ov;
    ov.x = v.x * rs * wv.x;
    ov.y = v.y * rs * wv.y;
    ov.z = v.z * rs * wv.z;
    ov.w = v.w * rs * wv.w;
    if (write_xn) {
        ((float4*)(g_xn + (size_t)t * NHID))[threadIdx.x] = ov;
    }
    uint32_t* p = (uint32_t*)(g_xnh + (size_t)t * NHID) + threadIdx.x * 2;
    p[0] = pack2h(ov.x, ov.y);
    p[1] = pack2h(ov.z, ov.w);
}

// ---------------- combined QKV weight pack ----------------
__global__ void split_pack_qkv_k(const float4* __restrict__ Wq, const float4* __restrict__ Wk,
                                 const float4* __restrict__ Wv) {
    int i = blockIdx.x * 256 + threadIdx.x;
    int el = i * 4;
    int r = el / QKVN;
    int c = el % QKVN;
    float4 v;
    if (c < 1024)      v = Wq[(r * 1024 + c) / 4];
    else if (c < 1280) v = Wk[(r * 256 + (c - 1024)) / 4];
    else               v = Wv[(r * 256 + (c - 1280)) / 4];
    uint32_t* p = (uint32_t*)(g_wqkvh + (size_t)r * QKVN + c);
    p[0] = pack2h(v.x, v.y);
    p[1] = pack2h(v.z, v.w);
}

// ---------------- plain convert: fp32 -> fp16 (sel 1: Wo, else Wd) ----------
__global__ void split_k(const float4* __restrict__ ext, int n4, int sel) {
    int i = blockIdx.x * 256 + threadIdx.x;
    if (i >= n4) return;
    uint32_t* d = (sel == 1) ? (uint32_t*)g_woh : (uint32_t*)g_wdh;
    float4 v = ext[i];
    d[i*2]   = pack2h(v.x, v.y);
    d[i*2+1] = pack2h(v.z, v.w);
}

// ---------------- gate|up interleaved pack ----------------
__global__ void split_pack_gu_k(const float4* __restrict__ Wg, const float4* __restrict__ Wu) {
    int i = blockIdx.x * 256 + threadIdx.x;
    float4 g4 = Wg[i];
    float4 u4 = Wu[i];
    int el = i * 4;
    size_t r = (size_t)(el / NF);
    int c = el % NF;
    uint4 o;
    o.x = pack2h(g4.x, u4.x);
    o.y = pack2h(g4.y, u4.y);
    o.z = pack2h(g4.z, u4.z);
    o.w = pack2h(g4.w, u4.w);
    *(uint4*)(g_wguh + r * GUN + 2 * c) = o;
}

// ---------------- tensor-core GEMM (fp16), 256x128x64 tiles, 2-stage --------
// 512 threads (16 warps, 4x4 of 64x32 microtiles), 1 CTA/SM
// op 0: QKV   A=g_xnh  B=g_wqkvh -> epilogue scatters fp16 Q(x0.125)/Kt/V
// op 1: Oproj A=g_atth B=g_woh   -> g_h AND out (Cadd = x residual)
// op 2: GU    A=gather xnh, B=g_wguh (interleaved) -> fused silu -> g_Gh fp16
// op 3: Down  A=g_Gh   B=g_wdh   -> atomic scatter onto out
// smem: A 2 stages x 256x144 = 73728 ; B 2 x 64x272 = 34816 -> 108544
#define TG_SMEM 108544

__device__ __forceinline__ void tg_load64(
        uint32_t sA, uint32_t sB, int stg, int k0,
        int ar, int ac4, int br, int bc2,
        const __half* apr, int asz,
        const __half* Bp, int N, int bx) {
    uint32_t abase = sA + stg * 73728 / 2 * 0 + stg * 36864 + ar * 144;
    #pragma unroll
    for (int i = 0; i < 4; i++) {
        int c8 = ac4 + i;
        cpa16(abase + c8 * 16, apr + k0 + c8 * 8, asz);
    }
    const __half* brow = Bp + (size_t)(k0 + br) * N + bx;
    uint32_t bbase = sB + stg * 17408 + br * 272;
    #pragma unroll
    for (int i = 0; i < 2; i++) {
        int c8 = bc2 + i;
        cpa16(bbase + c8 * 16, brow + c8 * 8, 16);
    }
    asm volatile("cp.async.commit_group;\n");
}

__global__ __launch_bounds__(512, 1) void tgemm_k(int op, const float* __restrict__ cadd_ext,
                                                  float* __restrict__ cout_ext) {
    extern __shared__ char smraw[];
    uint32_t sA = (uint32_t)__cvta_generic_to_shared(smraw);
    uint32_t sB = sA + 73728;

    const __half* Ah;
    const __half* Bh;
    float* C = 0;
    const float* Cadd = 0;
    int N, K, mode;
    if (op == 0) {
        Ah = g_xnh;  Bh = g_wqkvh;
        N = QKVN; K = NHID; mode = 0;
    } else if (op == 1) {
        Ah = g_atth; Bh = g_woh;
        C = g_h;    Cadd = cadd_ext; N = NHID; K = NHID; mode = 0;
    } else if (op == 2) {
        Ah = g_xnh;  Bh = g_wguh;
        N = GUN;  K = NHID; mode = 1;
    } else {
        Ah = g_Gh;   Bh = g_wdh;
        C = cout_ext; N = NHID; K = NF; mode = 2;
    }

    int tid = threadIdx.x;
    int bx = blockIdx.x * 128;
    int by = blockIdx.y * 256;
    int e = blockIdx.z;
    int m = NTOK;
    if (mode != 0) {
        m = g_cnt[e];
        if (by >= m) return;
        Bh += (size_t)e * K * N;
    }

    // A loader: row = tid>>1 (0..255), chunks (tid&1)*4..+3
    int ar = tid >> 1;
    int ac4 = (tid & 1) * 4;
    const __half* apr;
    int asz;
    {
        int lr = by + ar;
        size_t g0;
        bool v0 = true;
        if (mode == 0) {
            g0 = (size_t)lr;
        } else if (mode == 1) {
            v0 = lr < m;
            g0 = v0 ? (size_t)g_tok[e * NTOK + lr] : 0;
        } else {
            v0 = lr < m;
            g0 = (size_t)e * NTOK + (v0 ? (size_t)lr : 0);
        }
        apr = Ah + g0 * K;
        asz = v0 ? 16 : 0;
    }
    // B loader: row = tid>>3 (0..63), chunks (tid&7)*2..+1
    int br = tid >> 3;
    int bc2 = (tid & 7) * 2;

    int wid = tid >> 5;
    int lane = tid & 31;
    int wm = (wid >> 2) * 64;
    int wn = (wid & 3) * 32;

    float acc[4][4][4];
    #pragma unroll
    for (int i = 0; i < 4; i++) {
        #pragma unroll
        for (int j = 0; j < 4; j++) {
            #pragma unroll
            for (int r = 0; r < 4; r++) acc[i][j][r] = 0.f;
        }
    }

    int NC = K / 64;
    tg_load64(sA, sB, 0, 0, ar, ac4, br, bc2, apr, asz, Bh, N, bx);

    for (int c = 0; c < NC; c++) {
        int buf = c & 1;
        if (c + 1 < NC) {
            tg_load64(sA, sB, buf ^ 1, (c + 1) * 64, ar, ac4, br, bc2, apr, asz, Bh, N, bx);
            asm volatile("cp.async.wait_group 1;\n");
        } else {
            asm volatile("cp.async.wait_group 0;\n");
        }
        __syncthreads();

        uint32_t abase = sA + buf * 36864;
        uint32_t bbase = sB + buf * 17408;

        #pragma unroll
        for (int kk = 0; kk < 64; kk += 16) {
            uint32_t ah[4][4], bh2[2][4];
            int arow = wm + (lane & 15);
            int acolb = (kk + (lane >> 4) * 8) * 2;
            #pragma unroll
            for (int i = 0; i < 4; i++) {
                ldsm4(ah[i], abase + (arow + i*16)*144 + acolb);
            }
            int brow = kk + (lane & 15);
            #pragma unroll
            for (int j = 0; j < 2; j++) {
                ldsm4t(bh2[j], bbase + brow*272 + (wn + j*16 + (lane >> 4)*8)*2);
            }
            #pragma unroll
            for (int i = 0; i < 4; i++) {
                #pragma unroll
                for (int n8 = 0; n8 < 4; n8++) {
                    mma16816(acc[i][n8], ah[i], bh2[n8>>1][(n8&1)*2], bh2[n8>>1][(n8&1)*2+1]);
                }
            }
        }
        __syncthreads();
    }

    int ln4 = lane >> 2;
    int lc = (lane & 3) * 2;
    #pragma unroll
    for (int i = 0; i < 4; i++) {
        int r0 = wm + i * 16 + ln4;
        #pragma unroll
        for (int n8 = 0; n8 < 4; n8++) {
            int gc = bx + wn + n8 * 8 + lc;
            float* a = acc[i][n8];
            if (op == 0) {
                // scatter into attention operands, rows r0 and r0+8
                #pragma unroll
                for (int hh = 0; hh < 2; hh++) {
                    int row = by + r0 + hh * 8;
                    float va = a[hh*2];
                    float vb = a[hh*2+1];
                    int b = row >> 10;
                    int s = row & 1023;
                    if (gc < 1024) {
                        int h = gc >> 6, d = gc & 63;
                        size_t q = (((size_t)b * 16 + h) * 1024 + s) * 64 + d;
                        *(uint32_t*)(g_qh + q) = pack2h(va * 0.125f, vb * 0.125f);
                    } else if (gc < 1280) {
                        int cc = gc - 1024;
                        int g = cc >> 6, d = cc & 63;
                        size_t base = (((size_t)b * 4 + g) * 64 + d) * 1024 + s;
                        g_kth[base]        = __float2half(va);
                        g_kth[base + 1024] = __float2half(vb);
                    } else {
                        int cc = gc - 1280;
                        int g = cc >> 6, d = cc & 63;
                        size_t base = (((size_t)b * 4 + g) * 1024 + s) * 64 + d;
                        *(uint32_t*)(g_vh + base) = pack2h(va, vb);
                    }
                }
            } else if (mode == 0) {
                size_t o0 = (size_t)(by + r0) * N + gc;
                size_t o1 = o0 + (size_t)8 * N;
                float h0 = a[0] + Cadd[o0];
                float h1 = a[1] + Cadd[o0+1];
                float h2 = a[2] + Cadd[o1];
                float h3 = a[3] + Cadd[o1+1];
                C[o0] = h0; C[o0+1] = h1;
                C[o1] = h2; C[o1+1] = h3;
                cout_ext[o0] = h0; cout_ext[o0+1] = h1;
                cout_ext[o1] = h2; cout_ext[o1+1] = h3;
            } else if (mode == 1) {
                int s0 = by + r0;
                int s1 = s0 + 8;
                int n = gc >> 1;
                if (s0 < m) {
                    float r = a[0] / (1.f + __expf(-a[0])) * a[1];
                    g_Gh[((size_t)e * NTOK + s0) * NF + n] = __float2half(r);
                }
                if (s1 < m) {
                    float r = a[2] / (1.f + __expf(-a[2])) * a[3];
                    g_Gh[((size_t)e * NTOK + s1) * NF + n] = __float2half(r);
                }
            } else {
                int s0 = by + r0;
                int s1 = s0 + 8;
                if (s0 < m) {
                    int tk = g_tok[e*NTOK + s0];
                    float w = g_wgt[e*NTOK + s0];
                    atomicAdd(&C[(size_t)tk*N + gc],   w * a[0]);
                    atomicAdd(&C[(size_t)tk*N + gc+1], w * a[1]);
                }
                if (s1 < m) {
                    int tk = g_tok[e*NTOK + s1];
                    float w = g_wgt[e*NTOK + s1];
                    atomicAdd(&C[(size_t)tk*N + gc],   w * a[2]);
                    atomicAdd(&C[(size_t)tk*N + gc+1], w * a[3]);
                }
            }
        }
    }
}

// ---------------- mma flash attention (fp16 single) ----------------
#define FPITCH 144
#define FL_SMEM 46080

__device__ __forceinline__ void fl_load_kv(uint32_t base, int b, int g, int kv0, int tid) {
    #pragma unroll
    for (int j = 0; j < 4; j++) {
        int cc = tid + j * 128;
        int row = cc >> 3;
        int c8 = cc & 7;
        size_t koff = (((size_t)b * 4 + g) * 64 + row) * 1024 + kv0 + c8 * 8;
        cpa16(base + row * FPITCH + c8 * 16, g_kth + koff, 16);
    }
    #pragma unroll
    for (int j = 0; j < 4; j++) {
        int cc = tid + j * 128;
        int row = cc >> 3;
        int c8 = cc & 7;
        size_t voff = (((size_t)b * 4 + g) * 1024 + kv0 + row) * 64 + c8 * 8;
        cpa16(base + 9216 + row * FPITCH + c8 * 16, g_vh + voff, 16);
    }
    asm volatile("cp.async.commit_group;\n");
}

__global__ __launch_bounds__(128) void flashmma_k() {
    extern __shared__ char fsm[];
    uint32_t sb = (uint32_t)__cvta_generic_to_shared(fsm);
    int qt = blockIdx.x;
    int h = blockIdx.y;
    int b = blockIdx.z;
    int g = h >> 2;
    int tid = threadIdx.x;
    int wid = tid >> 5;
    int lane = tid & 31;

    #pragma unroll
    for (int j = 0; j < 4; j++) {
        int cc = tid + j * 128;
        int row = cc >> 3;
        int c8 = cc & 7;
        size_t qoff = (((size_t)b * 16 + h) * 1024 + qt * 64 + row) * 64 + c8 * 8;
        cpa16(sb + row * FPITCH + c8 * 16, g_qh + qoff, 16);
    }
    asm volatile("cp.async.commit_group;\n");
    fl_load_kv(sb + 9216, b, g, 0, tid);
    asm volatile("cp.async.wait_group 1;\n");
    __syncthreads();

    uint32_t ah[4][4];
    {
        int arow = wid * 16 + (lane & 15);
        #pragma unroll
        for (int j2 = 0; j2 < 4; j2++) {
            ldsm4(ah[j2], sb + arow * FPITCH + (uint32_t)(j2 * 16 + (lane >> 4) * 8) * 2);
        }
    }

    float m0 = -INFINITY, m1 = -INFINITY, l0 = 0.f, l1 = 0.f;
    float oacc[8][4];
    #pragma unroll
    for (int i = 0; i < 8; i++) {
        #pragma unroll
        for (int r = 0; r < 4; r++) oacc[i][r] = 0.f;
    }

    int r0g = qt * 64 + wid * 16 + (lane >> 2);

    for (int kt = 0; kt <= qt; kt++) {
        int st = kt & 1;
        if (kt < qt) {
            fl_load_kv(sb + 9216 + (st ^ 1) * 18432, b, g, (kt + 1) * 64, tid);
            asm volatile("cp.async.wait_group 1;\n");
        } else {
            asm volatile("cp.async.wait_group 0;\n");
        }
        __syncthreads();

        uint32_t kb = sb + 9216 + st * 18432;

        float sacc[8][4];
        #pragma unroll
        for (int i = 0; i < 8; i++) {
            #pragma unroll
            for (int r = 0; r < 4; r++) sacc[i][r] = 0.f;
        }
        #pragma unroll
        for (int j2 = 0; j2 < 4; j2++) {
            uint32_t bh2[4][4];
            int brow = j2 * 16 + (lane & 15);
            #pragma unroll
            for (int ng = 0; ng < 4; ng++) {
                ldsm4t(bh2[ng], kb + brow * FPITCH + (uint32_t)(ng * 16 + (lane >> 4) * 8) * 2);
            }
            #pragma unroll
            for (int n8 = 0; n8 < 8; n8++) {
                mma16816(sacc[n8], ah[j2], bh2[n8>>1][(n8&1)*2], bh2[n8>>1][(n8&1)*2+1]);
            }
        }

        if (kt == qt) {
            #pragma unroll
            for (int n8 = 0; n8 < 8; n8++) {
                int col = kt * 64 + n8 * 8 + (lane & 3) * 2;
                if (col > r0g)         sacc[n8][0] = -1e9f;
                if (col + 1 > r0g)     sacc[n8][1] = -1e9f;
                if (col > r0g + 8)     sacc[n8][2] = -1e9f;
                if (col + 1 > r0g + 8) sacc[n8][3] = -1e9f;
            }
        }

        float mx0 = -INFINITY, mx1 = -INFINITY;
        #pragma unroll
        for (int n8 = 0; n8 < 8; n8++) {
            mx0 = fmaxf(mx0, fmaxf(sacc[n8][0], sacc[n8][1]));
            mx1 = fmaxf(mx1, fmaxf(sacc[n8][2], sacc[n8][3]));
        }
        mx0 = fmaxf(mx0, __shfl_xor_sync(0xffffffffu, mx0, 1));
        mx0 = fmaxf(mx0, __shfl_xor_sync(0xffffffffu, mx0, 2));
        mx1 = fmaxf(mx1, __shfl_xor_sync(0xffffffffu, mx1, 1));
        mx1 = fmaxf(mx1, __shfl_xor_sync(0xffffffffu, mx1, 2));
        float nm0 = fmaxf(m0, mx0);
        float nm1 = fmaxf(m1, mx1);
        float f0 = __expf(m0 - nm0);
        float f1 = __expf(m1 - nm1);
        l0 *= f0;
        l1 *= f1;
        #pragma unroll
        for (int n8 = 0; n8 < 8; n8++) {
            oacc[n8][0] *= f0;
            oacc[n8][1] *= f0;
            oacc[n8][2] *= f1;
            oacc[n8][3] *= f1;
        }
        m0 = nm0;
        m1 = nm1;
        #pragma unroll
        for (int n8 = 0; n8 < 8; n8++) {
            float p0 = __expf(sacc[n8][0] - nm0);
            float p1 = __expf(sacc[n8][1] - nm0);
            float p2 = __expf(sacc[n8][2] - nm1);
            float p3 = __expf(sacc[n8][3] - nm1);
            l0 += p0 + p1;
            l1 += p2 + p3;
            sacc[n8][0] = p0;
            sacc[n8][1] = p1;
            sacc[n8][2] = p2;
            sacc[n8][3] = p3;
        }

        uint32_t vb = kb + 9216;
        #pragma unroll
        for (int j2 = 0; j2 < 4; j2++) {
            uint32_t pa[4];
            pa[0] = pack2h(sacc[2*j2][0],   sacc[2*j2][1]);
            pa[1] = pack2h(sacc[2*j2][2],   sacc[2*j2][3]);
            pa[2] = pack2h(sacc[2*j2+1][0], sacc[2*j2+1][1]);
            pa[3] = pack2h(sacc[2*j2+1][2], sacc[2*j2+1][3]);
            uint32_t vh2[4][4];
            int vrow = j2 * 16 + (lane & 15);
            #pragma unroll
            for (int ng = 0; ng < 4; ng++) {
                ldsm4t(vh2[ng], vb + vrow * FPITCH + (uint32_t)(ng * 16 + (lane >> 4) * 8) * 2);
            }
            #pragma unroll
            for (int n8 = 0; n8 < 8; n8++) {
                mma16816(oacc[n8], pa, vh2[n8>>1][(n8&1)*2], vh2[n8>>1][(n8&1)*2+1]);
            }
        }
        __syncthreads();
    }

    l0 += __shfl_xor_sync(0xffffffffu, l0, 1);
    l0 += __shfl_xor_sync(0xffffffffu, l0, 2);
    l1 += __shfl_xor_sync(0xffffffffu, l1, 1);
    l1 += __shfl_xor_sync(0xffffffffu, l1, 2);
    float i0 = 1.0f / l0;
    float i1 = 1.0f / l1;
    size_t t0 = (size_t)b * 1024 + r0g;
    size_t t1 = t0 + 8;
    #pragma unroll
    for (int n8 = 0; n8 < 8; n8++) {
        int col = h * 64 + n8 * 8 + (lane & 3) * 2;
        *(uint32_t*)(g_atth + t0 * NHID + col) = pack2h(oacc[n8][0] * i0, oacc[n8][1] * i0);
        *(uint32_t*)(g_atth + t1 * NHID + col) = pack2h(oacc[n8][2] * i1, oacc[n8][3] * i1);
    }
}

// ---------------- router (reads g_xn) ----------------
__global__ void router_k(const float* __restrict__ Wgate) {
    int t = blockIdx.x;
    float acc[NE];
    #pragma unroll
    for (int e = 0; e < NE; e++) acc[e] = 0.f;
    for (int h = threadIdx.x; h < NHID; h += 128) {
        float xv = g_xn[(size_t)t * NHID + h];
        const float4* wr = (const float4*)(Wgate + (size_t)h * NE);
        float4 w0 = wr[0];
        float4 w1 = wr[1];
        acc[0] += xv*w0.x; acc[1] += xv*w0.y; acc[2] += xv*w0.z; acc[3] += xv*w0.w;
        acc[4] += xv*w1.x; acc[5] += xv*w1.y; acc[6] += xv*w1.z; acc[7] += xv*w1.w;
    }
    #pragma unroll
    for (int e = 0; e < NE; e++) {
        #pragma unroll
        for (int o = 16; o; o >>= 1) acc[e] += __shfl_down_sync(0xffffffffu, acc[e], o);
    }
    __shared__ float sm[4][NE];
    int warp = threadIdx.x >> 5;
    int lane = threadIdx.x & 31;
    if (lane == 0) {
        for (int e = 0; e < NE; e++) sm[warp][e] = acc[e];
    }
    __syncthreads();
    if (threadIdx.x == 0) {
        float lg[NE];
        float mx = -INFINITY;
        for (int e = 0; e < NE; e++) {
            lg[e] = sm[0][e] + sm[1][e] + sm[2][e] + sm[3][e];
            mx = fmaxf(mx, lg[e]);
        }
        float p[NE];
        float sum = 0.f;
        for (int e = 0; e < NE; e++) { p[e] = expf(lg[e] - mx); sum += p[e]; }
        float inv = 1.0f / sum;
        for (int e = 0; e < NE; e++) p[e] *= inv;
        int i1 = 0;
        float b1 = p[0];
        for (int e = 1; e < NE; e++) {
            if (p[e] > b1) { b1 = p[e]; i1 = e; }
        }
        int i2 = -1;
        float b2 = -INFINITY;
        for (int e = 0; e < NE; e++) {
            if (e != i1 && p[e] > b2) { b2 = p[e]; i2 = e; }
        }
        int s1 = atomicAdd(&g_cnt[i1], 1);
        g_tok[i1 * NTOK + s1] = t;
        g_wgt[i1 * NTOK + s1] = b1;
        int s2 = atomicAdd(&g_cnt[i2], 1);
        g_tok[i2 * NTOK + s2] = t;
        g_wgt[i2 * NTOK + s2] = b2;
    }
}

__global__ void zero_cnt_k() {
    if (threadIdx.x < NE) g_cnt[threadIdx.x] = 0;
}

// ---------------- launch ----------------
extern "C" void kernel_launch(void* const* d_in, const int* in_sizes, int n_in,
                              void* d_out, int out_size) {
    (void)in_sizes; (void)n_in; (void)out_size;
    const float* x     = (const float*)d_in[0];
    const float* w_ln1 = (const float*)d_in[2];
    const float* w_ln2 = (const float*)d_in[3];
    const float* Wq    = (const float*)d_in[4];
    const float* Wk    = (const float*)d_in[5];
    const float* Wv    = (const float*)d_in[6];
    const float* Wo    = (const float*)d_in[7];
    const float* Wgate = (const float*)d_in[8];
    const float* Wg    = (const float*)d_in[9];
    const float* Wu    = (const float*)d_in[10];
    const float* Wd    = (const float*)d_in[11];
    float* out = (float*)d_out;

    cudaFuncSetAttribute(tgemm_k, cudaFuncAttributeMaxDynamicSharedMemorySize, TG_SMEM);
    cudaFuncSetAttribute(flashmma_k, cudaFuncAttributeMaxDynamicSharedMemorySize, FL_SMEM);

    // 0) fused QKV weight pack
    split_pack_qkv_k<<<NHID*QKVN/4/256, 256>>>((const float4*)Wq, (const float4*)Wk, (const float4*)Wv);
    // 1) Wo convert
    split_k<<<NHID*NHID/4/256, 256>>>((const float4*)Wo, NHID*NHID/4, 1);
    // 2) ln1 (fused fp16 convert)
    rmsnorm_half_k<<<NTOK, 256>>>(x, w_ln1, 0, 0);
    // 3) fused QKV projection -> direct fp16 Q/Kt/V scatter  <-- profiled slot
    tgemm_k<<<dim3(QKVN/128, NTOK/256), 512, TG_SMEM>>>(0, 0, 0);
    // 4) mma flash attention
    flashmma_k<<<dim3(NS/64, NHEADS, NB), 128, FL_SMEM>>>();
    // 5) output proj + residual -> g_h AND out
    tgemm_k<<<dim3(NHID/128, NTOK/256), 512, TG_SMEM>>>(1, x, out);
    // 6) ln2 (fused convert + fp32 for router)
    rmsnorm_half_k<<<NTOK, 256>>>(0, w_ln2, 1, 1);
    // 7) routing
    zero_cnt_k<<<1, 32>>>();
    router_k<<<NTOK, 128>>>(Wgate);
    // 8) gate|up interleaved weight pack
    split_pack_gu_k<<<NE*NHID*NF/4/256, 256>>>((const float4*)Wg, (const float4*)Wu);
    // 9) fused gate|up grouped GEMM + silu epilogue -> g_Gh fp16
    tgemm_k<<<dim3(GUN/128, NTOK/256, NE), 512, TG_SMEM>>>(2, 0, 0);
    // 10) Wd convert
    split_k<<<NE*NF*NHID/4/256, 256>>>((const float4*)Wd, NE*NF*NHID/4, 3);
    // 11) down-proj scatter onto out (out already holds h from step 5)
    tgemm_k<<<dim3(NHID/128, NTOK/256, NE), 512, TG_SMEM>>>(3, 0, out);
}

// round 14
// speedup vs baseline: 2.1840x; 1.0114x over previous
#include <cuda_runtime.h>
#include <cuda_fp16.h>
#include <math.h>
#include <stdint.h>

#define NB    4
#define NS    1024
#define NHID  1024
#define NHEADS 16
#define NKVH  4
#define DH    64
#define NE    8
#define NF    2048
#define NTOK  4096
#define QKVN  1536
#define GUN   4096

// ---------------- scratch (device globals, allocation-free) ----------------
__device__ float g_xn[NTOK * NHID];
__device__ __half g_xnh[NTOK * NHID];
__device__ __half g_atth[NTOK * NHID];
__device__ float g_h[NTOK * NHID];
__device__ __half g_wqkvh[NHID * QKVN];
__device__ __half g_woh[NHID * NHID];
__device__ __half g_wguh[NE * NHID * GUN];   // interleaved: col 2j=gate, 2j+1=up
__device__ __half g_wdh[NE * NF * NHID];
__device__ __half g_Gh[NE * NTOK * NF];
__device__ int   g_cnt[NE];
__device__ int   g_tok[NE * NTOK];
__device__ float g_wgt[NE * NTOK];
// attention operands: Q [b][h][s][d] (scaled), Kt [b][g][d][s], V [b][g][s][d]
__device__ __half g_qh[NB * NHEADS * NS * DH];
__device__ __half g_kth[NB * NKVH * DH * NS];
__device__ __half g_vh[NB * NKVH * NS * DH];

// ---------------- helpers ----------------
__device__ __forceinline__ uint32_t pack2h(float a, float b) {
    __half2 h = __floats2half2_rn(a, b);
    return *(uint32_t*)&h;
}
__device__ __forceinline__ void ldsm4(uint32_t* r, uint32_t a) {
    asm volatile("ldmatrix.sync.aligned.m8n8.x4.shared.b16 {%0,%1,%2,%3}, [%4];\n"
        : "=r"(r[0]), "=r"(r[1]), "=r"(r[2]), "=r"(r[3]) : "r"(a));
}
__device__ __forceinline__ void ldsm4t(uint32_t* r, uint32_t a) {
    asm volatile("ldmatrix.sync.aligned.m8n8.x4.trans.shared.b16 {%0,%1,%2,%3}, [%4];\n"
        : "=r"(r[0]), "=r"(r[1]), "=r"(r[2]), "=r"(r[3]) : "r"(a));
}
__device__ __forceinline__ void mma16816(float* d, const uint32_t* a, uint32_t b0, uint32_t b1) {
    asm volatile("mma.sync.aligned.m16n8k16.row.col.f32.f16.f16.f32 "
        "{%0,%1,%2,%3},{%4,%5,%6,%7},{%8,%9},{%0,%1,%2,%3};\n"
        : "+f"(d[0]), "+f"(d[1]), "+f"(d[2]), "+f"(d[3])
        : "r"(a[0]), "r"(a[1]), "r"(a[2]), "r"(a[3]), "r"(b0), "r"(b1));
}
__device__ __forceinline__ void cpa16(uint32_t dst, const void* src, int sz) {
    asm volatile("cp.async.cg.shared.global [%0], [%1], 16, %2;\n"
        :: "r"(dst), "l"(src), "r"(sz));
}

// ---------------- fused RMSNorm + fp16 convert ----------------
__global__ void rmsnorm_half_k(const float* __restrict__ xext, const float* __restrict__ w,
                               int use_h, int write_xn) {
    int t = blockIdx.x;
    const float* src = use_h ? (const float*)g_h : xext;
    const float4* xr = (const float4*)(src + (size_t)t * NHID);
    float4 v = xr[threadIdx.x];
    float ss = v.x*v.x + v.y*v.y + v.z*v.z + v.w*v.w;
    #pragma unroll
    for (int o = 16; o; o >>= 1) ss += __shfl_down_sync(0xffffffffu, ss, o);
    __shared__ float red[8];
    if ((threadIdx.x & 31) == 0) red[threadIdx.x >> 5] = ss;
    __syncthreads();
    if (threadIdx.x < 8) {
        float s = red[threadIdx.x];
        #pragma unroll
        for (int o = 4; o; o >>= 1) s += __shfl_down_sync(0xffu, s, o);
        if (threadIdx.x == 0) red[0] = s;
    }
    __syncthreads();
    float rs = rsqrtf(red[0] * (1.0f / NHID) + 1e-6f);
    float4 wv = ((const float4*)w)[threadIdx.x];
    float4 ov;
    ov.x = v.x * rs * wv.x;
    ov.y = v.y * rs * wv.y;
    ov.z = v.z * rs * wv.z;
    ov.w = v.w * rs * wv.w;
    if (write_xn) {
        ((float4*)(g_xn + (size_t)t * NHID))[threadIdx.x] = ov;
    }
    uint32_t* p = (uint32_t*)(g_xnh + (size_t)t * NHID) + threadIdx.x * 2;
    p[0] = pack2h(ov.x, ov.y);
    p[1] = pack2h(ov.z, ov.w);
}

// ---------------- combined QKV weight pack ----------------
__global__ void split_pack_qkv_k(const float4* __restrict__ Wq, const float4* __restrict__ Wk,
                                 const float4* __restrict__ Wv) {
    int i = blockIdx.x * 256 + threadIdx.x;
    int el = i * 4;
    int r = el / QKVN;
    int c = el % QKVN;
    float4 v;
    if (c < 1024)      v = Wq[(r * 1024 + c) / 4];
    else if (c < 1280) v = Wk[(r * 256 + (c - 1024)) / 4];
    else               v = Wv[(r * 256 + (c - 1280)) / 4];
    uint32_t* p = (uint32_t*)(g_wqkvh + (size_t)r * QKVN + c);
    p[0] = pack2h(v.x, v.y);
    p[1] = pack2h(v.z, v.w);
}

// ---------------- plain convert: fp32 -> fp16 (sel 1: Wo, else Wd) ----------
__global__ void split_k(const float4* __restrict__ ext, int n4, int sel) {
    int i = blockIdx.x * 256 + threadIdx.x;
    if (i >= n4) return;
    uint32_t* d = (sel == 1) ? (uint32_t*)g_woh : (uint32_t*)g_wdh;
    float4 v = ext[i];
    d[i*2]   = pack2h(v.x, v.y);
    d[i*2+1] = pack2h(v.z, v.w);
}

// ---------------- gate|up interleaved pack ----------------
__global__ void split_pack_gu_k(const float4* __restrict__ Wg, const float4* __restrict__ Wu) {
    int i = blockIdx.x * 256 + threadIdx.x;
    float4 g4 = Wg[i];
    float4 u4 = Wu[i];
    int el = i * 4;
    size_t r = (size_t)(el / NF);
    int c = el % NF;
    uint4 o;
    o.x = pack2h(g4.x, u4.x);
    o.y = pack2h(g4.y, u4.y);
    o.z = pack2h(g4.z, u4.z);
    o.w = pack2h(g4.w, u4.w);
    *(uint4*)(g_wguh + r * GUN + 2 * c) = o;
}

// ---------------- tensor-core GEMM (fp16), 128x128x64 tiles, 2-stage --------
// 256 threads, 2 CTA/SM
// op 0: QKV   A=g_xnh  B=g_wqkvh -> epilogue scatters fp16 Q(x0.125)/Kt/V
// op 1: Oproj A=g_atth B=g_woh   -> g_h AND out (Cadd = x residual)
// op 2: GU    A=gather xnh, B=g_wguh (interleaved) -> fused silu -> g_Gh fp16
// op 3: Down  A=g_Gh   B=g_wdh   -> atomic scatter onto out
#define TG_SMEM 71680

__device__ __forceinline__ void tg_load64(
        uint32_t sA, uint32_t sB, int stg, int k0,
        int ar, int ac4, int br, int bc4,
        const __half* apr, int asz,
        const __half* Bp, int N, int bx) {
    uint32_t abase = sA + stg * 18432 + ar * 144;
    #pragma unroll
    for (int i = 0; i < 4; i++) {
        int c8 = ac4 + i;
        cpa16(abase + c8 * 16, apr + k0 + c8 * 8, asz);
    }
    const __half* brow = Bp + (size_t)(k0 + br) * N + bx;
    uint32_t bbase = sB + stg * 17408 + br * 272;
    #pragma unroll
    for (int i = 0; i < 4; i++) {
        int c8 = bc4 + i;
        cpa16(bbase + c8 * 16, brow + c8 * 8, 16);
    }
    asm volatile("cp.async.commit_group;\n");
}

__global__ __launch_bounds__(256, 2) void tgemm_k(int op, const float* __restrict__ cadd_ext,
                                                  float* __restrict__ cout_ext) {
    extern __shared__ char smraw[];
    uint32_t sA = (uint32_t)__cvta_generic_to_shared(smraw);
    uint32_t sB = sA + 36864;

    const __half* Ah;
    const __half* Bh;
    float* C = 0;
    const float* Cadd = 0;
    int N, K, mode;
    if (op == 0) {
        Ah = g_xnh;  Bh = g_wqkvh;
        N = QKVN; K = NHID; mode = 0;
    } else if (op == 1) {
        Ah = g_atth; Bh = g_woh;
        C = g_h;    Cadd = cadd_ext; N = NHID; K = NHID; mode = 0;
    } else if (op == 2) {
        Ah = g_xnh;  Bh = g_wguh;
        N = GUN;  K = NHID; mode = 1;
    } else {
        Ah = g_Gh;   Bh = g_wdh;
        C = cout_ext; N = NHID; K = NF; mode = 2;
    }

    int tid = threadIdx.x;
    int bx = blockIdx.x * 128;
    int by = blockIdx.y * 128;
    int e = blockIdx.z;
    int m = NTOK;
    if (mode != 0) {
        m = g_cnt[e];
        if (by >= m) return;
        Bh += (size_t)e * K * N;
    }

    int ar = tid >> 1;
    int ac4 = (tid & 1) * 4;
    const __half* apr;
    int asz;
    {
        int lr = by + ar;
        size_t g0;
        bool v0 = true;
        if (mode == 0) {
            g0 = (size_t)lr;
        } else if (mode == 1) {
            v0 = lr < m;
            g0 = v0 ? (size_t)g_tok[e * NTOK + lr] : 0;
        } else {
            v0 = lr < m;
            g0 = (size_t)e * NTOK + (v0 ? (size_t)lr : 0);
        }
        apr = Ah + g0 * K;
        asz = v0 ? 16 : 0;
    }
    int br = tid >> 2;
    int bc4 = (tid & 3) * 4;

    int wid = tid >> 5;
    int lane = tid & 31;
    int wm = (wid >> 2) * 64;
    int wn = (wid & 3) * 32;

    float acc[4][4][4];
    #pragma unroll
    for (int i = 0; i < 4; i++) {
        #pragma unroll
        for (int j = 0; j < 4; j++) {
            #pragma unroll
            for (int r = 0; r < 4; r++) acc[i][j][r] = 0.f;
        }
    }

    int NC = K / 64;
    tg_load64(sA, sB, 0, 0, ar, ac4, br, bc4, apr, asz, Bh, N, bx);

    for (int c = 0; c < NC; c++) {
        int buf = c & 1;
        if (c + 1 < NC) {
            tg_load64(sA, sB, buf ^ 1, (c + 1) * 64, ar, ac4, br, bc4, apr, asz, Bh, N, bx);
            asm volatile("cp.async.wait_group 1;\n");
        } else {
            asm volatile("cp.async.wait_group 0;\n");
        }
        __syncthreads();

        uint32_t abase = sA + buf * 18432;
        uint32_t bbase = sB + buf * 17408;

        #pragma unroll
        for (int kk = 0; kk < 64; kk += 16) {
            uint32_t ah[4][4], bh2[2][4];
            int arow = wm + (lane & 15);
            int acolb = (kk + (lane >> 4) * 8) * 2;
            #pragma unroll
            for (int i = 0; i < 4; i++) {
                ldsm4(ah[i], abase + (arow + i*16)*144 + acolb);
            }
            int brow = kk + (lane & 15);
            #pragma unroll
            for (int j = 0; j < 2; j++) {
                ldsm4t(bh2[j], bbase + brow*272 + (wn + j*16 + (lane >> 4)*8)*2);
            }
            #pragma unroll
            for (int i = 0; i < 4; i++) {
                #pragma unroll
                for (int n8 = 0; n8 < 4; n8++) {
                    mma16816(acc[i][n8], ah[i], bh2[n8>>1][(n8&1)*2], bh2[n8>>1][(n8&1)*2+1]);
                }
            }
        }
        __syncthreads();
    }

    int ln4 = lane >> 2;
    int lc = (lane & 3) * 2;
    #pragma unroll
    for (int i = 0; i < 4; i++) {
        int r0 = wm + i * 16 + ln4;
        #pragma unroll
        for (int n8 = 0; n8 < 4; n8++) {
            int gc = bx + wn + n8 * 8 + lc;
            float* a = acc[i][n8];
            if (op == 0) {
                // scatter into attention operands, rows r0 and r0+8
                #pragma unroll
                for (int hh = 0; hh < 2; hh++) {
                    int row = by + r0 + hh * 8;
                    float va = a[hh*2];
                    float vb = a[hh*2+1];
                    int b = row >> 10;
                    int s = row & 1023;
                    if (gc < 1024) {
                        int h = gc >> 6, d = gc & 63;
                        size_t q = (((size_t)b * 16 + h) * 1024 + s) * 64 + d;
                        *(uint32_t*)(g_qh + q) = pack2h(va * 0.125f, vb * 0.125f);
                    } else if (gc < 1280) {
                        int cc = gc - 1024;
                        int g = cc >> 6, d = cc & 63;
                        size_t base = (((size_t)b * 4 + g) * 64 + d) * 1024 + s;
                        g_kth[base]        = __float2half(va);
                        g_kth[base + 1024] = __float2half(vb);
                    } else {
                        int cc = gc - 1280;
                        int g = cc >> 6, d = cc & 63;
                        size_t base = (((size_t)b * 4 + g) * 1024 + s) * 64 + d;
                        *(uint32_t*)(g_vh + base) = pack2h(va, vb);
                    }
                }
            } else if (mode == 0) {
                size_t o0 = (size_t)(by + r0) * N + gc;
                size_t o1 = o0 + (size_t)8 * N;
                float h0 = a[0] + Cadd[o0];
                float h1 = a[1] + Cadd[o0+1];
                float h2 = a[2] + Cadd[o1];
                float h3 = a[3] + Cadd[o1+1];
                C[o0] = h0; C[o0+1] = h1;
                C[o1] = h2; C[o1+1] = h3;
                cout_ext[o0] = h0; cout_ext[o0+1] = h1;
                cout_ext[o1] = h2; cout_ext[o1+1] = h3;
            } else if (mode == 1) {
                int s0 = by + r0;
                int s1 = s0 + 8;
                int n = gc >> 1;
                if (s0 < m) {
                    float r = a[0] / (1.f + __expf(-a[0])) * a[1];
                    g_Gh[((size_t)e * NTOK + s0) * NF + n] = __float2half(r);
                }
                if (s1 < m) {
                    float r = a[2] / (1.f + __expf(-a[2])) * a[3];
                    g_Gh[((size_t)e * NTOK + s1) * NF + n] = __float2half(r);
                }
            } else {
                int s0 = by + r0;
                int s1 = s0 + 8;
                if (s0 < m) {
                    int tk = g_tok[e*NTOK + s0];
                    float w = g_wgt[e*NTOK + s0];
                    atomicAdd(&C[(size_t)tk*N + gc],   w * a[0]);
                    atomicAdd(&C[(size_t)tk*N + gc+1], w * a[1]);
                }
                if (s1 < m) {
                    int tk = g_tok[e*NTOK + s1];
                    float w = g_wgt[e*NTOK + s1];
                    atomicAdd(&C[(size_t)tk*N + gc],   w * a[2]);
                    atomicAdd(&C[(size_t)tk*N + gc+1], w * a[3]);
                }
            }
        }
    }
}

// ---------------- mma flash attention (fp16 single) ----------------
#define FPITCH 144
#define FL_SMEM 46080

__device__ __forceinline__ void fl_load_kv(uint32_t base, int b, int g, int kv0, int tid) {
    #pragma unroll
    for (int j = 0; j < 4; j++) {
        int cc = tid + j * 128;
        int row = cc >> 3;
        int c8 = cc & 7;
        size_t koff = (((size_t)b * 4 + g) * 64 + row) * 1024 + kv0 + c8 * 8;
        cpa16(base + row * FPITCH + c8 * 16, g_kth + koff, 16);
    }
    #pragma unroll
    for (int j = 0; j < 4; j++) {
        int cc = tid + j * 128;
        int row = cc >> 3;
        int c8 = cc & 7;
        size_t voff = (((size_t)b * 4 + g) * 1024 + kv0 + row) * 64 + c8 * 8;
        cpa16(base + 9216 + row * FPITCH + c8 * 16, g_vh + voff, 16);
    }
    asm volatile("cp.async.commit_group;\n");
}

__global__ __launch_bounds__(128) void flashmma_k() {
    extern __shared__ char fsm[];
    uint32_t sb = (uint32_t)__cvta_generic_to_shared(fsm);
    int qt = blockIdx.x;
    int h = blockIdx.y;
    int b = blockIdx.z;
    int g = h >> 2;
    int tid = threadIdx.x;
    int wid = tid >> 5;
    int lane = tid & 31;

    #pragma unroll
    for (int j = 0; j < 4; j++) {
        int cc = tid + j * 128;
        int row = cc >> 3;
        int c8 = cc & 7;
        size_t qoff = (((size_t)b * 16 + h) * 1024 + qt * 64 + row) * 64 + c8 * 8;
        cpa16(sb + row * FPITCH + c8 * 16, g_qh + qoff, 16);
    }
    asm volatile("cp.async.commit_group;\n");
    fl_load_kv(sb + 9216, b, g, 0, tid);
    asm volatile("cp.async.wait_group 1;\n");
    __syncthreads();

    uint32_t ah[4][4];
    {
        int arow = wid * 16 + (lane & 15);
        #pragma unroll
        for (int j2 = 0; j2 < 4; j2++) {
            ldsm4(ah[j2], sb + arow * FPITCH + (uint32_t)(j2 * 16 + (lane >> 4) * 8) * 2);
        }
    }

    float m0 = -INFINITY, m1 = -INFINITY, l0 = 0.f, l1 = 0.f;
    float oacc[8][4];
    #pragma unroll
    for (int i = 0; i < 8; i++) {
        #pragma unroll
        for (int r = 0; r < 4; r++) oacc[i][r] = 0.f;
    }

    int r0g = qt * 64 + wid * 16 + (lane >> 2);

    for (int kt = 0; kt <= qt; kt++) {
        int st = kt & 1;
        if (kt < qt) {
            fl_load_kv(sb + 9216 + (st ^ 1) * 18432, b, g, (kt + 1) * 64, tid);
            asm volatile("cp.async.wait_group 1;\n");
        } else {
            asm volatile("cp.async.wait_group 0;\n");
        }
        __syncthreads();

        uint32_t kb = sb + 9216 + st * 18432;

        float sacc[8][4];
        #pragma unroll
        for (int i = 0; i < 8; i++) {
            #pragma unroll
            for (int r = 0; r < 4; r++) sacc[i][r] = 0.f;
        }
        #pragma unroll
        for (int j2 = 0; j2 < 4; j2++) {
            uint32_t bh2[4][4];
            int brow = j2 * 16 + (lane & 15);
            #pragma unroll
            for (int ng = 0; ng < 4; ng++) {
                ldsm4t(bh2[ng], kb + brow * FPITCH + (uint32_t)(ng * 16 + (lane >> 4) * 8) * 2);
            }
            #pragma unroll
            for (int n8 = 0; n8 < 8; n8++) {
                mma16816(sacc[n8], ah[j2], bh2[n8>>1][(n8&1)*2], bh2[n8>>1][(n8&1)*2+1]);
            }
        }

        if (kt == qt) {
            #pragma unroll
            for (int n8 = 0; n8 < 8; n8++) {
                int col = kt * 64 + n8 * 8 + (lane & 3) * 2;
                if (col > r0g)         sacc[n8][0] = -1e9f;
                if (col + 1 > r0g)     sacc[n8][1] = -1e9f;
                if (col > r0g + 8)     sacc[n8][2] = -1e9f;
                if (col + 1 > r0g + 8) sacc[n8][3] = -1e9f;
            }
        }

        float mx0 = -INFINITY, mx1 = -INFINITY;
        #pragma unroll
        for (int n8 = 0; n8 < 8; n8++) {
            mx0 = fmaxf(mx0, fmaxf(sacc[n8][0], sacc[n8][1]));
            mx1 = fmaxf(mx1, fmaxf(sacc[n8][2], sacc[n8][3]));
        }
        mx0 = fmaxf(mx0, __shfl_xor_sync(0xffffffffu, mx0, 1));
        mx0 = fmaxf(mx0, __shfl_xor_sync(0xffffffffu, mx0, 2));
        mx1 = fmaxf(mx1, __shfl_xor_sync(0xffffffffu, mx1, 1));
        mx1 = fmaxf(mx1, __shfl_xor_sync(0xffffffffu, mx1, 2));
        float nm0 = fmaxf(m0, mx0);
        float nm1 = fmaxf(m1, mx1);
        float f0 = __expf(m0 - nm0);
        float f1 = __expf(m1 - nm1);
        l0 *= f0;
        l1 *= f1;
        #pragma unroll
        for (int n8 = 0; n8 < 8; n8++) {
            oacc[n8][0] *= f0;
            oacc[n8][1] *= f0;
            oacc[n8][2] *= f1;
            oacc[n8][3] *= f1;
        }
        m0 = nm0;
        m1 = nm1;
        #pragma unroll
        for (int n8 = 0; n8 < 8; n8++) {
            float p0 = __expf(sacc[n8][0] - nm0);
            float p1 = __expf(sacc[n8][1] - nm0);
            float p2 = __expf(sacc[n8][2] - nm1);
            float p3 = __expf(sacc[n8][3] - nm1);
            l0 += p0 + p1;
            l1 += p2 + p3;
            sacc[n8][0] = p0;
            sacc[n8][1] = p1;
            sacc[n8][2] = p2;
            sacc[n8][3] = p3;
        }

        uint32_t vb = kb + 9216;
        #pragma unroll
        for (int j2 = 0; j2 < 4; j2++) {
            uint32_t pa[4];
            pa[0] = pack2h(sacc[2*j2][0],   sacc[2*j2][1]);
            pa[1] = pack2h(sacc[2*j2][2],   sacc[2*j2][3]);
            pa[2] = pack2h(sacc[2*j2+1][0], sacc[2*j2+1][1]);
            pa[3] = pack2h(sacc[2*j2+1][2], sacc[2*j2+1][3]);
            uint32_t vh2[4][4];
            int vrow = j2 * 16 + (lane & 15);
            #pragma unroll
            for (int ng = 0; ng < 4; ng++) {
                ldsm4t(vh2[ng], vb + vrow * FPITCH + (uint32_t)(ng * 16 + (lane >> 4) * 8) * 2);
            }
            #pragma unroll
            for (int n8 = 0; n8 < 8; n8++) {
                mma16816(oacc[n8], pa, vh2[n8>>1][(n8&1)*2], vh2[n8>>1][(n8&1)*2+1]);
            }
        }
        __syncthreads();
    }

    l0 += __shfl_xor_sync(0xffffffffu, l0, 1);
    l0 += __shfl_xor_sync(0xffffffffu, l0, 2);
    l1 += __shfl_xor_sync(0xffffffffu, l1, 1);
    l1 += __shfl_xor_sync(0xffffffffu, l1, 2);
    float i0 = 1.0f / l0;
    float i1 = 1.0f / l1;
    size_t t0 = (size_t)b * 1024 + r0g;
    size_t t1 = t0 + 8;
    #pragma unroll
    for (int n8 = 0; n8 < 8; n8++) {
        int col = h * 64 + n8 * 8 + (lane & 3) * 2;
        *(uint32_t*)(g_atth + t0 * NHID + col) = pack2h(oacc[n8][0] * i0, oacc[n8][1] * i0);
        *(uint32_t*)(g_atth + t1 * NHID + col) = pack2h(oacc[n8][2] * i1, oacc[n8][3] * i1);
    }
}

// ---------------- router (reads g_xn) ----------------
__global__ void router_k(const float* __restrict__ Wgate) {
    int t = blockIdx.x;
    float acc[NE];
    #pragma unroll
    for (int e = 0; e < NE; e++) acc[e] = 0.f;
    for (int h = threadIdx.x; h < NHID; h += 128) {
        float xv = g_xn[(size_t)t * NHID + h];
        const float4* wr = (const float4*)(Wgate + (size_t)h * NE);
        float4 w0 = wr[0];
        float4 w1 = wr[1];
        acc[0] += xv*w0.x; acc[1] += xv*w0.y; acc[2] += xv*w0.z; acc[3] += xv*w0.w;
        acc[4] += xv*w1.x; acc[5] += xv*w1.y; acc[6] += xv*w1.z; acc[7] += xv*w1.w;
    }
    #pragma unroll
    for (int e = 0; e < NE; e++) {
        #pragma unroll
        for (int o = 16; o; o >>= 1) acc[e] += __shfl_down_sync(0xffffffffu, acc[e], o);
    }
    __shared__ float sm[4][NE];
    int warp = threadIdx.x >> 5;
    int lane = threadIdx.x & 31;
    if (lane == 0) {
        for (int e = 0; e < NE; e++) sm[warp][e] = acc[e];
    }
    __syncthreads();
    if (threadIdx.x == 0) {
        float lg[NE];
        float mx = -INFINITY;
        for (int e = 0; e < NE; e++) {
            lg[e] = sm[0][e] + sm[1][e] + sm[2][e] + sm[3][e];
            mx = fmaxf(mx, lg[e]);
        }
        float p[NE];
        float sum = 0.f;
        for (int e = 0; e < NE; e++) { p[e] = expf(lg[e] - mx); sum += p[e]; }
        float inv = 1.0f / sum;
        for (int e = 0; e < NE; e++) p[e] *= inv;
        int i1 = 0;
        float b1 = p[0];
        for (int e = 1; e < NE; e++) {
            if (p[e] > b1) { b1 = p[e]; i1 = e; }
        }
        int i2 = -1;
        float b2 = -INFINITY;
        for (int e = 0; e < NE; e++) {
            if (e != i1 && p[e] > b2) { b2 = p[e]; i2 = e; }
        }
        int s1 = atomicAdd(&g_cnt[i1], 1);
        g_tok[i1 * NTOK + s1] = t;
        g_wgt[i1 * NTOK + s1] = b1;
        int s2 = atomicAdd(&g_cnt[i2], 1);
        g_tok[i2 * NTOK + s2] = t;
        g_wgt[i2 * NTOK + s2] = b2;
    }
}

__global__ void zero_cnt_k() {
    if (threadIdx.x < NE) g_cnt[threadIdx.x] = 0;
}

// ---------------- launch ----------------
extern "C" void kernel_launch(void* const* d_in, const int* in_sizes, int n_in,
                              void* d_out, int out_size) {
    (void)in_sizes; (void)n_in; (void)out_size;
    const float* x     = (const float*)d_in[0];
    const float* w_ln1 = (const float*)d_in[2];
    const float* w_ln2 = (const float*)d_in[3];
    const float* Wq    = (const float*)d_in[4];
    const float* Wk    = (const float*)d_in[5];
    const float* Wv    = (const float*)d_in[6];
    const float* Wo    = (const float*)d_in[7];
    const float* Wgate = (const float*)d_in[8];
    const float* Wg    = (const float*)d_in[9];
    const float* Wu    = (const float*)d_in[10];
    const float* Wd    = (const float*)d_in[11];
    float* out = (float*)d_out;

    cudaFuncSetAttribute(tgemm_k, cudaFuncAttributeMaxDynamicSharedMemorySize, TG_SMEM);
    cudaFuncSetAttribute(flashmma_k, cudaFuncAttributeMaxDynamicSharedMemorySize, FL_SMEM);

    // 0) fused QKV weight pack
    split_pack_qkv_k<<<NHID*QKVN/4/256, 256>>>((const float4*)Wq, (const float4*)Wk, (const float4*)Wv);
    // 1) Wo convert
    split_k<<<NHID*NHID/4/256, 256>>>((const float4*)Wo, NHID*NHID/4, 1);
    // 2) ln1 (fused fp16 convert)
    rmsnorm_half_k<<<NTOK, 256>>>(x, w_ln1, 0, 0);
    // 3) fused QKV projection -> direct fp16 Q/Kt/V scatter  <-- profiled slot
    tgemm_k<<<dim3(QKVN/128, NTOK/128), 256, TG_SMEM>>>(0, 0, 0);
    // 4) mma flash attention
    flashmma_k<<<dim3(NS/64, NHEADS, NB), 128, FL_SMEM>>>();
    // 5) output proj + residual -> g_h AND out
    tgemm_k<<<dim3(NHID/128, NTOK/128), 256, TG_SMEM>>>(1, x, out);
    // 6) ln2 (fused convert + fp32 for router)
    rmsnorm_half_k<<<NTOK, 256>>>(0, w_ln2, 1, 1);
    // 7) routing
    zero_cnt_k<<<1, 32>>>();
    router_k<<<NTOK, 128>>>(Wgate);
    // 8) gate|up interleaved weight pack
    split_pack_gu_k<<<NE*NHID*NF/4/256, 256>>>((const float4*)Wg, (const float4*)Wu);
    // 9) fused gate|up grouped GEMM + silu epilogue -> g_Gh fp16
    tgemm_k<<<dim3(GUN/128, NTOK/128, NE), 256, TG_SMEM>>>(2, 0, 0);
    // 10) Wd convert
    split_k<<<NE*NF*NHID/4/256, 256>>>((const float4*)Wd, NE*NF*NHID/4, 3);
    // 11) down-proj scatter onto out (out already holds h from step 5)
    tgemm_k<<<dim3(NHID/128, NTOK/128, NE), 256, TG_SMEM>>>(3, 0, out);
}

// round 15
// speedup vs baseline: 2.2136x; 1.0135x over previous
#include <cuda_runtime.h>
#include <cuda_fp16.h>
#include <math.h>
#include <stdint.h>

#define NB    4
#define NS    1024
#define NHID  1024
#define NHEADS 16
#define NKVH  4
#define DH    64
#define NE    8
#define NF    2048
#define NTOK  4096
#define QKVN  1536
#define GUN   4096

// ---------------- scratch (device globals, allocation-free) ----------------
__device__ float g_xn[NTOK * NHID];
__device__ __half g_xnh[NTOK * NHID];
__device__ __half g_atth[NTOK * NHID];
__device__ float g_h[NTOK * NHID];
__device__ __half g_wqkvh[NHID * QKVN];
__device__ __half g_woh[NHID * NHID];
__device__ __half g_wguh[NE * NHID * GUN];   // interleaved: col 2j=gate, 2j+1=up
__device__ __half g_wdh[NE * NF * NHID];
__device__ __half g_Gh[NE * NTOK * NF];
__device__ int   g_cnt[NE];
__device__ int   g_tok[NE * NTOK];
__device__ float g_wgt[NE * NTOK];
// attention operands: Q [b][h][s][d] (scaled), Kt [b][g][d][s], V [b][g][s][d]
__device__ __half g_qh[NB * NHEADS * NS * DH];
__device__ __half g_kth[NB * NKVH * DH * NS];
__device__ __half g_vh[NB * NKVH * NS * DH];

// ---------------- helpers ----------------
__device__ __forceinline__ uint32_t pack2h(float a, float b) {
    __half2 h = __floats2half2_rn(a, b);
    return *(uint32_t*)&h;
}
__device__ __forceinline__ void ldsm4(uint32_t* r, uint32_t a) {
    asm volatile("ldmatrix.sync.aligned.m8n8.x4.shared.b16 {%0,%1,%2,%3}, [%4];\n"
        : "=r"(r[0]), "=r"(r[1]), "=r"(r[2]), "=r"(r[3]) : "r"(a));
}
__device__ __forceinline__ void ldsm4t(uint32_t* r, uint32_t a) {
    asm volatile("ldmatrix.sync.aligned.m8n8.x4.trans.shared.b16 {%0,%1,%2,%3}, [%4];\n"
        : "=r"(r[0]), "=r"(r[1]), "=r"(r[2]), "=r"(r[3]) : "r"(a));
}
__device__ __forceinline__ void mma16816(float* d, const uint32_t* a, uint32_t b0, uint32_t b1) {
    asm volatile("mma.sync.aligned.m16n8k16.row.col.f32.f16.f16.f32 "
        "{%0,%1,%2,%3},{%4,%5,%6,%7},{%8,%9},{%0,%1,%2,%3};\n"
        : "+f"(d[0]), "+f"(d[1]), "+f"(d[2]), "+f"(d[3])
        : "r"(a[0]), "r"(a[1]), "r"(a[2]), "r"(a[3]), "r"(b0), "r"(b1));
}
__device__ __forceinline__ void cpa16(uint32_t dst, const void* src, int sz) {
    asm volatile("cp.async.cg.shared.global [%0], [%1], 16, %2;\n"
        :: "r"(dst), "l"(src), "r"(sz));
}

// ---------------- fused RMSNorm + fp16 convert ----------------
__global__ void rmsnorm_half_k(const float* __restrict__ xext, const float* __restrict__ w,
                               int use_h, int write_xn) {
    int t = blockIdx.x;
    const float* src = use_h ? (const float*)g_h : xext;
    const float4* xr = (const float4*)(src + (size_t)t * NHID);
    float4 v = xr[threadIdx.x];
    float ss = v.x*v.x + v.y*v.y + v.z*v.z + v.w*v.w;
    #pragma unroll
    for (int o = 16; o; o >>= 1) ss += __shfl_down_sync(0xffffffffu, ss, o);
    __shared__ float red[8];
    if ((threadIdx.x & 31) == 0) red[threadIdx.x >> 5] = ss;
    __syncthreads();
    if (threadIdx.x < 8) {
        float s = red[threadIdx.x];
        #pragma unroll
        for (int o = 4; o; o >>= 1) s += __shfl_down_sync(0xffu, s, o);
        if (threadIdx.x == 0) red[0] = s;
    }
    __syncthreads();
    float rs = rsqrtf(red[0] * (1.0f / NHID) + 1e-6f);
    float4 wv = ((const float4*)w)[threadIdx.x];
    float4 ov;
    ov.x = v.x * rs * wv.x;
    ov.y = v.y * rs * wv.y;
    ov.z = v.z * rs * wv.z;
    ov.w = v.w * rs * wv.w;
    if (write_xn) {
        ((float4*)(g_xn + (size_t)t * NHID))[threadIdx.x] = ov;
    }
    uint32_t* p = (uint32_t*)(g_xnh + (size_t)t * NHID) + threadIdx.x * 2;
    p[0] = pack2h(ov.x, ov.y);
    p[1] = pack2h(ov.z, ov.w);
}

// ---------------- combined QKV weight pack ----------------
__global__ void split_pack_qkv_k(const float4* __restrict__ Wq, const float4* __restrict__ Wk,
                                 const float4* __restrict__ Wv) {
    int i = blockIdx.x * 256 + threadIdx.x;
    int el = i * 4;
    int r = el / QKVN;
    int c = el % QKVN;
    float4 v;
    if (c < 1024)      v = Wq[(r * 1024 + c) / 4];
    else if (c < 1280) v = Wk[(r * 256 + (c - 1024)) / 4];
    else               v = Wv[(r * 256 + (c - 1280)) / 4];
    uint32_t* p = (uint32_t*)(g_wqkvh + (size_t)r * QKVN + c);
    p[0] = pack2h(v.x, v.y);
    p[1] = pack2h(v.z, v.w);
}

// ---------------- plain convert: fp32 -> fp16 (sel 1: Wo, else Wd) ----------
__global__ void split_k(const float4* __restrict__ ext, int n4, int sel) {
    int i = blockIdx.x * 256 + threadIdx.x;
    if (i >= n4) return;
    uint32_t* d = (sel == 1) ? (uint32_t*)g_woh : (uint32_t*)g_wdh;
    float4 v = ext[i];
    d[i*2]   = pack2h(v.x, v.y);
    d[i*2+1] = pack2h(v.z, v.w);
}

// ---------------- gate|up interleaved pack ----------------
__global__ void split_pack_gu_k(const float4* __restrict__ Wg, const float4* __restrict__ Wu) {
    int i = blockIdx.x * 256 + threadIdx.x;
    float4 g4 = Wg[i];
    float4 u4 = Wu[i];
    int el = i * 4;
    size_t r = (size_t)(el / NF);
    int c = el % NF;
    uint4 o;
    o.x = pack2h(g4.x, u4.x);
    o.y = pack2h(g4.y, u4.y);
    o.z = pack2h(g4.z, u4.z);
    o.w = pack2h(g4.w, u4.w);
    *(uint4*)(g_wguh + r * GUN + 2 * c) = o;
}

// ---------------- tensor-core GEMM (fp16), 128x128x64 tiles, 3-stage --------
// 256 threads, 2 CTA/SM; single __syncthreads per chunk (distance-2 prefetch)
// op 0: QKV   A=g_xnh  B=g_wqkvh -> epilogue scatters fp16 Q(x0.125)/Kt/V
// op 1: Oproj A=g_atth B=g_woh   -> g_h AND out (Cadd = x residual)
// op 2: GU    A=gather xnh, B=g_wguh (interleaved) -> fused silu -> g_Gh fp16
// op 3: Down  A=g_Gh   B=g_wdh   -> atomic scatter onto out
// smem: A 3 x 128x144 = 55296 ; B 3 x 64x272 = 52224 -> 107520 (2 CTAs = 215KB)
#define TG_SMEM 107520

__device__ __forceinline__ void tg_load64(
        uint32_t sA, uint32_t sB, int stg, int k0,
        int ar, int ac4, int br, int bc4,
        const __half* apr, int asz,
        const __half* Bp, int N, int bx) {
    uint32_t abase = sA + stg * 18432 + ar * 144;
    #pragma unroll
    for (int i = 0; i < 4; i++) {
        int c8 = ac4 + i;
        cpa16(abase + c8 * 16, apr + k0 + c8 * 8, asz);
    }
    const __half* brow = Bp + (size_t)(k0 + br) * N + bx;
    uint32_t bbase = sB + stg * 17408 + br * 272;
    #pragma unroll
    for (int i = 0; i < 4; i++) {
        int c8 = bc4 + i;
        cpa16(bbase + c8 * 16, brow + c8 * 8, 16);
    }
    asm volatile("cp.async.commit_group;\n");
}

__global__ __launch_bounds__(256, 2) void tgemm_k(int op, const float* __restrict__ cadd_ext,
                                                  float* __restrict__ cout_ext) {
    extern __shared__ char smraw[];
    uint32_t sA = (uint32_t)__cvta_generic_to_shared(smraw);
    uint32_t sB = sA + 55296;

    const __half* Ah;
    const __half* Bh;
    float* C = 0;
    const float* Cadd = 0;
    int N, K, mode;
    if (op == 0) {
        Ah = g_xnh;  Bh = g_wqkvh;
        N = QKVN; K = NHID; mode = 0;
    } else if (op == 1) {
        Ah = g_atth; Bh = g_woh;
        C = g_h;    Cadd = cadd_ext; N = NHID; K = NHID; mode = 0;
    } else if (op == 2) {
        Ah = g_xnh;  Bh = g_wguh;
        N = GUN;  K = NHID; mode = 1;
    } else {
        Ah = g_Gh;   Bh = g_wdh;
        C = cout_ext; N = NHID; K = NF; mode = 2;
    }

    int tid = threadIdx.x;
    int bx = blockIdx.x * 128;
    int by = blockIdx.y * 128;
    int e = blockIdx.z;
    int m = NTOK;
    if (mode != 0) {
        m = g_cnt[e];
        if (by >= m) return;
        Bh += (size_t)e * K * N;
    }

    int ar = tid >> 1;
    int ac4 = (tid & 1) * 4;
    const __half* apr;
    int asz;
    {
        int lr = by + ar;
        size_t g0;
        bool v0 = true;
        if (mode == 0) {
            g0 = (size_t)lr;
        } else if (mode == 1) {
            v0 = lr < m;
            g0 = v0 ? (size_t)g_tok[e * NTOK + lr] : 0;
        } else {
            v0 = lr < m;
            g0 = (size_t)e * NTOK + (v0 ? (size_t)lr : 0);
        }
        apr = Ah + g0 * K;
        asz = v0 ? 16 : 0;
    }
    int br = tid >> 2;
    int bc4 = (tid & 3) * 4;

    int wid = tid >> 5;
    int lane = tid & 31;
    int wm = (wid >> 2) * 64;
    int wn = (wid & 3) * 32;

    float acc[4][4][4];
    #pragma unroll
    for (int i = 0; i < 4; i++) {
        #pragma unroll
        for (int j = 0; j < 4; j++) {
            #pragma unroll
            for (int r = 0; r < 4; r++) acc[i][j][r] = 0.f;
        }
    }

    int NC = K / 64;
    tg_load64(sA, sB, 0, 0,  ar, ac4, br, bc4, apr, asz, Bh, N, bx);
    tg_load64(sA, sB, 1, 64, ar, ac4, br, bc4, apr, asz, Bh, N, bx);

    for (int c = 0; c < NC; c++) {
        if (c + 1 < NC) {
            asm volatile("cp.async.wait_group 1;\n");
        } else {
            asm volatile("cp.async.wait_group 0;\n");
        }
        __syncthreads();
        int ld = c + 2;
        if (ld < NC) {
            int ls = ld - (ld / 3) * 3;
            tg_load64(sA, sB, ls, ld * 64, ar, ac4, br, bc4, apr, asz, Bh, N, bx);
        }
        int st = c - (c / 3) * 3;
        uint32_t abase = sA + st * 18432;
        uint32_t bbase = sB + st * 17408;

        #pragma unroll
        for (int kk = 0; kk < 64; kk += 16) {
            uint32_t ah[4][4], bh2[2][4];
            int arow = wm + (lane & 15);
            int acolb = (kk + (lane >> 4) * 8) * 2;
            #pragma unroll
            for (int i = 0; i < 4; i++) {
                ldsm4(ah[i], abase + (arow + i*16)*144 + acolb);
            }
            int brow = kk + (lane & 15);
            #pragma unroll
            for (int j = 0; j < 2; j++) {
                ldsm4t(bh2[j], bbase + brow*272 + (wn + j*16 + (lane >> 4)*8)*2);
            }
            #pragma unroll
            for (int i = 0; i < 4; i++) {
                #pragma unroll
                for (int n8 = 0; n8 < 4; n8++) {
                    mma16816(acc[i][n8], ah[i], bh2[n8>>1][(n8&1)*2], bh2[n8>>1][(n8&1)*2+1]);
                }
            }
        }
    }

    int ln4 = lane >> 2;
    int lc = (lane & 3) * 2;
    #pragma unroll
    for (int i = 0; i < 4; i++) {
        int r0 = wm + i * 16 + ln4;
        #pragma unroll
        for (int n8 = 0; n8 < 4; n8++) {
            int gc = bx + wn + n8 * 8 + lc;
            float* a = acc[i][n8];
            if (op == 0) {
                #pragma unroll
                for (int hh = 0; hh < 2; hh++) {
                    int row = by + r0 + hh * 8;
                    float va = a[hh*2];
                    float vb = a[hh*2+1];
                    int b = row >> 10;
                    int s = row & 1023;
                    if (gc < 1024) {
                        int h = gc >> 6, d = gc & 63;
                        size_t q = (((size_t)b * 16 + h) * 1024 + s) * 64 + d;
                        *(uint32_t*)(g_qh + q) = pack2h(va * 0.125f, vb * 0.125f);
                    } else if (gc < 1280) {
                        int cc = gc - 1024;
                        int g = cc >> 6, d = cc & 63;
                        size_t base = (((size_t)b * 4 + g) * 64 + d) * 1024 + s;
                        g_kth[base]        = __float2half(va);
                        g_kth[base + 1024] = __float2half(vb);
                    } else {
                        int cc = gc - 1280;
                        int g = cc >> 6, d = cc & 63;
                        size_t base = (((size_t)b * 4 + g) * 1024 + s) * 64 + d;
                        *(uint32_t*)(g_vh + base) = pack2h(va, vb);
                    }
                }
            } else if (mode == 0) {
                size_t o0 = (size_t)(by + r0) * N + gc;
                size_t o1 = o0 + (size_t)8 * N;
                float h0 = a[0] + Cadd[o0];
                float h1 = a[1] + Cadd[o0+1];
                float h2 = a[2] + Cadd[o1];
                float h3 = a[3] + Cadd[o1+1];
                C[o0] = h0; C[o0+1] = h1;
                C[o1] = h2; C[o1+1] = h3;
                cout_ext[o0] = h0; cout_ext[o0+1] = h1;
                cout_ext[o1] = h2; cout_ext[o1+1] = h3;
            } else if (mode == 1) {
                int s0 = by + r0;
                int s1 = s0 + 8;
                int n = gc >> 1;
                if (s0 < m) {
                    float r = a[0] / (1.f + __expf(-a[0])) * a[1];
                    g_Gh[((size_t)e * NTOK + s0) * NF + n] = __float2half(r);
                }
                if (s1 < m) {
                    float r = a[2] / (1.f + __expf(-a[2])) * a[3];
                    g_Gh[((size_t)e * NTOK + s1) * NF + n] = __float2half(r);
                }
            } else {
                int s0 = by + r0;
                int s1 = s0 + 8;
                if (s0 < m) {
                    int tk = g_tok[e*NTOK + s0];
                    float w = g_wgt[e*NTOK + s0];
                    atomicAdd(&C[(size_t)tk*N + gc],   w * a[0]);
                    atomicAdd(&C[(size_t)tk*N + gc+1], w * a[1]);
                }
                if (s1 < m) {
                    int tk = g_tok[e*NTOK + s1];
                    float w = g_wgt[e*NTOK + s1];
                    atomicAdd(&C[(size_t)tk*N + gc],   w * a[2]);
                    atomicAdd(&C[(size_t)tk*N + gc+1], w * a[3]);
                }
            }
        }
    }
}

// ---------------- mma flash attention (fp16 single) ----------------
#define FPITCH 144
#define FL_SMEM 46080

__device__ __forceinline__ void fl_load_kv(uint32_t base, int b, int g, int kv0, int tid) {
    #pragma unroll
    for (int j = 0; j < 4; j++) {
        int cc = tid + j * 128;
        int row = cc >> 3;
        int c8 = cc & 7;
        size_t koff = (((size_t)b * 4 + g) * 64 + row) * 1024 + kv0 + c8 * 8;
        cpa16(base + row * FPITCH + c8 * 16, g_kth + koff, 16);
    }
    #pragma unroll
    for (int j = 0; j < 4; j++) {
        int cc = tid + j * 128;
        int row = cc >> 3;
        int c8 = cc & 7;
        size_t voff = (((size_t)b * 4 + g) * 1024 + kv0 + row) * 64 + c8 * 8;
        cpa16(base + 9216 + row * FPITCH + c8 * 16, g_vh + voff, 16);
    }
    asm volatile("cp.async.commit_group;\n");
}

__global__ __launch_bounds__(128) void flashmma_k() {
    extern __shared__ char fsm[];
    uint32_t sb = (uint32_t)__cvta_generic_to_shared(fsm);
    int qt = blockIdx.x;
    int h = blockIdx.y;
    int b = blockIdx.z;
    int g = h >> 2;
    int tid = threadIdx.x;
    int wid = tid >> 5;
    int lane = tid & 31;

    #pragma unroll
    for (int j = 0; j < 4; j++) {
        int cc = tid + j * 128;
        int row = cc >> 3;
        int c8 = cc & 7;
        size_t qoff = (((size_t)b * 16 + h) * 1024 + qt * 64 + row) * 64 + c8 * 8;
        cpa16(sb + row * FPITCH + c8 * 16, g_qh + qoff, 16);
    }
    asm volatile("cp.async.commit_group;\n");
    fl_load_kv(sb + 9216, b, g, 0, tid);
    asm volatile("cp.async.wait_group 1;\n");
    __syncthreads();

    uint32_t ah[4][4];
    {
        int arow = wid * 16 + (lane & 15);
        #pragma unroll
        for (int j2 = 0; j2 < 4; j2++) {
            ldsm4(ah[j2], sb + arow * FPITCH + (uint32_t)(j2 * 16 + (lane >> 4) * 8) * 2);
        }
    }

    float m0 = -INFINITY, m1 = -INFINITY, l0 = 0.f, l1 = 0.f;
    float oacc[8][4];
    #pragma unroll
    for (int i = 0; i < 8; i++) {
        #pragma unroll
        for (int r = 0; r < 4; r++) oacc[i][r] = 0.f;
    }

    int r0g = qt * 64 + wid * 16 + (lane >> 2);

    for (int kt = 0; kt <= qt; kt++) {
        int st = kt & 1;
        if (kt < qt) {
            fl_load_kv(sb + 9216 + (st ^ 1) * 18432, b, g, (kt + 1) * 64, tid);
            asm volatile("cp.async.wait_group 1;\n");
        } else {
            asm volatile("cp.async.wait_group 0;\n");
        }
        __syncthreads();

        uint32_t kb = sb + 9216 + st * 18432;

        float sacc[8][4];
        #pragma unroll
        for (int i = 0; i < 8; i++) {
            #pragma unroll
            for (int r = 0; r < 4; r++) sacc[i][r] = 0.f;
        }
        #pragma unroll
        for (int j2 = 0; j2 < 4; j2++) {
            uint32_t bh2[4][4];
            int brow = j2 * 16 + (lane & 15);
            #pragma unroll
            for (int ng = 0; ng < 4; ng++) {
                ldsm4t(bh2[ng], kb + brow * FPITCH + (uint32_t)(ng * 16 + (lane >> 4) * 8) * 2);
            }
            #pragma unroll
            for (int n8 = 0; n8 < 8; n8++) {
                mma16816(sacc[n8], ah[j2], bh2[n8>>1][(n8&1)*2], bh2[n8>>1][(n8&1)*2+1]);
            }
        }

        if (kt == qt) {
            #pragma unroll
            for (int n8 = 0; n8 < 8; n8++) {
                int col = kt * 64 + n8 * 8 + (lane & 3) * 2;
                if (col > r0g)         sacc[n8][0] = -1e9f;
                if (col + 1 > r0g)     sacc[n8][1] = -1e9f;
                if (col > r0g + 8)     sacc[n8][2] = -1e9f;
                if (col + 1 > r0g + 8) sacc[n8][3] = -1e9f;
            }
        }

        float mx0 = -INFINITY, mx1 = -INFINITY;
        #pragma unroll
        for (int n8 = 0; n8 < 8; n8++) {
            mx0 = fmaxf(mx0, fmaxf(sacc[n8][0], sacc[n8][1]));
            mx1 = fmaxf(mx1, fmaxf(sacc[n8][2], sacc[n8][3]));
        }
        mx0 = fmaxf(mx0, __shfl_xor_sync(0xffffffffu, mx0, 1));
        mx0 = fmaxf(mx0, __shfl_xor_sync(0xffffffffu, mx0, 2));
        mx1 = fmaxf(mx1, __shfl_xor_sync(0xffffffffu, mx1, 1));
        mx1 = fmaxf(mx1, __shfl_xor_sync(0xffffffffu, mx1, 2));
        float nm0 = fmaxf(m0, mx0);
        float nm1 = fmaxf(m1, mx1);
        float f0 = __expf(m0 - nm0);
        float f1 = __expf(m1 - nm1);
        l0 *= f0;
        l1 *= f1;
        #pragma unroll
        for (int n8 = 0; n8 < 8; n8++) {
            oacc[n8][0] *= f0;
            oacc[n8][1] *= f0;
            oacc[n8][2] *= f1;
            oacc[n8][3] *= f1;
        }
        m0 = nm0;
        m1 = nm1;
        #pragma unroll
        for (int n8 = 0; n8 < 8; n8++) {
            float p0 = __expf(sacc[n8][0] - nm0);
            float p1 = __expf(sacc[n8][1] - nm0);
            float p2 = __expf(sacc[n8][2] - nm1);
            float p3 = __expf(sacc[n8][3] - nm1);
            l0 += p0 + p1;
            l1 += p2 + p3;
            sacc[n8][0] = p0;
            sacc[n8][1] = p1;
            sacc[n8][2] = p2;
            sacc[n8][3] = p3;
        }

        uint32_t vb = kb + 9216;
        #pragma unroll
        for (int j2 = 0; j2 < 4; j2++) {
            uint32_t pa[4];
            pa[0] = pack2h(sacc[2*j2][0],   sacc[2*j2][1]);
            pa[1] = pack2h(sacc[2*j2][2],   sacc[2*j2][3]);
            pa[2] = pack2h(sacc[2*j2+1][0], sacc[2*j2+1][1]);
            pa[3] = pack2h(sacc[2*j2+1][2], sacc[2*j2+1][3]);
            uint32_t vh2[4][4];
            int vrow = j2 * 16 + (lane & 15);
            #pragma unroll
            for (int ng = 0; ng < 4; ng++) {
                ldsm4t(vh2[ng], vb + vrow * FPITCH + (uint32_t)(ng * 16 + (lane >> 4) * 8) * 2);
            }
            #pragma unroll
            for (int n8 = 0; n8 < 8; n8++) {
                mma16816(oacc[n8], pa, vh2[n8>>1][(n8&1)*2], vh2[n8>>1][(n8&1)*2+1]);
            }
        }
        __syncthreads();
    }

    l0 += __shfl_xor_sync(0xffffffffu, l0, 1);
    l0 += __shfl_xor_sync(0xffffffffu, l0, 2);
    l1 += __shfl_xor_sync(0xffffffffu, l1, 1);
    l1 += __shfl_xor_sync(0xffffffffu, l1, 2);
    float i0 = 1.0f / l0;
    float i1 = 1.0f / l1;
    size_t t0 = (size_t)b * 1024 + r0g;
    size_t t1 = t0 + 8;
    #pragma unroll
    for (int n8 = 0; n8 < 8; n8++) {
        int col = h * 64 + n8 * 8 + (lane & 3) * 2;
        *(uint32_t*)(g_atth + t0 * NHID + col) = pack2h(oacc[n8][0] * i0, oacc[n8][1] * i0);
        *(uint32_t*)(g_atth + t1 * NHID + col) = pack2h(oacc[n8][2] * i1, oacc[n8][3] * i1);
    }
}

// ---------------- router (reads g_xn) ----------------
__global__ void router_k(const float* __restrict__ Wgate) {
    int t = blockIdx.x;
    float acc[NE];
    #pragma unroll
    for (int e = 0; e < NE; e++) acc[e] = 0.f;
    for (int h = threadIdx.x; h < NHID; h += 128) {
        float xv = g_xn[(size_t)t * NHID + h];
        const float4* wr = (const float4*)(Wgate + (size_t)h * NE);
        float4 w0 = wr[0];
        float4 w1 = wr[1];
        acc[0] += xv*w0.x; acc[1] += xv*w0.y; acc[2] += xv*w0.z; acc[3] += xv*w0.w;
        acc[4] += xv*w1.x; acc[5] += xv*w1.y; acc[6] += xv*w1.z; acc[7] += xv*w1.w;
    }
    #pragma unroll
    for (int e = 0; e < NE; e++) {
        #pragma unroll
        for (int o = 16; o; o >>= 1) acc[e] += __shfl_down_sync(0xffffffffu, acc[e], o);
    }
    __shared__ float sm[4][NE];
    int warp = threadIdx.x >> 5;
    int lane = threadIdx.x & 31;
    if (lane == 0) {
        for (int e = 0; e < NE; e++) sm[warp][e] = acc[e];
    }
    __syncthreads();
    if (threadIdx.x == 0) {
        float lg[NE];
        float mx = -INFINITY;
        for (int e = 0; e < NE; e++) {
            lg[e] = sm[0][e] + sm[1][e] + sm[2][e] + sm[3][e];
            mx = fmaxf(mx, lg[e]);
        }
        float p[NE];
        float sum = 0.f;
        for (int e = 0; e < NE; e++) { p[e] = expf(lg[e] - mx); sum += p[e]; }
        float inv = 1.0f / sum;
        for (int e = 0; e < NE; e++) p[e] *= inv;
        int i1 = 0;
        float b1 = p[0];
        for (int e = 1; e < NE; e++) {
            if (p[e] > b1) { b1 = p[e]; i1 = e; }
        }
        int i2 = -1;
        float b2 = -INFINITY;
        for (int e = 0; e < NE; e++) {
            if (e != i1 && p[e] > b2) { b2 = p[e]; i2 = e; }
        }
        int s1 = atomicAdd(&g_cnt[i1], 1);
        g_tok[i1 * NTOK + s1] = t;
        g_wgt[i1 * NTOK + s1] = b1;
        int s2 = atomicAdd(&g_cnt[i2], 1);
        g_tok[i2 * NTOK + s2] = t;
        g_wgt[i2 * NTOK + s2] = b2;
    }
}

__global__ void zero_cnt_k() {
    if (threadIdx.x < NE) g_cnt[threadIdx.x] = 0;
}

// ---------------- launch ----------------
extern "C" void kernel_launch(void* const* d_in, const int* in_sizes, int n_in,
                              void* d_out, int out_size) {
    (void)in_sizes; (void)n_in; (void)out_size;
    const float* x     = (const float*)d_in[0];
    const float* w_ln1 = (const float*)d_in[2];
    const float* w_ln2 = (const float*)d_in[3];
    const float* Wq    = (const float*)d_in[4];
    const float* Wk    = (const float*)d_in[5];
    const float* Wv    = (const float*)d_in[6];
    const float* Wo    = (const float*)d_in[7];
    const float* Wgate = (const float*)d_in[8];
    const float* Wg    = (const float*)d_in[9];
    const float* Wu    = (const float*)d_in[10];
    const float* Wd    = (const float*)d_in[11];
    float* out = (float*)d_out;

    cudaFuncSetAttribute(tgemm_k, cudaFuncAttributeMaxDynamicSharedMemorySize, TG_SMEM);
    cudaFuncSetAttribute(flashmma_k, cudaFuncAttributeMaxDynamicSharedMemorySize, FL_SMEM);

    // 0) fused QKV weight pack
    split_pack_qkv_k<<<NHID*QKVN/4/256, 256>>>((const float4*)Wq, (const float4*)Wk, (const float4*)Wv);
    // 1) Wo convert
    split_k<<<NHID*NHID/4/256, 256>>>((const float4*)Wo, NHID*NHID/4, 1);
    // 2) ln1 (fused fp16 convert)
    rmsnorm_half_k<<<NTOK, 256>>>(x, w_ln1, 0, 0);
    // 3) fused QKV projection -> direct fp16 Q/Kt/V scatter  <-- profiled slot
    tgemm_k<<<dim3(QKVN/128, NTOK/128), 256, TG_SMEM>>>(0, 0, 0);
    // 4) mma flash attention
    flashmma_k<<<dim3(NS/64, NHEADS, NB), 128, FL_SMEM>>>();
    // 5) output proj + residual -> g_h AND out
    tgemm_k<<<dim3(NHID/128, NTOK/128), 256, TG_SMEM>>>(1, x, out);
    // 6) ln2 (fused convert + fp32 for router)
    rmsnorm_half_k<<<NTOK, 256>>>(0, w_ln2, 1, 1);
    // 7) routing
    zero_cnt_k<<<1, 32>>>();
    router_k<<<NTOK, 128>>>(Wgate);
    // 8) gate|up interleaved weight pack
    split_pack_gu_k<<<NE*NHID*NF/4/256, 256>>>((const float4*)Wg, (const float4*)Wu);
    // 9) fused gate|up grouped GEMM + silu epilogue -> g_Gh fp16
    tgemm_k<<<dim3(GUN/128, NTOK/128, NE), 256, TG_SMEM>>>(2, 0, 0);
    // 10) Wd convert
    split_k<<<NE*NF*NHID/4/256, 256>>>((const float4*)Wd, NE*NF*NHID/4, 3);
    // 11) down-proj scatter onto out (out already holds h from step 5)
    tgemm_k<<<dim3(NHID/128, NTOK/128, NE), 256, TG_SMEM>>>(3, 0, out);
}

// round 16
// speedup vs baseline: 2.2634x; 1.0225x over previous
#include <cuda_runtime.h>
#include <cuda_fp16.h>
#include <math.h>
#include <stdint.h>

#define NB    4
#define NS    1024
#define NHID  1024
#define NHEADS 16
#define NKVH  4
#define DH    64
#define NE    8
#define NF    2048
#define NTOK  4096
#define QKVN  1536
#define GUN   4096

// ---------------- scratch (device globals, allocation-free) ----------------
__device__ float g_xn[NTOK * NHID];
__device__ __half g_xnh[NTOK * NHID];
__device__ __half g_atth[NTOK * NHID];
__device__ __half g_wqkvh[NHID * QKVN];
__device__ __half g_woh[NHID * NHID];
__device__ __half g_wguh[NE * NHID * GUN];   // interleaved: col 2j=gate, 2j+1=up
__device__ __half g_wdh[NE * NF * NHID];
__device__ __half g_Gh[NE * NTOK * NF];
__device__ int   g_cnt[NE];
__device__ int   g_tok[NE * NTOK];
__device__ float g_wgt[NE * NTOK];
// attention operands: Q [b][h][s][d] (scaled), Kt [b][g][d][s], V [b][g][s][d]
__device__ __half g_qh[NB * NHEADS * NS * DH];
__device__ __half g_kth[NB * NKVH * DH * NS];
__device__ __half g_vh[NB * NKVH * NS * DH];

// ---------------- helpers ----------------
__device__ __forceinline__ uint32_t pack2h(float a, float b) {
    __half2 h = __floats2half2_rn(a, b);
    return *(uint32_t*)&h;
}
__device__ __forceinline__ void ldsm4(uint32_t* r, uint32_t a) {
    asm volatile("ldmatrix.sync.aligned.m8n8.x4.shared.b16 {%0,%1,%2,%3}, [%4];\n"
        : "=r"(r[0]), "=r"(r[1]), "=r"(r[2]), "=r"(r[3]) : "r"(a));
}
__device__ __forceinline__ void ldsm4t(uint32_t* r, uint32_t a) {
    asm volatile("ldmatrix.sync.aligned.m8n8.x4.trans.shared.b16 {%0,%1,%2,%3}, [%4];\n"
        : "=r"(r[0]), "=r"(r[1]), "=r"(r[2]), "=r"(r[3]) : "r"(a));
}
// NOTE: non-volatile — pure register dataflow, lets ptxas pipeline mma with ldsm
__device__ __forceinline__ void mma16816(float* d, const uint32_t* a, uint32_t b0, uint32_t b1) {
    asm("mma.sync.aligned.m16n8k16.row.col.f32.f16.f16.f32 "
        "{%0,%1,%2,%3},{%4,%5,%6,%7},{%8,%9},{%0,%1,%2,%3};\n"
        : "+f"(d[0]), "+f"(d[1]), "+f"(d[2]), "+f"(d[3])
        : "r"(a[0]), "r"(a[1]), "r"(a[2]), "r"(a[3]), "r"(b0), "r"(b1));
}
__device__ __forceinline__ void cpa16(uint32_t dst, const void* src, int sz) {
    asm volatile("cp.async.cg.shared.global [%0], [%1], 16, %2;\n"
        :: "r"(dst), "l"(src), "r"(sz));
}

// ---------------- fused RMSNorm + fp16 convert ----------------
__global__ void rmsnorm_half_k(const float* __restrict__ src, const float* __restrict__ w,
                               int write_xn) {
    int t = blockIdx.x;
    const float4* xr = (const float4*)(src + (size_t)t * NHID);
    float4 v = xr[threadIdx.x];
    float ss = v.x*v.x + v.y*v.y + v.z*v.z + v.w*v.w;
    #pragma unroll
    for (int o = 16; o; o >>= 1) ss += __shfl_down_sync(0xffffffffu, ss, o);
    __shared__ float red[8];
    if ((threadIdx.x & 31) == 0) red[threadIdx.x >> 5] = ss;
    __syncthreads();
    if (threadIdx.x < 8) {
        float s = red[threadIdx.x];
        #pragma unroll
        for (int o = 4; o; o >>= 1) s += __shfl_down_sync(0xffu, s, o);
        if (threadIdx.x == 0) red[0] = s;
    }
    __syncthreads();
    float rs = rsqrtf(red[0] * (1.0f / NHID) + 1e-6f);
    float4 wv = ((const float4*)w)[threadIdx.x];
    float4 ov;
    ov.x = v.x * rs * wv.x;
    ov.y = v.y * rs * wv.y;
    ov.z = v.z * rs * wv.z;
    ov.w = v.w * rs * wv.w;
    if (write_xn) {
        ((float4*)(g_xn + (size_t)t * NHID))[threadIdx.x] = ov;
    }
    uint32_t* p = (uint32_t*)(g_xnh + (size_t)t * NHID) + threadIdx.x * 2;
    p[0] = pack2h(ov.x, ov.y);
    p[1] = pack2h(ov.z, ov.w);
}

// ---------------- combined QKV weight pack ----------------
__global__ void split_pack_qkv_k(const float4* __restrict__ Wq, const float4* __restrict__ Wk,
                                 const float4* __restrict__ Wv) {
    int i = blockIdx.x * 256 + threadIdx.x;
    int el = i * 4;
    int r = el / QKVN;
    int c = el % QKVN;
    float4 v;
    if (c < 1024)      v = Wq[(r * 1024 + c) / 4];
    else if (c < 1280) v = Wk[(r * 256 + (c - 1024)) / 4];
    else               v = Wv[(r * 256 + (c - 1280)) / 4];
    uint32_t* p = (uint32_t*)(g_wqkvh + (size_t)r * QKVN + c);
    p[0] = pack2h(v.x, v.y);
    p[1] = pack2h(v.z, v.w);
}

// ---------------- plain convert: fp32 -> fp16, 8 elems/thread ---------------
__global__ void split_k(const float4* __restrict__ ext, int n8, int sel) {
    int i = blockIdx.x * 256 + threadIdx.x;
    if (i >= n8) return;
    __half* d = (sel == 1) ? g_woh : g_wdh;
    float4 v0 = ext[i*2];
    float4 v1 = ext[i*2+1];
    uint4 o;
    o.x = pack2h(v0.x, v0.y);
    o.y = pack2h(v0.z, v0.w);
    o.z = pack2h(v1.x, v1.y);
    o.w = pack2h(v1.z, v1.w);
    *(uint4*)(d + (size_t)i * 8) = o;
}

// ---------------- gate|up interleaved pack ----------------
__global__ void split_pack_gu_k(const float4* __restrict__ Wg, const float4* __restrict__ Wu) {
    int i = blockIdx.x * 256 + threadIdx.x;
    float4 g4 = Wg[i];
    float4 u4 = Wu[i];
    int el = i * 4;
    size_t r = (size_t)(el / NF);
    int c = el % NF;
    uint4 o;
    o.x = pack2h(g4.x, u4.x);
    o.y = pack2h(g4.y, u4.y);
    o.z = pack2h(g4.z, u4.z);
    o.w = pack2h(g4.w, u4.w);
    *(uint4*)(g_wguh + r * GUN + 2 * c) = o;
}

// ---------------- tensor-core GEMM (fp16), 128x128x64 tiles, 3-stage --------
// 256 threads, 2 CTA/SM; single __syncthreads per chunk (distance-2 prefetch)
// op 0: QKV   A=g_xnh  B=g_wqkvh -> epilogue scatters fp16 Q(x0.125)/Kt/V
// op 1: Oproj A=g_atth B=g_woh   -> out (Cadd = x residual)
// op 2: GU    A=gather xnh, B=g_wguh (interleaved) -> fused silu -> g_Gh fp16
// op 3: Down  A=g_Gh   B=g_wdh   -> atomic scatter onto out
#define TG_SMEM 107520

__device__ __forceinline__ void tg_load64(
        uint32_t sA, uint32_t sB, int stg, int k0,
        int ar, int ac4, int br, int bc4,
        const __half* apr, int asz,
        const __half* Bp, int N, int bx) {
    uint32_t abase = sA + stg * 18432 + ar * 144;
    #pragma unroll
    for (int i = 0; i < 4; i++) {
        int c8 = ac4 + i;
        cpa16(abase + c8 * 16, apr + k0 + c8 * 8, asz);
    }
    const __half* brow = Bp + (size_t)(k0 + br) * N + bx;
    uint32_t bbase = sB + stg * 17408 + br * 272;
    #pragma unroll
    for (int i = 0; i < 4; i++) {
        int c8 = bc4 + i;
        cpa16(bbase + c8 * 16, brow + c8 * 8, 16);
    }
    asm volatile("cp.async.commit_group;\n");
}

__global__ __launch_bounds__(256, 2) void tgemm_k(int op, const float* __restrict__ cadd_ext,
                                                  float* __restrict__ cout_ext) {
    extern __shared__ char smraw[];
    uint32_t sA = (uint32_t)__cvta_generic_to_shared(smraw);
    uint32_t sB = sA + 55296;

    const __half* Ah;
    const __half* Bh;
    float* C = 0;
    const float* Cadd = 0;
    int N, K, mode;
    if (op == 0) {
        Ah = g_xnh;  Bh = g_wqkvh;
        N = QKVN; K = NHID; mode = 0;
    } else if (op == 1) {
        Ah = g_atth; Bh = g_woh;
        C = cout_ext; Cadd = cadd_ext; N = NHID; K = NHID; mode = 0;
    } else if (op == 2) {
        Ah = g_xnh;  Bh = g_wguh;
        N = GUN;  K = NHID; mode = 1;
    } else {
        Ah = g_Gh;   Bh = g_wdh;
        C = cout_ext; N = NHID; K = NF; mode = 2;
    }

    int tid = threadIdx.x;
    int bx = blockIdx.x * 128;
    int by = blockIdx.y * 128;
    int e = blockIdx.z;
    int m = NTOK;
    if (mode != 0) {
        m = g_cnt[e];
        if (by >= m) return;
        Bh += (size_t)e * K * N;
    }

    int ar = tid >> 1;
    int ac4 = (tid & 1) * 4;
    const __half* apr;
    int asz;
    {
        int lr = by + ar;
        size_t g0;
        bool v0 = true;
        if (mode == 0) {
            g0 = (size_t)lr;
        } else if (mode == 1) {
            v0 = lr < m;
            g0 = v0 ? (size_t)g_tok[e * NTOK + lr] : 0;
        } else {
            v0 = lr < m;
            g0 = (size_t)e * NTOK + (v0 ? (size_t)lr : 0);
        }
        apr = Ah + g0 * K;
        asz = v0 ? 16 : 0;
    }
    int br = tid >> 2;
    int bc4 = (tid & 3) * 4;

    int wid = tid >> 5;
    int lane = tid & 31;
    int wm = (wid >> 2) * 64;
    int wn = (wid & 3) * 32;

    float acc[4][4][4];
    #pragma unroll
    for (int i = 0; i < 4; i++) {
        #pragma unroll
        for (int j = 0; j < 4; j++) {
            #pragma unroll
            for (int r = 0; r < 4; r++) acc[i][j][r] = 0.f;
        }
    }

    int NC = K / 64;
    tg_load64(sA, sB, 0, 0,  ar, ac4, br, bc4, apr, asz, Bh, N, bx);
    tg_load64(sA, sB, 1, 64, ar, ac4, br, bc4, apr, asz, Bh, N, bx);

    for (int c = 0; c < NC; c++) {
        if (c + 1 < NC) {
            asm volatile("cp.async.wait_group 1;\n");
        } else {
            asm volatile("cp.async.wait_group 0;\n");
        }
        __syncthreads();
        int ld = c + 2;
        if (ld < NC) {
            int ls = ld - (ld / 3) * 3;
            tg_load64(sA, sB, ls, ld * 64, ar, ac4, br, bc4, apr, asz, Bh, N, bx);
        }
        int st = c - (c / 3) * 3;
        uint32_t abase = sA + st * 18432;
        uint32_t bbase = sB + st * 17408;

        #pragma unroll
        for (int kk = 0; kk < 64; kk += 16) {
            uint32_t ah[4][4], bh2[2][4];
            int arow = wm + (lane & 15);
            int acolb = (kk + (lane >> 4) * 8) * 2;
            #pragma unroll
            for (int i = 0; i < 4; i++) {
                ldsm4(ah[i], abase + (arow + i*16)*144 + acolb);
            }
            int brow = kk + (lane & 15);
            #pragma unroll
            for (int j = 0; j < 2; j++) {
                ldsm4t(bh2[j], bbase + brow*272 + (wn + j*16 + (lane >> 4)*8)*2);
            }
            #pragma unroll
            for (int i = 0; i < 4; i++) {
                #pragma unroll
                for (int n8 = 0; n8 < 4; n8++) {
                    mma16816(acc[i][n8], ah[i], bh2[n8>>1][(n8&1)*2], bh2[n8>>1][(n8&1)*2+1]);
                }
            }
        }
    }

    int ln4 = lane >> 2;
    int lc = (lane & 3) * 2;
    #pragma unroll
    for (int i = 0; i < 4; i++) {
        int r0 = wm + i * 16 + ln4;
        #pragma unroll
        for (int n8 = 0; n8 < 4; n8++) {
            int gc = bx + wn + n8 * 8 + lc;
            float* a = acc[i][n8];
            if (op == 0) {
                #pragma unroll
                for (int hh = 0; hh < 2; hh++) {
                    int row = by + r0 + hh * 8;
                    float va = a[hh*2];
                    float vb = a[hh*2+1];
                    int b = row >> 10;
                    int s = row & 1023;
                    if (gc < 1024) {
                        int h = gc >> 6, d = gc & 63;
                        size_t q = (((size_t)b * 16 + h) * 1024 + s) * 64 + d;
                        *(uint32_t*)(g_qh + q) = pack2h(va * 0.125f, vb * 0.125f);
                    } else if (gc < 1280) {
                        int cc = gc - 1024;
                        int g = cc >> 6, d = cc & 63;
                        size_t base = (((size_t)b * 4 + g) * 64 + d) * 1024 + s;
                        g_kth[base]        = __float2half(va);
                        g_kth[base + 1024] = __float2half(vb);
                    } else {
                        int cc = gc - 1280;
                        int g = cc >> 6, d = cc & 63;
                        size_t base = (((size_t)b * 4 + g) * 1024 + s) * 64 + d;
                        *(uint32_t*)(g_vh + base) = pack2h(va, vb);
                    }
                }
            } else if (mode == 0) {
                size_t o0 = (size_t)(by + r0) * N + gc;
                size_t o1 = o0 + (size_t)8 * N;
                float2 w0;
                w0.x = a[0] + Cadd[o0];
                w0.y = a[1] + Cadd[o0+1];
                float2 w1;
                w1.x = a[2] + Cadd[o1];
                w1.y = a[3] + Cadd[o1+1];
                *(float2*)(C + o0) = w0;
                *(float2*)(C + o1) = w1;
            } else if (mode == 1) {
                int s0 = by + r0;
                int s1 = s0 + 8;
                int n = gc >> 1;
                if (s0 < m) {
                    float r = a[0] / (1.f + __expf(-a[0])) * a[1];
                    g_Gh[((size_t)e * NTOK + s0) * NF + n] = __float2half(r);
                }
                if (s1 < m) {
                    float r = a[2] / (1.f + __expf(-a[2])) * a[3];
                    g_Gh[((size_t)e * NTOK + s1) * NF + n] = __float2half(r);
                }
            } else {
                int s0 = by + r0;
                int s1 = s0 + 8;
                if (s0 < m) {
                    int tk = g_tok[e*NTOK + s0];
                    float w = g_wgt[e*NTOK + s0];
                    atomicAdd(&C[(size_t)tk*N + gc],   w * a[0]);
                    atomicAdd(&C[(size_t)tk*N + gc+1], w * a[1]);
                }
                if (s1 < m) {
                    int tk = g_tok[e*NTOK + s1];
                    float w = g_wgt[e*NTOK + s1];
                    atomicAdd(&C[(size_t)tk*N + gc],   w * a[2]);
                    atomicAdd(&C[(size_t)tk*N + gc+1], w * a[3]);
                }
            }
        }
    }
}

// ---------------- mma flash attention (fp16 single) ----------------
#define FPITCH 144
#define FL_SMEM 46080

__device__ __forceinline__ void fl_load_kv(uint32_t base, int b, int g, int kv0, int tid) {
    #pragma unroll
    for (int j = 0; j < 4; j++) {
        int cc = tid + j * 128;
        int row = cc >> 3;
        int c8 = cc & 7;
        size_t koff = (((size_t)b * 4 + g) * 64 + row) * 1024 + kv0 + c8 * 8;
        cpa16(base + row * FPITCH + c8 * 16, g_kth + koff, 16);
    }
    #pragma unroll
    for (int j = 0; j < 4; j++) {
        int cc = tid + j * 128;
        int row = cc >> 3;
        int c8 = cc & 7;
        size_t voff = (((size_t)b * 4 + g) * 1024 + kv0 + row) * 64 + c8 * 8;
        cpa16(base + 9216 + row * FPITCH + c8 * 16, g_vh + voff, 16);
    }
    asm volatile("cp.async.commit_group;\n");
}

__global__ __launch_bounds__(128) void flashmma_k() {
    extern __shared__ char fsm[];
    uint32_t sb = (uint32_t)__cvta_generic_to_shared(fsm);
    int qt = blockIdx.x;
    int h = blockIdx.y;
    int b = blockIdx.z;
    int g = h >> 2;
    int tid = threadIdx.x;
    int wid = tid >> 5;
    int lane = tid & 31;

    #pragma unroll
    for (int j = 0; j < 4; j++) {
        int cc = tid + j * 128;
        int row = cc >> 3;
        int c8 = cc & 7;
        size_t qoff = (((size_t)b * 16 + h) * 1024 + qt * 64 + row) * 64 + c8 * 8;
        cpa16(sb + row * FPITCH + c8 * 16, g_qh + qoff, 16);
    }
    asm volatile("cp.async.commit_group;\n");
    fl_load_kv(sb + 9216, b, g, 0, tid);
    asm volatile("cp.async.wait_group 1;\n");
    __syncthreads();

    uint32_t ah[4][4];
    {
        int arow = wid * 16 + (lane & 15);
        #pragma unroll
        for (int j2 = 0; j2 < 4; j2++) {
            ldsm4(ah[j2], sb + arow * FPITCH + (uint32_t)(j2 * 16 + (lane >> 4) * 8) * 2);
        }
    }

    float m0 = -INFINITY, m1 = -INFINITY, l0 = 0.f, l1 = 0.f;
    float oacc[8][4];
    #pragma unroll
    for (int i = 0; i < 8; i++) {
        #pragma unroll
        for (int r = 0; r < 4; r++) oacc[i][r] = 0.f;
    }

    int r0g = qt * 64 + wid * 16 + (lane >> 2);

    for (int kt = 0; kt <= qt; kt++) {
        int st = kt & 1;
        if (kt < qt) {
            fl_load_kv(sb + 9216 + (st ^ 1) * 18432, b, g, (kt + 1) * 64, tid);
            asm volatile("cp.async.wait_group 1;\n");
        } else {
            asm volatile("cp.async.wait_group 0;\n");
        }
        __syncthreads();

        uint32_t kb = sb + 9216 + st * 18432;

        float sacc[8][4];
        #pragma unroll
        for (int i = 0; i < 8; i++) {
            #pragma unroll
            for (int r = 0; r < 4; r++) sacc[i][r] = 0.f;
        }
        #pragma unroll
        for (int j2 = 0; j2 < 4; j2++) {
            uint32_t bh2[4][4];
            int brow = j2 * 16 + (lane & 15);
            #pragma unroll
            for (int ng = 0; ng < 4; ng++) {
                ldsm4t(bh2[ng], kb + brow * FPITCH + (uint32_t)(ng * 16 + (lane >> 4) * 8) * 2);
            }
            #pragma unroll
            for (int n8 = 0; n8 < 8; n8++) {
                mma16816(sacc[n8], ah[j2], bh2[n8>>1][(n8&1)*2], bh2[n8>>1][(n8&1)*2+1]);
            }
        }

        if (kt == qt) {
            #pragma unroll
            for (int n8 = 0; n8 < 8; n8++) {
                int col = kt * 64 + n8 * 8 + (lane & 3) * 2;
                if (col > r0g)         sacc[n8][0] = -1e9f;
                if (col + 1 > r0g)     sacc[n8][1] = -1e9f;
                if (col > r0g + 8)     sacc[n8][2] = -1e9f;
                if (col + 1 > r0g + 8) sacc[n8][3] = -1e9f;
            }
        }

        float mx0 = -INFINITY, mx1 = -INFINITY;
        #pragma unroll
        for (int n8 = 0; n8 < 8; n8++) {
            mx0 = fmaxf(mx0, fmaxf(sacc[n8][0], sacc[n8][1]));
            mx1 = fmaxf(mx1, fmaxf(sacc[n8][2], sacc[n8][3]));
        }
        mx0 = fmaxf(mx0, __shfl_xor_sync(0xffffffffu, mx0, 1));
        mx0 = fmaxf(mx0, __shfl_xor_sync(0xffffffffu, mx0, 2));
        mx1 = fmaxf(mx1, __shfl_xor_sync(0xffffffffu, mx1, 1));
        mx1 = fmaxf(mx1, __shfl_xor_sync(0xffffffffu, mx1, 2));
        float nm0 = fmaxf(m0, mx0);
        float nm1 = fmaxf(m1, mx1);
        float f0 = __expf(m0 - nm0);
        float f1 = __expf(m1 - nm1);
        l0 *= f0;
        l1 *= f1;
        #pragma unroll
        for (int n8 = 0; n8 < 8; n8++) {
            oacc[n8][0] *= f0;
            oacc[n8][1] *= f0;
            oacc[n8][2] *= f1;
            oacc[n8][3] *= f1;
        }
        m0 = nm0;
        m1 = nm1;
        #pragma unroll
        for (int n8 = 0; n8 < 8; n8++) {
            float p0 = __expf(sacc[n8][0] - nm0);
            float p1 = __expf(sacc[n8][1] - nm0);
            float p2 = __expf(sacc[n8][2] - nm1);
            float p3 = __expf(sacc[n8][3] - nm1);
            l0 += p0 + p1;
            l1 += p2 + p3;
            sacc[n8][0] = p0;
            sacc[n8][1] = p1;
            sacc[n8][2] = p2;
            sacc[n8][3] = p3;
        }

        uint32_t vb = kb + 9216;
        #pragma unroll
        for (int j2 = 0; j2 < 4; j2++) {
            uint32_t pa[4];
            pa[0] = pack2h(sacc[2*j2][0],   sacc[2*j2][1]);
            pa[1] = pack2h(sacc[2*j2][2],   sacc[2*j2][3]);
            pa[2] = pack2h(sacc[2*j2+1][0], sacc[2*j2+1][1]);
            pa[3] = pack2h(sacc[2*j2+1][2], sacc[2*j2+1][3]);
            uint32_t vh2[4][4];
            int vrow = j2 * 16 + (lane & 15);
            #pragma unroll
            for (int ng = 0; ng < 4; ng++) {
                ldsm4t(vh2[ng], vb + vrow * FPITCH + (uint32_t)(ng * 16 + (lane >> 4) * 8) * 2);
            }
            #pragma unroll
            for (int n8 = 0; n8 < 8; n8++) {
                mma16816(oacc[n8], pa, vh2[n8>>1][(n8&1)*2], vh2[n8>>1][(n8&1)*2+1]);
            }
        }
        __syncthreads();
    }

    l0 += __shfl_xor_sync(0xffffffffu, l0, 1);
    l0 += __shfl_xor_sync(0xffffffffu, l0, 2);
    l1 += __shfl_xor_sync(0xffffffffu, l1, 1);
    l1 += __shfl_xor_sync(0xffffffffu, l1, 2);
    float i0 = 1.0f / l0;
    float i1 = 1.0f / l1;
    size_t t0 = (size_t)b * 1024 + r0g;
    size_t t1 = t0 + 8;
    #pragma unroll
    for (int n8 = 0; n8 < 8; n8++) {
        int col = h * 64 + n8 * 8 + (lane & 3) * 2;
        *(uint32_t*)(g_atth + t0 * NHID + col) = pack2h(oacc[n8][0] * i0, oacc[n8][1] * i0);
        *(uint32_t*)(g_atth + t1 * NHID + col) = pack2h(oacc[n8][2] * i1, oacc[n8][3] * i1);
    }
}

// ---------------- router (reads g_xn) ----------------
__global__ void router_k(const float* __restrict__ Wgate) {
    int t = blockIdx.x;
    float acc[NE];
    #pragma unroll
    for (int e = 0; e < NE; e++) acc[e] = 0.f;
    for (int h = threadIdx.x; h < NHID; h += 128) {
        float xv = g_xn[(size_t)t * NHID + h];
        const float4* wr = (const float4*)(Wgate + (size_t)h * NE);
        float4 w0 = wr[0];
        float4 w1 = wr[1];
        acc[0] += xv*w0.x; acc[1] += xv*w0.y; acc[2] += xv*w0.z; acc[3] += xv*w0.w;
        acc[4] += xv*w1.x; acc[5] += xv*w1.y; acc[6] += xv*w1.z; acc[7] += xv*w1.w;
    }
    #pragma unroll
    for (int e = 0; e < NE; e++) {
        #pragma unroll
        for (int o = 16; o; o >>= 1) acc[e] += __shfl_down_sync(0xffffffffu, acc[e], o);
    }
    __shared__ float sm[4][NE];
    int warp = threadIdx.x >> 5;
    int lane = threadIdx.x & 31;
    if (lane == 0) {
        for (int e = 0; e < NE; e++) sm[warp][e] = acc[e];
    }
    __syncthreads();
    if (threadIdx.x == 0) {
        float lg[NE];
        float mx = -INFINITY;
        for (int e = 0; e < NE; e++) {
            lg[e] = sm[0][e] + sm[1][e] + sm[2][e] + sm[3][e];
            mx = fmaxf(mx, lg[e]);
        }
        float p[NE];
        float sum = 0.f;
        for (int e = 0; e < NE; e++) { p[e] = expf(lg[e] - mx); sum += p[e]; }
        float inv = 1.0f / sum;
        for (int e = 0; e < NE; e++) p[e] *= inv;
        int i1 = 0;
        float b1 = p[0];
        for (int e = 1; e < NE; e++) {
            if (p[e] > b1) { b1 = p[e]; i1 = e; }
        }
        int i2 = -1;
        float b2 = -INFINITY;
        for (int e = 0; e < NE; e++) {
            if (e != i1 && p[e] > b2) { b2 = p[e]; i2 = e; }
        }
        int s1 = atomicAdd(&g_cnt[i1], 1);
        g_tok[i1 * NTOK + s1] = t;
        g_wgt[i1 * NTOK + s1] = b1;
        int s2 = atomicAdd(&g_cnt[i2], 1);
        g_tok[i2 * NTOK + s2] = t;
        g_wgt[i2 * NTOK + s2] = b2;
    }
}

__global__ void zero_cnt_k() {
    if (threadIdx.x < NE) g_cnt[threadIdx.x] = 0;
}

// ---------------- launch ----------------
extern "C" void kernel_launch(void* const* d_in, const int* in_sizes, int n_in,
                              void* d_out, int out_size) {
    (void)in_sizes; (void)n_in; (void)out_size;
    const float* x     = (const float*)d_in[0];
    const float* w_ln1 = (const float*)d_in[2];
    const float* w_ln2 = (const float*)d_in[3];
    const float* Wq    = (const float*)d_in[4];
    const float* Wk    = (const float*)d_in[5];
    const float* Wv    = (const float*)d_in[6];
    const float* Wo    = (const float*)d_in[7];
    const float* Wgate = (const float*)d_in[8];
    const float* Wg    = (const float*)d_in[9];
    const float* Wu    = (const float*)d_in[10];
    const float* Wd    = (const float*)d_in[11];
    float* out = (float*)d_out;

    cudaFuncSetAttribute(tgemm_k, cudaFuncAttributeMaxDynamicSharedMemorySize, TG_SMEM);
    cudaFuncSetAttribute(flashmma_k, cudaFuncAttributeMaxDynamicSharedMemorySize, FL_SMEM);

    // 0) fused QKV weight pack
    split_pack_qkv_k<<<NHID*QKVN/4/256, 256>>>((const float4*)Wq, (const float4*)Wk, (const float4*)Wv);
    // 1) Wo convert
    split_k<<<NHID*NHID/8/256, 256>>>((const float4*)Wo, NHID*NHID/8, 1);
    // 2) ln1 (fused fp16 convert)
    rmsnorm_half_k<<<NTOK, 256>>>(x, w_ln1, 0);
    // 3) fused QKV projection -> direct fp16 Q/Kt/V scatter  <-- profiled slot
    tgemm_k<<<dim3(QKVN/128, NTOK/128), 256, TG_SMEM>>>(0, 0, 0);
    // 4) mma flash attention
    flashmma_k<<<dim3(NS/64, NHEADS, NB), 128, FL_SMEM>>>();
    // 5) output proj + residual -> out (h)
    tgemm_k<<<dim3(NHID/128, NTOK/128), 256, TG_SMEM>>>(1, x, out);
    // 6) ln2 (reads h from out; fp32 copy for router)
    rmsnorm_half_k<<<NTOK, 256>>>(out, w_ln2, 1);
    // 7) routing
    zero_cnt_k<<<1, 32>>>();
    router_k<<<NTOK, 128>>>(Wgate);
    // 8) gate|up interleaved weight pack
    split_pack_gu_k<<<NE*NHID*NF/4/256, 256>>>((const float4*)Wg, (const float4*)Wu);
    // 9) fused gate|up grouped GEMM + silu epilogue -> g_Gh fp16
    tgemm_k<<<dim3(GUN/128, NTOK/128, NE), 256, TG_SMEM>>>(2, 0, 0);
    // 10) Wd convert
    split_k<<<NE*NF*NHID/8/256, 256>>>((const float4*)Wd, NE*NF*NHID/8, 3);
    // 11) down-proj scatter onto out (out already holds h from step 5)
    tgemm_k<<<dim3(NHID/128, NTOK/128, NE), 256, TG_SMEM>>>(3, 0, out);
}